// round 11
// baseline (speedup 1.0000x reference)
#include <cuda_runtime.h>
#include <cuda_bf16.h>
#include <math.h>
#include <stdint.h>

#define B_  2
#define L_  2048
#define D_  2048
#define NH_ 16
#define NKV_ 8
#define HD_ 128
#define GQ_ 2
#define SCALE_ 0.08838834764831845f  // 128^-0.5

// ---------------- scratch (static device globals) ----------------
__device__ float g_q[(size_t)B_ * L_ * NH_ * HD_];
__device__ float g_k[(size_t)B_ * L_ * NKV_ * HD_];
__device__ float g_v[(size_t)B_ * L_ * NKV_ * HD_];
__device__ float g_o[(size_t)B_ * L_ * NH_ * HD_];
__device__ float g_cos[(size_t)L_ * 64];
__device__ float g_sin[(size_t)L_ * 64];

__device__ __nv_bfloat16 g_xh[(size_t)B_ * L_ * D_];
__device__ __nv_bfloat16 g_xl[(size_t)B_ * L_ * D_];
__device__ __nv_bfloat16 g_wqh[(size_t)D_ * D_];
__device__ __nv_bfloat16 g_wql[(size_t)D_ * D_];
__device__ __nv_bfloat16 g_wkh[(size_t)NKV_ * HD_ * D_];
__device__ __nv_bfloat16 g_wkl[(size_t)NKV_ * HD_ * D_];
__device__ __nv_bfloat16 g_wvh[(size_t)NKV_ * HD_ * D_];
__device__ __nv_bfloat16 g_wvl[(size_t)NKV_ * HD_ * D_];
__device__ __nv_bfloat16 g_woh[(size_t)D_ * D_];
__device__ __nv_bfloat16 g_wol[(size_t)D_ * D_];
__device__ __nv_bfloat16 g_oh[(size_t)B_ * L_ * D_];
__device__ __nv_bfloat16 g_ol[(size_t)B_ * L_ * D_];

// pre-split (and RoPE'd / transposed) attention operands
__device__ __nv_bfloat16 g_qh[(size_t)B_ * L_ * NH_ * HD_];
__device__ __nv_bfloat16 g_ql[(size_t)B_ * L_ * NH_ * HD_];
__device__ __nv_bfloat16 g_kh[(size_t)B_ * L_ * NKV_ * HD_];
__device__ __nv_bfloat16 g_kl[(size_t)B_ * L_ * NKV_ * HD_];
__device__ __nv_bfloat16 g_vth[(size_t)B_ * NKV_ * HD_ * L_];
__device__ __nv_bfloat16 g_vtl[(size_t)B_ * NKV_ * HD_ * L_];

// ---------------- helpers ----------------
__device__ __forceinline__ uint32_t smem_u32(const void* p) {
    uint32_t a;
    asm("{ .reg .u64 t; cvta.to.shared.u64 t, %1; cvt.u32.u64 %0, t; }"
        : "=r"(a) : "l"(p));
    return a;
}
#define LDSM4(r, a) \
    asm volatile("ldmatrix.sync.aligned.m8n8.x4.shared.b16 {%0,%1,%2,%3}, [%4];" \
                 : "=r"((r)[0]), "=r"((r)[1]), "=r"((r)[2]), "=r"((r)[3]) : "r"(a))
#define LDSM2(r, a) \
    asm volatile("ldmatrix.sync.aligned.m8n8.x2.shared.b16 {%0,%1}, [%2];" \
                 : "=r"((r)[0]), "=r"((r)[1]) : "r"(a))
#define MMA16816(d, a, b) \
    asm volatile("mma.sync.aligned.m16n8k16.row.col.f32.bf16.bf16.f32 " \
                 "{%0,%1,%2,%3}, {%4,%5,%6,%7}, {%8,%9}, {%0,%1,%2,%3};" \
                 : "+f"((d)[0]), "+f"((d)[1]), "+f"((d)[2]), "+f"((d)[3]) \
                 : "r"((a)[0]), "r"((a)[1]), "r"((a)[2]), "r"((a)[3]), \
                   "r"((b)[0]), "r"((b)[1]))
#define CP_ASYNC16(s, g) \
    asm volatile("cp.async.cg.shared.global [%0], [%1], 16;" :: "r"(s), "l"(g))
#define CP_COMMIT() asm volatile("cp.async.commit_group;" ::: "memory")
#define CP_WAIT1()  asm volatile("cp.async.wait_group 1;" ::: "memory")
#define CP_WAIT0()  asm volatile("cp.async.wait_group 0;" ::: "memory")

__device__ __forceinline__ uint32_t packbf2(__nv_bfloat16 lo, __nv_bfloat16 hi) {
    __nv_bfloat162 t = __halves2bfloat162(lo, hi);
    return *(uint32_t*)&t;
}

__device__ __forceinline__ void split4(const float4 v, __nv_bfloat16* h,
                                       __nv_bfloat16* l, int i4) {
    __nv_bfloat16 h0 = __float2bfloat16_rn(v.x);
    __nv_bfloat16 h1 = __float2bfloat16_rn(v.y);
    __nv_bfloat16 h2 = __float2bfloat16_rn(v.z);
    __nv_bfloat16 h3 = __float2bfloat16_rn(v.w);
    h[i4 * 4 + 0] = h0; h[i4 * 4 + 1] = h1; h[i4 * 4 + 2] = h2; h[i4 * 4 + 3] = h3;
    l[i4 * 4 + 0] = __float2bfloat16_rn(v.x - __bfloat162float(h0));
    l[i4 * 4 + 1] = __float2bfloat16_rn(v.y - __bfloat162float(h1));
    l[i4 * 4 + 2] = __float2bfloat16_rn(v.z - __bfloat162float(h2));
    l[i4 * 4 + 3] = __float2bfloat16_rn(v.w - __bfloat162float(h3));
}

// ---------------------------------------------------------------------------
// split: fp32 -> bf16 hi + lo (used for o after flash)
// ---------------------------------------------------------------------------
__global__ void split_bf16(const float* __restrict__ s,
                           __nv_bfloat16* __restrict__ h,
                           __nv_bfloat16* __restrict__ l, int n4) {
    const int i = blockIdx.x * blockDim.x + threadIdx.x;
    if (i >= n4) return;
    split4(((const float4*)s)[i], h, l, i);
}

// ---------------------------------------------------------------------------
// prep_split: rope table + all input/weight hi/lo splits in ONE launch.
// blocks: [0,512) rope table; then x 8192, Wq 4096, Wk 2048, Wv 2048, Wo 4096
// ---------------------------------------------------------------------------
#define PREP_BLOCKS 20992
__global__ void __launch_bounds__(256) prep_split(const float* __restrict__ x,
                                                  const float* __restrict__ Wq,
                                                  const float* __restrict__ Wk,
                                                  const float* __restrict__ Wv,
                                                  const float* __restrict__ Wo) {
    int bid = blockIdx.x;
    const int tid = threadIdx.x;
    if (bid < 512) {
        const int idx = bid * 256 + tid;
        const int i = idx & 63;
        const int pos = idx >> 6;
        const double inv = exp(-(double)i / 64.0 * log(10000.0));
        double sd, cd;
        sincos((double)pos * inv, &sd, &cd);
        g_cos[idx] = (float)cd;
        g_sin[idx] = (float)sd;
        return;
    }
    bid -= 512;
    const float* src;
    __nv_bfloat16 *h, *l;
    int base;
    if (bid < 8192)       { src = x;  h = g_xh;  l = g_xl;  base = bid; }
    else if (bid < 12288) { src = Wq; h = g_wqh; l = g_wql; base = bid - 8192; }
    else if (bid < 14336) { src = Wk; h = g_wkh; l = g_wkl; base = bid - 12288; }
    else if (bid < 16384) { src = Wv; h = g_wvh; l = g_wvl; base = bid - 14336; }
    else                  { src = Wo; h = g_woh; l = g_wol; base = bid - 16384; }
    const int i = base * 256 + tid;
    split4(((const float4*)src)[i], h, l, i);
}

// ---------------------------------------------------------------------------
// mma.sync bf16x3 GEMM (validated)
// ---------------------------------------------------------------------------
#define GP 72
#define GT_TILE (128 * GP)
#define GT_SMEM (4 * GT_TILE * 2)

__global__ void __launch_bounds__(256) gemm_mma(const __nv_bfloat16* __restrict__ Ah,
                                                const __nv_bfloat16* __restrict__ Al,
                                                const __nv_bfloat16* __restrict__ Bh,
                                                const __nv_bfloat16* __restrict__ Bl,
                                                float* __restrict__ C,
                                                int N, int K) {
    extern __shared__ __nv_bfloat16 sb[];
    __nv_bfloat16* Ash = sb;
    __nv_bfloat16* Asl = sb + GT_TILE;
    __nv_bfloat16* Bsh = sb + 2 * GT_TILE;
    __nv_bfloat16* Bsl = sb + 3 * GT_TILE;

    const int tid = threadIdx.x;
    const int lane = tid & 31;
    const int wid = tid >> 5;
    const int wm = (wid >> 2) * 64;
    const int wn = (wid & 3) * 32;
    const int m0 = blockIdx.y * 128;
    const int n0 = blockIdx.x * 128;

    const int srow = tid >> 1;
    const int sub  = (tid & 1) * 4;

    float acc[4][4][4];
#pragma unroll
    for (int i = 0; i < 4; ++i)
#pragma unroll
        for (int j = 0; j < 4; ++j)
#pragma unroll
            for (int q = 0; q < 4; ++q) acc[i][j][q] = 0.f;

    const int arow = lane & 15, acol = (lane >> 4) << 3;
    const int brow = lane & 7,  bcol = ((lane >> 3) & 1) << 3;
    const uint32_t a_h0 = smem_u32(Ash + (wm + arow) * GP + acol);
    const uint32_t a_l0 = smem_u32(Asl + (wm + arow) * GP + acol);
    const uint32_t b_h0 = smem_u32(Bsh + (wn + brow) * GP + bcol);
    const uint32_t b_l0 = smem_u32(Bsl + (wn + brow) * GP + bcol);

    for (int kc = 0; kc < K; kc += 64) {
        {
            const char* gA = (const char*)(Ah + (size_t)(m0 + srow) * K + kc);
            const char* gAl = (const char*)(Al + (size_t)(m0 + srow) * K + kc);
            const char* gB = (const char*)(Bh + (size_t)(n0 + srow) * K + kc);
            const char* gBl = (const char*)(Bl + (size_t)(n0 + srow) * K + kc);
            char* dA  = (char*)(Ash + srow * GP);
            char* dAl = (char*)(Asl + srow * GP);
            char* dB  = (char*)(Bsh + srow * GP);
            char* dBl = (char*)(Bsl + srow * GP);
#pragma unroll
            for (int u = 0; u < 4; ++u) {
                const int off = (sub + u) * 16;
                *(float4*)(dA + off)  = *(const float4*)(gA + off);
                *(float4*)(dAl + off) = *(const float4*)(gAl + off);
                *(float4*)(dB + off)  = *(const float4*)(gB + off);
                *(float4*)(dBl + off) = *(const float4*)(gBl + off);
            }
        }
        __syncthreads();

#pragma unroll
        for (int ks = 0; ks < 4; ++ks) {
            const uint32_t koff = ks * 16 * 2;
            uint32_t ah[4][4], al[4][4], bh[4][2], bl[4][2];
#pragma unroll
            for (int mi = 0; mi < 4; ++mi) {
                LDSM4(ah[mi], a_h0 + mi * 16 * GP * 2 + koff);
                LDSM4(al[mi], a_l0 + mi * 16 * GP * 2 + koff);
            }
#pragma unroll
            for (int ni = 0; ni < 4; ++ni) {
                LDSM2(bh[ni], b_h0 + ni * 8 * GP * 2 + koff);
                LDSM2(bl[ni], b_l0 + ni * 8 * GP * 2 + koff);
            }
#pragma unroll
            for (int mi = 0; mi < 4; ++mi)
#pragma unroll
                for (int ni = 0; ni < 4; ++ni) {
                    MMA16816(acc[mi][ni], ah[mi], bh[ni]);
                    MMA16816(acc[mi][ni], ah[mi], bl[ni]);
                    MMA16816(acc[mi][ni], al[mi], bh[ni]);
                }
        }
        __syncthreads();
    }

    const int erow = lane >> 2;
    const int ecol = (lane & 3) * 2;
#pragma unroll
    for (int mi = 0; mi < 4; ++mi)
#pragma unroll
        for (int ni = 0; ni < 4; ++ni) {
            float* cp = C + (size_t)(m0 + wm + mi * 16 + erow) * N + n0 + wn + ni * 8 + ecol;
            *(float2*)cp = make_float2(acc[mi][ni][0], acc[mi][ni][1]);
            *(float2*)(cp + 8 * (size_t)N) = make_float2(acc[mi][ni][2], acc[mi][ni][3]);
        }
}

// ---------------------------------------------------------------------------
// rope_vt: fused RoPE+split (Q,K) and V split+transpose in ONE launch.
// blocks [0,24576): rope; [24576, 28672): vt
// ---------------------------------------------------------------------------
#define RVT_BLOCKS 28672
__global__ void __launch_bounds__(256) rope_vt(const float* __restrict__ q,
                                               const float* __restrict__ k,
                                               const float* __restrict__ v) {
    const int bid = blockIdx.x;
    const int tid = threadIdx.x;
    if (bid < 24576) {
        const long long idx = (long long)bid * 256 + tid;
        const int i  = (int)(idx & 63);
        long long r  = idx >> 6;
        const int hh = (int)(r % (NH_ + NKV_));
        r /= (NH_ + NKV_);
        const int bl  = (int)r;
        const int pos = bl & (L_ - 1);

        const float* src;
        __nv_bfloat16 *dh, *dl;
        size_t off;
        if (hh < NH_) {
            off = ((size_t)bl * NH_ + hh) * HD_;
            src = q + off; dh = g_qh + off; dl = g_ql + off;
        } else {
            off = ((size_t)bl * NKV_ + (hh - NH_)) * HD_;
            src = k + off; dh = g_kh + off; dl = g_kl + off;
        }

        const float c = g_cos[pos * 64 + i];
        const float s = g_sin[pos * 64 + i];
        const float a = src[i];
        const float b = src[i + 64];
        const float r0 = a * c - b * s;
        const float r1 = b * c + a * s;

        const __nv_bfloat16 h0 = __float2bfloat16_rn(r0);
        const __nv_bfloat16 h1 = __float2bfloat16_rn(r1);
        dh[i]      = h0;
        dh[i + 64] = h1;
        dl[i]      = __float2bfloat16_rn(r0 - __bfloat162float(h0));
        dl[i + 64] = __float2bfloat16_rn(r1 - __bfloat162float(h1));
    } else {
        __shared__ float s[32][33];
        const int lb = bid - 24576;
        const int l0 = (lb & 63) * 32;
        const int d0 = ((lb >> 6) & 3) * 32;
        const int bk = lb >> 8;               // b*NKV + kvh
        const int b = bk >> 3, kvh = bk & 7;
        const int tx = tid & 31, ty = tid >> 5;

        const float* vb = v + ((size_t)b * L_ * NKV_ + kvh) * HD_;
#pragma unroll
        for (int rr = 0; rr < 4; ++rr) {
            const int lr = ty * 4 + rr;
            s[lr][tx] = vb[(size_t)(l0 + lr) * (NKV_ * HD_) + d0 + tx];
        }
        __syncthreads();

        __nv_bfloat16* oh = g_vth + (size_t)bk * HD_ * L_;
        __nv_bfloat16* ol = g_vtl + (size_t)bk * HD_ * L_;
#pragma unroll
        for (int rr = 0; rr < 4; ++rr) {
            const int dr = ty * 4 + rr;
            const float val = s[tx][dr];
            const __nv_bfloat16 hv = __float2bfloat16_rn(val);
            oh[(size_t)(d0 + dr) * L_ + l0 + tx] = hv;
            ol[(size_t)(d0 + dr) * L_ + l0 + tx] =
                __float2bfloat16_rn(val - __bfloat162float(hv));
        }
    }
}

// ---------------------------------------------------------------------------
// Flash attention v8: 64 q-rows / 128 threads, k-tile 32, DOUBLE-BUFFERED
// cp.async staging, 110.6KB smem -> 2 CTAs/SM. Full 3-product split math.
// smem: Qh[64][272B], Ql; 2 x { Kh[32][272B], Kl, Vth[128][80B], Vtl }
// ---------------------------------------------------------------------------
#define OQH 0
#define OQL 17408
#define OBUF 34816
#define FBUF 37888
#define BKH 0
#define BKL 8704
#define BVH 17408
#define BVL 27648
#define FM_SMEM 110592

__device__ __forceinline__ void fm_stage(uint32_t sbuf,
                                         const char* kh, const char* kl,
                                         const char* vth, const char* vtl,
                                         int k0, int tid) {
    // K tile: 32 rows x 256B (pitch 272)
#pragma unroll
    for (int i = tid; i < 32 * 16; i += 128) {
        const int row = i >> 4;
        const int u = (i & 15) << 4;
        const size_t g = (size_t)(k0 + row) * (NKV_ * HD_ * 2) + u;
        const uint32_t d = sbuf + row * 272 + u;
        CP_ASYNC16(d + BKH, kh + g);
        CP_ASYNC16(d + BKL, kl + g);
    }
    // V^T tile: 128 rows x 64B (pitch 80)
#pragma unroll
    for (int i = tid; i < 128 * 4; i += 128) {
        const int row = i >> 2;
        const int u = (i & 3) << 4;
        const size_t g = (size_t)row * (L_ * 2) + (size_t)k0 * 2 + u;
        const uint32_t d = sbuf + row * 80 + u;
        CP_ASYNC16(d + BVH, vth + g);
        CP_ASYNC16(d + BVL, vtl + g);
    }
}

__global__ void __launch_bounds__(128) flash_mma(const __nv_bfloat16* __restrict__ Qhg,
                                                 const __nv_bfloat16* __restrict__ Qlg,
                                                 const __nv_bfloat16* __restrict__ Khg,
                                                 const __nv_bfloat16* __restrict__ Klg,
                                                 const __nv_bfloat16* __restrict__ Vthg,
                                                 const __nv_bfloat16* __restrict__ Vtlg,
                                                 float* __restrict__ O) {
    extern __shared__ char smem[];
    const uint32_t sQ = smem_u32(smem);

    const int tid = threadIdx.x;
    const int lane = tid & 31, wid = tid >> 5;   // 4 warps
    const int b = blockIdx.z, h = blockIdx.y;
    const int kvh = h >> 1;
    const int qt = (gridDim.x - 1) - blockIdx.x;   // heavy tiles first
    const int q0 = qt * 64;
    const int wrow = wid * 16;

    const char* qh_g = (const char*)(Qhg + ((size_t)(b * L_ + q0) * NH_ + h) * HD_);
    const char* ql_g = (const char*)(Qlg + ((size_t)(b * L_ + q0) * NH_ + h) * HD_);
    const char* kh_g = (const char*)(Khg + ((size_t)b * L_ * NKV_ + kvh) * HD_);
    const char* kl_g = (const char*)(Klg + ((size_t)b * L_ * NKV_ + kvh) * HD_);
    const char* vth_g = (const char*)(Vthg + (size_t)(b * NKV_ + kvh) * HD_ * L_);
    const char* vtl_g = (const char*)(Vtlg + (size_t)(b * NKV_ + kvh) * HD_ * L_);

    // stage Q once + first K/V tile, one commit group (group 0)
    for (int i = tid; i < 64 * 16; i += 128) {
        const int row = i >> 4;
        const int u = (i & 15) << 4;
        const size_t g = (size_t)row * (NH_ * HD_ * 2) + u;
        const uint32_t d = row * 272 + u;
        CP_ASYNC16(sQ + OQH + d, qh_g + g);
        CP_ASYNC16(sQ + OQL + d, ql_g + g);
    }
    fm_stage(sQ + OBUF, kh_g, kl_g, vth_g, vtl_g, 0, tid);
    CP_COMMIT();

    // fragment smem base addresses (buffer 0)
    const uint32_t aQh = sQ + OQH + (wrow + (lane & 15)) * 272 + ((lane >> 4) << 4);
    const uint32_t aQl = aQh + (OQL - OQH);
    const uint32_t bK0 = sQ + OBUF + (lane & 7) * 272 + (((lane >> 3) & 1) << 4);
    const uint32_t bV0 = sQ + OBUF + BVH + (lane & 7) * 80 + (((lane >> 3) & 1) << 4);

    float m0 = -1e30f, m1 = -1e30f, l0 = 0.f, l1 = 0.f;
    float ao[16][4];
#pragma unroll
    for (int i = 0; i < 16; ++i)
#pragma unroll
        for (int j = 0; j < 4; ++j) ao[i][j] = 0.f;

    const int tmax = 2 * qt + 2;
    for (int t = 0; t < tmax; ++t) {
        const int k0 = t * 32;
        const uint32_t boff = (uint32_t)(t & 1) * FBUF;

        if (t + 1 < tmax) {
            fm_stage(sQ + OBUF + (uint32_t)((t + 1) & 1) * FBUF,
                     kh_g, kl_g, vth_g, vtl_g, k0 + 32, tid);
            CP_COMMIT();
            CP_WAIT1();
        } else {
            CP_WAIT0();
        }
        __syncthreads();

        const uint32_t bKh = bK0 + boff;
        const uint32_t bKl = bKh + BKL;
        const uint32_t bVh = bV0 + boff;
        const uint32_t bVl = bVh + (BVL - BVH);

        // ---- S = Q @ K^T (3-way split), 16q x 32k per warp ----
        float sc[4][4];
#pragma unroll
        for (int ni = 0; ni < 4; ++ni)
#pragma unroll
            for (int j = 0; j < 4; ++j) sc[ni][j] = 0.f;

#pragma unroll
        for (int ks = 0; ks < 8; ++ks) {
            const uint32_t koff = ks * 32;
            uint32_t ah[4], al[4];
            LDSM4(ah, aQh + koff);
            LDSM4(al, aQl + koff);
#pragma unroll
            for (int ni = 0; ni < 4; ++ni) {
                uint32_t bh[2], bl[2];
                LDSM2(bh, bKh + ni * (8 * 272) + koff);
                LDSM2(bl, bKl + ni * (8 * 272) + koff);
                MMA16816(sc[ni], ah, bh);
                MMA16816(sc[ni], ah, bl);
                MMA16816(sc[ni], al, bh);
            }
        }

#pragma unroll
        for (int ni = 0; ni < 4; ++ni)
#pragma unroll
            for (int j = 0; j < 4; ++j) sc[ni][j] *= SCALE_;

        if (t >= 2 * qt) {   // diagonal-overlapping tiles
            const int qr0 = q0 + wrow + (lane >> 2);
#pragma unroll
            for (int ni = 0; ni < 4; ++ni) {
                const int kc = k0 + ni * 8 + (lane & 3) * 2;
                if (kc > qr0)         sc[ni][0] = -1e30f;
                if (kc + 1 > qr0)     sc[ni][1] = -1e30f;
                if (kc > qr0 + 8)     sc[ni][2] = -1e30f;
                if (kc + 1 > qr0 + 8) sc[ni][3] = -1e30f;
            }
        }

        // ---- online softmax ----
        float mx0 = -1e30f, mx1 = -1e30f;
#pragma unroll
        for (int ni = 0; ni < 4; ++ni) {
            mx0 = fmaxf(mx0, fmaxf(sc[ni][0], sc[ni][1]));
            mx1 = fmaxf(mx1, fmaxf(sc[ni][2], sc[ni][3]));
        }
        mx0 = fmaxf(mx0, __shfl_xor_sync(0xffffffffu, mx0, 1));
        mx0 = fmaxf(mx0, __shfl_xor_sync(0xffffffffu, mx0, 2));
        mx1 = fmaxf(mx1, __shfl_xor_sync(0xffffffffu, mx1, 1));
        mx1 = fmaxf(mx1, __shfl_xor_sync(0xffffffffu, mx1, 2));

        const float nm0 = fmaxf(m0, mx0), nm1 = fmaxf(m1, mx1);
        const float al0 = __expf(m0 - nm0), al1 = __expf(m1 - nm1);
        float s0 = 0.f, s1 = 0.f;
#pragma unroll
        for (int ni = 0; ni < 4; ++ni) {
            sc[ni][0] = __expf(sc[ni][0] - nm0); s0 += sc[ni][0];
            sc[ni][1] = __expf(sc[ni][1] - nm0); s0 += sc[ni][1];
            sc[ni][2] = __expf(sc[ni][2] - nm1); s1 += sc[ni][2];
            sc[ni][3] = __expf(sc[ni][3] - nm1); s1 += sc[ni][3];
        }
        s0 += __shfl_xor_sync(0xffffffffu, s0, 1);
        s0 += __shfl_xor_sync(0xffffffffu, s0, 2);
        s1 += __shfl_xor_sync(0xffffffffu, s1, 1);
        s1 += __shfl_xor_sync(0xffffffffu, s1, 2);
        l0 = l0 * al0 + s0; l1 = l1 * al1 + s1;
        m0 = nm0; m1 = nm1;

#pragma unroll
        for (int i = 0; i < 16; ++i) {
            ao[i][0] *= al0; ao[i][1] *= al0;
            ao[i][2] *= al1; ao[i][3] *= al1;
        }

        // ---- O += P @ V (3-product split) ----
#pragma unroll
        for (int ks = 0; ks < 2; ++ks) {
            const float p0 = sc[2 * ks][0], p1 = sc[2 * ks][1];
            const float p2 = sc[2 * ks][2], p3 = sc[2 * ks][3];
            const float p4 = sc[2 * ks + 1][0], p5 = sc[2 * ks + 1][1];
            const float p6 = sc[2 * ks + 1][2], p7 = sc[2 * ks + 1][3];
            const __nv_bfloat16 q0b = __float2bfloat16_rn(p0), q1b = __float2bfloat16_rn(p1);
            const __nv_bfloat16 q2b = __float2bfloat16_rn(p2), q3b = __float2bfloat16_rn(p3);
            const __nv_bfloat16 q4b = __float2bfloat16_rn(p4), q5b = __float2bfloat16_rn(p5);
            const __nv_bfloat16 q6b = __float2bfloat16_rn(p6), q7b = __float2bfloat16_rn(p7);
            uint32_t pah[4], pal[4];
            pah[0] = packbf2(q0b, q1b);
            pah[1] = packbf2(q2b, q3b);
            pah[2] = packbf2(q4b, q5b);
            pah[3] = packbf2(q6b, q7b);
            pal[0] = packbf2(__float2bfloat16_rn(p0 - __bfloat162float(q0b)),
                             __float2bfloat16_rn(p1 - __bfloat162float(q1b)));
            pal[1] = packbf2(__float2bfloat16_rn(p2 - __bfloat162float(q2b)),
                             __float2bfloat16_rn(p3 - __bfloat162float(q3b)));
            pal[2] = packbf2(__float2bfloat16_rn(p4 - __bfloat162float(q4b)),
                             __float2bfloat16_rn(p5 - __bfloat162float(q5b)));
            pal[3] = packbf2(__float2bfloat16_rn(p6 - __bfloat162float(q6b)),
                             __float2bfloat16_rn(p7 - __bfloat162float(q7b)));

            const uint32_t koff = ks * 32;
#pragma unroll
            for (int ni = 0; ni < 16; ++ni) {
                uint32_t bh[2], bl[2];
                LDSM2(bh, bVh + ni * (8 * 80) + koff);
                LDSM2(bl, bVl + ni * (8 * 80) + koff);
                MMA16816(ao[ni], pah, bh);
                MMA16816(ao[ni], pal, bh);
                MMA16816(ao[ni], pah, bl);
            }
        }
        __syncthreads();   // compute done before this buffer is restaged
    }

    // ---- epilogue ----
    const float inv0 = 1.0f / l0, inv1 = 1.0f / l1;
    const int r0 = q0 + wrow + (lane >> 2);
    const int ecol = (lane & 3) * 2;
    float* Ob0 = O + ((size_t)(b * L_ + r0) * NH_ + h) * HD_ + ecol;
    float* Ob1 = O + ((size_t)(b * L_ + r0 + 8) * NH_ + h) * HD_ + ecol;
#pragma unroll
    for (int ni = 0; ni < 16; ++ni) {
        *(float2*)(Ob0 + ni * 8) = make_float2(ao[ni][0] * inv0, ao[ni][1] * inv0);
        *(float2*)(Ob1 + ni * 8) = make_float2(ao[ni][2] * inv1, ao[ni][3] * inv1);
    }
}

// ---------------------------------------------------------------------------
extern "C" void kernel_launch(void* const* d_in, const int* in_sizes, int n_in,
                              void* d_out, int out_size) {
    const float* x  = (const float*)d_in[0];
    const float* Wq = (const float*)d_in[1];
    const float* Wk = (const float*)d_in[2];
    const float* Wv = (const float*)d_in[3];
    const float* Wo = (const float*)d_in[4];
    float* out = (float*)d_out;

    float *q, *k, *v, *o;
    cudaGetSymbolAddress((void**)&q, g_q);
    cudaGetSymbolAddress((void**)&k, g_k);
    cudaGetSymbolAddress((void**)&v, g_v);
    cudaGetSymbolAddress((void**)&o, g_o);
    __nv_bfloat16 *xh, *xl, *wqh, *wql, *wkh, *wkl, *wvh, *wvl, *woh, *wol, *oh, *ol;
    __nv_bfloat16 *qh, *ql, *kh, *kl, *vth, *vtl;
    cudaGetSymbolAddress((void**)&xh, g_xh);   cudaGetSymbolAddress((void**)&xl, g_xl);
    cudaGetSymbolAddress((void**)&wqh, g_wqh); cudaGetSymbolAddress((void**)&wql, g_wql);
    cudaGetSymbolAddress((void**)&wkh, g_wkh); cudaGetSymbolAddress((void**)&wkl, g_wkl);
    cudaGetSymbolAddress((void**)&wvh, g_wvh); cudaGetSymbolAddress((void**)&wvl, g_wvl);
    cudaGetSymbolAddress((void**)&woh, g_woh); cudaGetSymbolAddress((void**)&wol, g_wol);
    cudaGetSymbolAddress((void**)&oh, g_oh);   cudaGetSymbolAddress((void**)&ol, g_ol);
    cudaGetSymbolAddress((void**)&qh, g_qh);   cudaGetSymbolAddress((void**)&ql, g_ql);
    cudaGetSymbolAddress((void**)&kh, g_kh);   cudaGetSymbolAddress((void**)&kl, g_kl);
    cudaGetSymbolAddress((void**)&vth, g_vth); cudaGetSymbolAddress((void**)&vtl, g_vtl);

    const int M = B_ * L_;       // 4096
    const int NKVD = NKV_ * HD_; // 1024

    cudaFuncSetAttribute(gemm_mma, cudaFuncAttributeMaxDynamicSharedMemorySize, GT_SMEM);
    cudaFuncSetAttribute(flash_mma, cudaFuncAttributeMaxDynamicSharedMemorySize, FM_SMEM);

    // launch 0: all prep (rope table + 5 splits)
    prep_split<<<PREP_BLOCKS, 256>>>(x, Wq, Wk, Wv, Wo);

    // launches 1-3: projections
    gemm_mma<<<dim3(D_ / 128, M / 128), 256, GT_SMEM>>>(xh, xl, wqh, wql, q, D_, D_);
    gemm_mma<<<dim3(NKVD / 128, M / 128), 256, GT_SMEM>>>(xh, xl, wkh, wkl, k, NKVD, D_);
    gemm_mma<<<dim3(NKVD / 128, M / 128), 256, GT_SMEM>>>(xh, xl, wvh, wvl, v, NKVD, D_);

    // launch 4: rope+split Q/K and V split+transpose
    rope_vt<<<RVT_BLOCKS, 256>>>(q, k, v);

    // launch 5: flash attention (ncu capture slot)
    flash_mma<<<dim3(L_ / 64, NH_, B_), 128, FM_SMEM>>>(qh, ql, kh, kl, vth, vtl, o);

    // launches 6-7: output projection
    split_bf16<<<(M * D_ / 4 + 255) / 256, 256>>>(o, oh, ol, M * D_ / 4);
    gemm_mma<<<dim3(D_ / 128, M / 128), 256, GT_SMEM>>>(oh, ol, woh, wol, out, D_, D_);
}

// round 12
// speedup vs baseline: 1.1372x; 1.1372x over previous
#include <cuda_runtime.h>
#include <cuda_bf16.h>
#include <math.h>
#include <stdint.h>

#define B_  2
#define L_  2048
#define D_  2048
#define NH_ 16
#define NKV_ 8
#define HD_ 128
#define GQ_ 2
#define SCALE_ 0.08838834764831845f  // 128^-0.5

// ---------------- scratch (static device globals) ----------------
__device__ float g_q[(size_t)B_ * L_ * NH_ * HD_];
__device__ float g_k[(size_t)B_ * L_ * NKV_ * HD_];
__device__ float g_v[(size_t)B_ * L_ * NKV_ * HD_];
__device__ float g_o[(size_t)B_ * L_ * NH_ * HD_];
__device__ float g_cos[(size_t)L_ * 64];
__device__ float g_sin[(size_t)L_ * 64];

__device__ __nv_bfloat16 g_xh[(size_t)B_ * L_ * D_];
__device__ __nv_bfloat16 g_xl[(size_t)B_ * L_ * D_];
__device__ __nv_bfloat16 g_wqh[(size_t)D_ * D_];
__device__ __nv_bfloat16 g_wql[(size_t)D_ * D_];
__device__ __nv_bfloat16 g_wkh[(size_t)NKV_ * HD_ * D_];
__device__ __nv_bfloat16 g_wkl[(size_t)NKV_ * HD_ * D_];
__device__ __nv_bfloat16 g_wvh[(size_t)NKV_ * HD_ * D_];
__device__ __nv_bfloat16 g_wvl[(size_t)NKV_ * HD_ * D_];
__device__ __nv_bfloat16 g_woh[(size_t)D_ * D_];
__device__ __nv_bfloat16 g_wol[(size_t)D_ * D_];
__device__ __nv_bfloat16 g_oh[(size_t)B_ * L_ * D_];
__device__ __nv_bfloat16 g_ol[(size_t)B_ * L_ * D_];

// pre-split (and RoPE'd / transposed) attention operands
__device__ __nv_bfloat16 g_qh[(size_t)B_ * L_ * NH_ * HD_];
__device__ __nv_bfloat16 g_ql[(size_t)B_ * L_ * NH_ * HD_];
__device__ __nv_bfloat16 g_kh[(size_t)B_ * L_ * NKV_ * HD_];
__device__ __nv_bfloat16 g_kl[(size_t)B_ * L_ * NKV_ * HD_];
__device__ __nv_bfloat16 g_vth[(size_t)B_ * NKV_ * HD_ * L_];
__device__ __nv_bfloat16 g_vtl[(size_t)B_ * NKV_ * HD_ * L_];

// ---------------- helpers ----------------
__device__ __forceinline__ uint32_t smem_u32(const void* p) {
    uint32_t a;
    asm("{ .reg .u64 t; cvta.to.shared.u64 t, %1; cvt.u32.u64 %0, t; }"
        : "=r"(a) : "l"(p));
    return a;
}
#define LDSM4(r, a) \
    asm volatile("ldmatrix.sync.aligned.m8n8.x4.shared.b16 {%0,%1,%2,%3}, [%4];" \
                 : "=r"((r)[0]), "=r"((r)[1]), "=r"((r)[2]), "=r"((r)[3]) : "r"(a))
#define LDSM2(r, a) \
    asm volatile("ldmatrix.sync.aligned.m8n8.x2.shared.b16 {%0,%1}, [%2];" \
                 : "=r"((r)[0]), "=r"((r)[1]) : "r"(a))
#define MMA16816(d, a, b) \
    asm volatile("mma.sync.aligned.m16n8k16.row.col.f32.bf16.bf16.f32 " \
                 "{%0,%1,%2,%3}, {%4,%5,%6,%7}, {%8,%9}, {%0,%1,%2,%3};" \
                 : "+f"((d)[0]), "+f"((d)[1]), "+f"((d)[2]), "+f"((d)[3]) \
                 : "r"((a)[0]), "r"((a)[1]), "r"((a)[2]), "r"((a)[3]), \
                   "r"((b)[0]), "r"((b)[1]))
#define CP_ASYNC16(s, g) \
    asm volatile("cp.async.cg.shared.global [%0], [%1], 16;" :: "r"(s), "l"(g))
#define CP_COMMIT() asm volatile("cp.async.commit_group;" ::: "memory")
#define CP_WAIT1()  asm volatile("cp.async.wait_group 1;" ::: "memory")
#define CP_WAIT0()  asm volatile("cp.async.wait_group 0;" ::: "memory")

__device__ __forceinline__ uint32_t packbf2(__nv_bfloat16 lo, __nv_bfloat16 hi) {
    __nv_bfloat162 t = __halves2bfloat162(lo, hi);
    return *(uint32_t*)&t;
}

__device__ __forceinline__ void split4(const float4 v, __nv_bfloat16* h,
                                       __nv_bfloat16* l, int i4) {
    __nv_bfloat16 h0 = __float2bfloat16_rn(v.x);
    __nv_bfloat16 h1 = __float2bfloat16_rn(v.y);
    __nv_bfloat16 h2 = __float2bfloat16_rn(v.z);
    __nv_bfloat16 h3 = __float2bfloat16_rn(v.w);
    h[i4 * 4 + 0] = h0; h[i4 * 4 + 1] = h1; h[i4 * 4 + 2] = h2; h[i4 * 4 + 3] = h3;
    l[i4 * 4 + 0] = __float2bfloat16_rn(v.x - __bfloat162float(h0));
    l[i4 * 4 + 1] = __float2bfloat16_rn(v.y - __bfloat162float(h1));
    l[i4 * 4 + 2] = __float2bfloat16_rn(v.z - __bfloat162float(h2));
    l[i4 * 4 + 3] = __float2bfloat16_rn(v.w - __bfloat162float(h3));
}

// ---------------------------------------------------------------------------
__global__ void split_bf16(const float* __restrict__ s,
                           __nv_bfloat16* __restrict__ h,
                           __nv_bfloat16* __restrict__ l, int n4) {
    const int i = blockIdx.x * blockDim.x + threadIdx.x;
    if (i >= n4) return;
    split4(((const float4*)s)[i], h, l, i);
}

// ---------------------------------------------------------------------------
// prep_split: rope table + all input/weight hi/lo splits in ONE launch.
// ---------------------------------------------------------------------------
#define PREP_BLOCKS 20992
__global__ void __launch_bounds__(256) prep_split(const float* __restrict__ x,
                                                  const float* __restrict__ Wq,
                                                  const float* __restrict__ Wk,
                                                  const float* __restrict__ Wv,
                                                  const float* __restrict__ Wo) {
    int bid = blockIdx.x;
    const int tid = threadIdx.x;
    if (bid < 512) {
        const int idx = bid * 256 + tid;
        const int i = idx & 63;
        const int pos = idx >> 6;
        const double inv = exp(-(double)i / 64.0 * log(10000.0));
        double sd, cd;
        sincos((double)pos * inv, &sd, &cd);
        g_cos[idx] = (float)cd;
        g_sin[idx] = (float)sd;
        return;
    }
    bid -= 512;
    const float* src;
    __nv_bfloat16 *h, *l;
    int base;
    if (bid < 8192)       { src = x;  h = g_xh;  l = g_xl;  base = bid; }
    else if (bid < 12288) { src = Wq; h = g_wqh; l = g_wql; base = bid - 8192; }
    else if (bid < 14336) { src = Wk; h = g_wkh; l = g_wkl; base = bid - 12288; }
    else if (bid < 16384) { src = Wv; h = g_wvh; l = g_wvl; base = bid - 14336; }
    else                  { src = Wo; h = g_woh; l = g_wol; base = bid - 16384; }
    const int i = base * 256 + tid;
    split4(((const float4*)src)[i], h, l, i);
}

// ---------------------------------------------------------------------------
// mma.sync bf16x3 GEMM, cp.async DOUBLE-BUFFERED staging.
// Tile 128x128, K-chunk 64. Stage bytes: Ah 0, Al 18432, Bh 36864, Bl 55296.
// Stage size 73728 B x 2 buffers = 147456 B smem.
// ---------------------------------------------------------------------------
#define GSTG 73728
#define GT_SMEM (2 * GSTG)

__global__ void __launch_bounds__(256) gemm_mma(const __nv_bfloat16* __restrict__ Ah,
                                                const __nv_bfloat16* __restrict__ Al,
                                                const __nv_bfloat16* __restrict__ Bh,
                                                const __nv_bfloat16* __restrict__ Bl,
                                                float* __restrict__ C,
                                                int N, int K) {
    extern __shared__ __nv_bfloat16 sb[];
    const uint32_t sbase = smem_u32(sb);

    const int tid = threadIdx.x;
    const int lane = tid & 31;
    const int wid = tid >> 5;
    const int wm = (wid >> 2) * 64;
    const int wn = (wid & 3) * 32;
    const int m0 = blockIdx.y * 128;
    const int n0 = blockIdx.x * 128;

    const int srow = tid >> 1;
    const int sub  = (tid & 1) * 4;

    const char* gAh = (const char*)(Ah + (size_t)(m0 + srow) * K);
    const char* gAl = (const char*)(Al + (size_t)(m0 + srow) * K);
    const char* gBh = (const char*)(Bh + (size_t)(n0 + srow) * K);
    const char* gBl = (const char*)(Bl + (size_t)(n0 + srow) * K);
    const uint32_t srow144 = srow * 144;

    auto stage = [&](int kc, uint32_t sbuf) {
#pragma unroll
        for (int u = 0; u < 4; ++u) {
            const int off = (sub + u) * 16;
            const uint32_t d = sbuf + srow144 + off;
            const int gofs = kc * 2 + off;
            CP_ASYNC16(d,         gAh + gofs);
            CP_ASYNC16(d + 18432, gAl + gofs);
            CP_ASYNC16(d + 36864, gBh + gofs);
            CP_ASYNC16(d + 55296, gBl + gofs);
        }
    };

    float acc[4][4][4];
#pragma unroll
    for (int i = 0; i < 4; ++i)
#pragma unroll
        for (int j = 0; j < 4; ++j)
#pragma unroll
            for (int q = 0; q < 4; ++q) acc[i][j][q] = 0.f;

    const int arow = lane & 15, acol = (lane >> 4) << 3;
    const int brow = lane & 7,  bcol = ((lane >> 3) & 1) << 3;
    const uint32_t a_h0 = sbase + (wm + arow) * 144 + acol * 2;
    const uint32_t b_h0 = sbase + 36864 + (wn + brow) * 144 + bcol * 2;

    // prologue: stage chunk 0 into buffer 0
    stage(0, sbase);
    CP_COMMIT();

    const int nchunk = K >> 6;
    for (int c = 0; c < nchunk; ++c) {
        if (c + 1 < nchunk) {
            stage((c + 1) << 6, sbase + (uint32_t)((c + 1) & 1) * GSTG);
            CP_COMMIT();
            CP_WAIT1();
        } else {
            CP_WAIT0();
        }
        __syncthreads();

        const uint32_t boff = (uint32_t)(c & 1) * GSTG;
        const uint32_t a_h = a_h0 + boff;
        const uint32_t a_l = a_h + 18432;
        const uint32_t b_h = b_h0 + boff;
        const uint32_t b_l = b_h + 18432;

#pragma unroll
        for (int ks = 0; ks < 4; ++ks) {
            const uint32_t koff = ks * 32;
            uint32_t ah[4][4], al[4][4], bh[4][2], bl[4][2];
#pragma unroll
            for (int mi = 0; mi < 4; ++mi) {
                LDSM4(ah[mi], a_h + mi * (16 * 144) + koff);
                LDSM4(al[mi], a_l + mi * (16 * 144) + koff);
            }
#pragma unroll
            for (int ni = 0; ni < 4; ++ni) {
                LDSM2(bh[ni], b_h + ni * (8 * 144) + koff);
                LDSM2(bl[ni], b_l + ni * (8 * 144) + koff);
            }
#pragma unroll
            for (int mi = 0; mi < 4; ++mi)
#pragma unroll
                for (int ni = 0; ni < 4; ++ni) {
                    MMA16816(acc[mi][ni], ah[mi], bh[ni]);
                    MMA16816(acc[mi][ni], ah[mi], bl[ni]);
                    MMA16816(acc[mi][ni], al[mi], bh[ni]);
                }
        }
        __syncthreads();   // reads done before this buffer is restaged
    }

    const int erow = lane >> 2;
    const int ecol = (lane & 3) * 2;
#pragma unroll
    for (int mi = 0; mi < 4; ++mi)
#pragma unroll
        for (int ni = 0; ni < 4; ++ni) {
            float* cp = C + (size_t)(m0 + wm + mi * 16 + erow) * N + n0 + wn + ni * 8 + ecol;
            *(float2*)cp = make_float2(acc[mi][ni][0], acc[mi][ni][1]);
            *(float2*)(cp + 8 * (size_t)N) = make_float2(acc[mi][ni][2], acc[mi][ni][3]);
        }
}

// ---------------------------------------------------------------------------
// rope_vt: fused RoPE+split (Q,K) and V split+transpose in ONE launch.
// ---------------------------------------------------------------------------
#define RVT_BLOCKS 28672
__global__ void __launch_bounds__(256) rope_vt(const float* __restrict__ q,
                                               const float* __restrict__ k,
                                               const float* __restrict__ v) {
    const int bid = blockIdx.x;
    const int tid = threadIdx.x;
    if (bid < 24576) {
        const long long idx = (long long)bid * 256 + tid;
        const int i  = (int)(idx & 63);
        long long r  = idx >> 6;
        const int hh = (int)(r % (NH_ + NKV_));
        r /= (NH_ + NKV_);
        const int bl  = (int)r;
        const int pos = bl & (L_ - 1);

        const float* src;
        __nv_bfloat16 *dh, *dl;
        size_t off;
        if (hh < NH_) {
            off = ((size_t)bl * NH_ + hh) * HD_;
            src = q + off; dh = g_qh + off; dl = g_ql + off;
        } else {
            off = ((size_t)bl * NKV_ + (hh - NH_)) * HD_;
            src = k + off; dh = g_kh + off; dl = g_kl + off;
        }

        const float c = g_cos[pos * 64 + i];
        const float s = g_sin[pos * 64 + i];
        const float a = src[i];
        const float b = src[i + 64];
        const float r0 = a * c - b * s;
        const float r1 = b * c + a * s;

        const __nv_bfloat16 h0 = __float2bfloat16_rn(r0);
        const __nv_bfloat16 h1 = __float2bfloat16_rn(r1);
        dh[i]      = h0;
        dh[i + 64] = h1;
        dl[i]      = __float2bfloat16_rn(r0 - __bfloat162float(h0));
        dl[i + 64] = __float2bfloat16_rn(r1 - __bfloat162float(h1));
    } else {
        __shared__ float s[32][33];
        const int lb = bid - 24576;
        const int l0 = (lb & 63) * 32;
        const int d0 = ((lb >> 6) & 3) * 32;
        const int bk = lb >> 8;
        const int b = bk >> 3, kvh = bk & 7;
        const int tx = tid & 31, ty = tid >> 5;

        const float* vb = v + ((size_t)b * L_ * NKV_ + kvh) * HD_;
#pragma unroll
        for (int rr = 0; rr < 4; ++rr) {
            const int lr = ty * 4 + rr;
            s[lr][tx] = vb[(size_t)(l0 + lr) * (NKV_ * HD_) + d0 + tx];
        }
        __syncthreads();

        __nv_bfloat16* oh = g_vth + (size_t)bk * HD_ * L_;
        __nv_bfloat16* ol = g_vtl + (size_t)bk * HD_ * L_;
#pragma unroll
        for (int rr = 0; rr < 4; ++rr) {
            const int dr = ty * 4 + rr;
            const float val = s[tx][dr];
            const __nv_bfloat16 hv = __float2bfloat16_rn(val);
            oh[(size_t)(d0 + dr) * L_ + l0 + tx] = hv;
            ol[(size_t)(d0 + dr) * L_ + l0 + tx] =
                __float2bfloat16_rn(val - __bfloat162float(hv));
        }
    }
}

// ---------------------------------------------------------------------------
// Flash attention (R9 best): 64 q-rows / 128 threads, k-tile 64,
// single K/V buffer, 104KB smem -> 2 CTAs/SM, full 3-product split math.
// ---------------------------------------------------------------------------
#define OQH 0
#define OQL 17408
#define OKH2 34816
#define OKL2 52224
#define OVH2 69632
#define OVL2 88064
#define FM_SMEM 106496

__global__ void __launch_bounds__(128) flash_mma(const __nv_bfloat16* __restrict__ Qhg,
                                                 const __nv_bfloat16* __restrict__ Qlg,
                                                 const __nv_bfloat16* __restrict__ Khg,
                                                 const __nv_bfloat16* __restrict__ Klg,
                                                 const __nv_bfloat16* __restrict__ Vthg,
                                                 const __nv_bfloat16* __restrict__ Vtlg,
                                                 float* __restrict__ O) {
    extern __shared__ char smem[];
    const uint32_t sQ = smem_u32(smem);

    const int tid = threadIdx.x;
    const int lane = tid & 31, wid = tid >> 5;
    const int b = blockIdx.z, h = blockIdx.y;
    const int kvh = h >> 1;
    const int qt = (gridDim.x - 1) - blockIdx.x;
    const int q0 = qt * 64;
    const int wrow = wid * 16;

    const char* qh_g = (const char*)(Qhg + ((size_t)(b * L_ + q0) * NH_ + h) * HD_);
    const char* ql_g = (const char*)(Qlg + ((size_t)(b * L_ + q0) * NH_ + h) * HD_);
    const char* kh_g = (const char*)(Khg + ((size_t)b * L_ * NKV_ + kvh) * HD_);
    const char* kl_g = (const char*)(Klg + ((size_t)b * L_ * NKV_ + kvh) * HD_);
    const char* vth_g = (const char*)(Vthg + (size_t)(b * NKV_ + kvh) * HD_ * L_);
    const char* vtl_g = (const char*)(Vtlg + (size_t)(b * NKV_ + kvh) * HD_ * L_);

    for (int i = tid; i < 64 * 16; i += 128) {
        const int row = i >> 4;
        const int u = (i & 15) << 4;
        const size_t g = (size_t)row * (NH_ * HD_ * 2) + u;
        const uint32_t d = row * 272 + u;
        CP_ASYNC16(sQ + OQH + d, qh_g + g);
        CP_ASYNC16(sQ + OQL + d, ql_g + g);
    }

    const uint32_t aQh = sQ + OQH + (wrow + (lane & 15)) * 272 + ((lane >> 4) << 4);
    const uint32_t aQl = aQh + (OQL - OQH);
    const uint32_t bKh = sQ + OKH2 + (lane & 7) * 272 + (((lane >> 3) & 1) << 4);
    const uint32_t bKl = bKh + (OKL2 - OKH2);
    const uint32_t bVh = sQ + OVH2 + (lane & 7) * 144 + (((lane >> 3) & 1) << 4);
    const uint32_t bVl = bVh + (OVL2 - OVH2);

    float m0 = -1e30f, m1 = -1e30f, l0 = 0.f, l1 = 0.f;
    float ao[16][4];
#pragma unroll
    for (int i = 0; i < 16; ++i)
#pragma unroll
        for (int j = 0; j < 4; ++j) ao[i][j] = 0.f;

    for (int t = 0; t <= qt; ++t) {
        const int k0 = t * 64;

        for (int i = tid; i < 64 * 16; i += 128) {
            const int row = i >> 4;
            const int u = (i & 15) << 4;
            const size_t g = (size_t)(k0 + row) * (NKV_ * HD_ * 2) + u;
            const uint32_t d = row * 272 + u;
            CP_ASYNC16(sQ + OKH2 + d, kh_g + g);
            CP_ASYNC16(sQ + OKL2 + d, kl_g + g);
        }
        for (int i = tid; i < 128 * 8; i += 128) {
            const int row = i >> 3;
            const int u = (i & 7) << 4;
            const size_t g = (size_t)row * (L_ * 2) + (size_t)k0 * 2 + u;
            const uint32_t d = row * 144 + u;
            CP_ASYNC16(sQ + OVH2 + d, vth_g + g);
            CP_ASYNC16(sQ + OVL2 + d, vtl_g + g);
        }
        CP_COMMIT();
        CP_WAIT0();
        __syncthreads();

        float sc[8][4];
#pragma unroll
        for (int ni = 0; ni < 8; ++ni)
#pragma unroll
            for (int j = 0; j < 4; ++j) sc[ni][j] = 0.f;

#pragma unroll
        for (int ks = 0; ks < 8; ++ks) {
            const uint32_t koff = ks * 32;
            uint32_t ah[4], al[4];
            LDSM4(ah, aQh + koff);
            LDSM4(al, aQl + koff);
#pragma unroll
            for (int ni = 0; ni < 8; ++ni) {
                uint32_t bh[2], bl[2];
                LDSM2(bh, bKh + ni * (8 * 272) + koff);
                LDSM2(bl, bKl + ni * (8 * 272) + koff);
                MMA16816(sc[ni], ah, bh);
                MMA16816(sc[ni], ah, bl);
                MMA16816(sc[ni], al, bh);
            }
        }

#pragma unroll
        for (int ni = 0; ni < 8; ++ni)
#pragma unroll
            for (int j = 0; j < 4; ++j) sc[ni][j] *= SCALE_;

        if (t == qt) {
            const int qr0 = q0 + wrow + (lane >> 2);
#pragma unroll
            for (int ni = 0; ni < 8; ++ni) {
                const int kc = k0 + ni * 8 + (lane & 3) * 2;
                if (kc > qr0)         sc[ni][0] = -1e30f;
                if (kc + 1 > qr0)     sc[ni][1] = -1e30f;
                if (kc > qr0 + 8)     sc[ni][2] = -1e30f;
                if (kc + 1 > qr0 + 8) sc[ni][3] = -1e30f;
            }
        }

        float mx0 = -1e30f, mx1 = -1e30f;
#pragma unroll
        for (int ni = 0; ni < 8; ++ni) {
            mx0 = fmaxf(mx0, fmaxf(sc[ni][0], sc[ni][1]));
            mx1 = fmaxf(mx1, fmaxf(sc[ni][2], sc[ni][3]));
        }
        mx0 = fmaxf(mx0, __shfl_xor_sync(0xffffffffu, mx0, 1));
        mx0 = fmaxf(mx0, __shfl_xor_sync(0xffffffffu, mx0, 2));
        mx1 = fmaxf(mx1, __shfl_xor_sync(0xffffffffu, mx1, 1));
        mx1 = fmaxf(mx1, __shfl_xor_sync(0xffffffffu, mx1, 2));

        const float nm0 = fmaxf(m0, mx0), nm1 = fmaxf(m1, mx1);
        const float al0 = __expf(m0 - nm0), al1 = __expf(m1 - nm1);
        float s0 = 0.f, s1 = 0.f;
#pragma unroll
        for (int ni = 0; ni < 8; ++ni) {
            sc[ni][0] = __expf(sc[ni][0] - nm0); s0 += sc[ni][0];
            sc[ni][1] = __expf(sc[ni][1] - nm0); s0 += sc[ni][1];
            sc[ni][2] = __expf(sc[ni][2] - nm1); s1 += sc[ni][2];
            sc[ni][3] = __expf(sc[ni][3] - nm1); s1 += sc[ni][3];
        }
        s0 += __shfl_xor_sync(0xffffffffu, s0, 1);
        s0 += __shfl_xor_sync(0xffffffffu, s0, 2);
        s1 += __shfl_xor_sync(0xffffffffu, s1, 1);
        s1 += __shfl_xor_sync(0xffffffffu, s1, 2);
        l0 = l0 * al0 + s0; l1 = l1 * al1 + s1;
        m0 = nm0; m1 = nm1;

#pragma unroll
        for (int i = 0; i < 16; ++i) {
            ao[i][0] *= al0; ao[i][1] *= al0;
            ao[i][2] *= al1; ao[i][3] *= al1;
        }

#pragma unroll
        for (int ks = 0; ks < 4; ++ks) {
            const float p0 = sc[2 * ks][0], p1 = sc[2 * ks][1];
            const float p2 = sc[2 * ks][2], p3 = sc[2 * ks][3];
            const float p4 = sc[2 * ks + 1][0], p5 = sc[2 * ks + 1][1];
            const float p6 = sc[2 * ks + 1][2], p7 = sc[2 * ks + 1][3];
            const __nv_bfloat16 q0b = __float2bfloat16_rn(p0), q1b = __float2bfloat16_rn(p1);
            const __nv_bfloat16 q2b = __float2bfloat16_rn(p2), q3b = __float2bfloat16_rn(p3);
            const __nv_bfloat16 q4b = __float2bfloat16_rn(p4), q5b = __float2bfloat16_rn(p5);
            const __nv_bfloat16 q6b = __float2bfloat16_rn(p6), q7b = __float2bfloat16_rn(p7);
            uint32_t pah[4], pal[4];
            pah[0] = packbf2(q0b, q1b);
            pah[1] = packbf2(q2b, q3b);
            pah[2] = packbf2(q4b, q5b);
            pah[3] = packbf2(q6b, q7b);
            pal[0] = packbf2(__float2bfloat16_rn(p0 - __bfloat162float(q0b)),
                             __float2bfloat16_rn(p1 - __bfloat162float(q1b)));
            pal[1] = packbf2(__float2bfloat16_rn(p2 - __bfloat162float(q2b)),
                             __float2bfloat16_rn(p3 - __bfloat162float(q3b)));
            pal[2] = packbf2(__float2bfloat16_rn(p4 - __bfloat162float(q4b)),
                             __float2bfloat16_rn(p5 - __bfloat162float(q5b)));
            pal[3] = packbf2(__float2bfloat16_rn(p6 - __bfloat162float(q6b)),
                             __float2bfloat16_rn(p7 - __bfloat162float(q7b)));

            const uint32_t koff = ks * 32;
#pragma unroll
            for (int ni = 0; ni < 16; ++ni) {
                uint32_t bh[2], bl[2];
                LDSM2(bh, bVh + ni * (8 * 144) + koff);
                LDSM2(bl, bVl + ni * (8 * 144) + koff);
                MMA16816(ao[ni], pah, bh);
                MMA16816(ao[ni], pal, bh);
                MMA16816(ao[ni], pah, bl);
            }
        }
        __syncthreads();
    }

    const float inv0 = 1.0f / l0, inv1 = 1.0f / l1;
    const int r0 = q0 + wrow + (lane >> 2);
    const int ecol = (lane & 3) * 2;
    float* Ob0 = O + ((size_t)(b * L_ + r0) * NH_ + h) * HD_ + ecol;
    float* Ob1 = O + ((size_t)(b * L_ + r0 + 8) * NH_ + h) * HD_ + ecol;
#pragma unroll
    for (int ni = 0; ni < 16; ++ni) {
        *(float2*)(Ob0 + ni * 8) = make_float2(ao[ni][0] * inv0, ao[ni][1] * inv0);
        *(float2*)(Ob1 + ni * 8) = make_float2(ao[ni][2] * inv1, ao[ni][3] * inv1);
    }
}

// ---------------------------------------------------------------------------
extern "C" void kernel_launch(void* const* d_in, const int* in_sizes, int n_in,
                              void* d_out, int out_size) {
    const float* x  = (const float*)d_in[0];
    const float* Wq = (const float*)d_in[1];
    const float* Wk = (const float*)d_in[2];
    const float* Wv = (const float*)d_in[3];
    const float* Wo = (const float*)d_in[4];
    float* out = (float*)d_out;

    float *q, *k, *v, *o;
    cudaGetSymbolAddress((void**)&q, g_q);
    cudaGetSymbolAddress((void**)&k, g_k);
    cudaGetSymbolAddress((void**)&v, g_v);
    cudaGetSymbolAddress((void**)&o, g_o);
    __nv_bfloat16 *xh, *xl, *wqh, *wql, *wkh, *wkl, *wvh, *wvl, *woh, *wol, *oh, *ol;
    __nv_bfloat16 *qh, *ql, *kh, *kl, *vth, *vtl;
    cudaGetSymbolAddress((void**)&xh, g_xh);   cudaGetSymbolAddress((void**)&xl, g_xl);
    cudaGetSymbolAddress((void**)&wqh, g_wqh); cudaGetSymbolAddress((void**)&wql, g_wql);
    cudaGetSymbolAddress((void**)&wkh, g_wkh); cudaGetSymbolAddress((void**)&wkl, g_wkl);
    cudaGetSymbolAddress((void**)&wvh, g_wvh); cudaGetSymbolAddress((void**)&wvl, g_wvl);
    cudaGetSymbolAddress((void**)&woh, g_woh); cudaGetSymbolAddress((void**)&wol, g_wol);
    cudaGetSymbolAddress((void**)&oh, g_oh);   cudaGetSymbolAddress((void**)&ol, g_ol);
    cudaGetSymbolAddress((void**)&qh, g_qh);   cudaGetSymbolAddress((void**)&ql, g_ql);
    cudaGetSymbolAddress((void**)&kh, g_kh);   cudaGetSymbolAddress((void**)&kl, g_kl);
    cudaGetSymbolAddress((void**)&vth, g_vth); cudaGetSymbolAddress((void**)&vtl, g_vtl);

    const int M = B_ * L_;       // 4096
    const int NKVD = NKV_ * HD_; // 1024

    cudaFuncSetAttribute(gemm_mma, cudaFuncAttributeMaxDynamicSharedMemorySize, GT_SMEM);
    cudaFuncSetAttribute(flash_mma, cudaFuncAttributeMaxDynamicSharedMemorySize, FM_SMEM);

    prep_split<<<PREP_BLOCKS, 256>>>(x, Wq, Wk, Wv, Wo);

    gemm_mma<<<dim3(D_ / 128, M / 128), 256, GT_SMEM>>>(xh, xl, wqh, wql, q, D_, D_);
    gemm_mma<<<dim3(NKVD / 128, M / 128), 256, GT_SMEM>>>(xh, xl, wkh, wkl, k, NKVD, D_);
    gemm_mma<<<dim3(NKVD / 128, M / 128), 256, GT_SMEM>>>(xh, xl, wvh, wvl, v, NKVD, D_);

    rope_vt<<<RVT_BLOCKS, 256>>>(q, k, v);

    flash_mma<<<dim3(L_ / 64, NH_, B_), 128, FM_SMEM>>>(qh, ql, kh, kl, vth, vtl, o);

    split_bf16<<<(M * D_ / 4 + 255) / 256, 256>>>(o, oh, ol, M * D_ / 4);
    gemm_mma<<<dim3(D_ / 128, M / 128), 256, GT_SMEM>>>(oh, ol, woh, wol, out, D_, D_);
}

// round 13
// speedup vs baseline: 1.3064x; 1.1488x over previous
#include <cuda_runtime.h>
#include <cuda_bf16.h>
#include <math.h>
#include <stdint.h>

#define B_  2
#define L_  2048
#define D_  2048
#define NH_ 16
#define NKV_ 8
#define HD_ 128
#define GQ_ 2
#define SCALE_ 0.08838834764831845f  // 128^-0.5

// ---------------- scratch (static device globals) ----------------
__device__ float g_q[(size_t)B_ * L_ * NH_ * HD_];
__device__ float g_k[(size_t)B_ * L_ * NKV_ * HD_];
__device__ float g_v[(size_t)B_ * L_ * NKV_ * HD_];
__device__ float g_o[(size_t)B_ * L_ * NH_ * HD_];
__device__ float g_cos[(size_t)L_ * 64];
__device__ float g_sin[(size_t)L_ * 64];

__device__ __nv_bfloat16 g_xh[(size_t)B_ * L_ * D_];
__device__ __nv_bfloat16 g_xl[(size_t)B_ * L_ * D_];
__device__ __nv_bfloat16 g_wqh[(size_t)D_ * D_];
__device__ __nv_bfloat16 g_wql[(size_t)D_ * D_];
__device__ __nv_bfloat16 g_wkh[(size_t)NKV_ * HD_ * D_];
__device__ __nv_bfloat16 g_wkl[(size_t)NKV_ * HD_ * D_];
__device__ __nv_bfloat16 g_wvh[(size_t)NKV_ * HD_ * D_];
__device__ __nv_bfloat16 g_wvl[(size_t)NKV_ * HD_ * D_];
__device__ __nv_bfloat16 g_woh[(size_t)D_ * D_];
__device__ __nv_bfloat16 g_wol[(size_t)D_ * D_];
__device__ __nv_bfloat16 g_oh[(size_t)B_ * L_ * D_];
__device__ __nv_bfloat16 g_ol[(size_t)B_ * L_ * D_];

// pre-split (and RoPE'd / transposed) attention operands
__device__ __nv_bfloat16 g_qh[(size_t)B_ * L_ * NH_ * HD_];
__device__ __nv_bfloat16 g_ql[(size_t)B_ * L_ * NH_ * HD_];
__device__ __nv_bfloat16 g_kh[(size_t)B_ * L_ * NKV_ * HD_];
__device__ __nv_bfloat16 g_kl[(size_t)B_ * L_ * NKV_ * HD_];
__device__ __nv_bfloat16 g_vth[(size_t)B_ * NKV_ * HD_ * L_];
__device__ __nv_bfloat16 g_vtl[(size_t)B_ * NKV_ * HD_ * L_];

// ---------------- helpers ----------------
__device__ __forceinline__ uint32_t smem_u32(const void* p) {
    uint32_t a;
    asm("{ .reg .u64 t; cvta.to.shared.u64 t, %1; cvt.u32.u64 %0, t; }"
        : "=r"(a) : "l"(p));
    return a;
}
#define LDSM4(r, a) \
    asm volatile("ldmatrix.sync.aligned.m8n8.x4.shared.b16 {%0,%1,%2,%3}, [%4];" \
                 : "=r"((r)[0]), "=r"((r)[1]), "=r"((r)[2]), "=r"((r)[3]) : "r"(a))
#define LDSM2(r, a) \
    asm volatile("ldmatrix.sync.aligned.m8n8.x2.shared.b16 {%0,%1}, [%2];" \
                 : "=r"((r)[0]), "=r"((r)[1]) : "r"(a))
#define MMA16816(d, a, b) \
    asm volatile("mma.sync.aligned.m16n8k16.row.col.f32.bf16.bf16.f32 " \
                 "{%0,%1,%2,%3}, {%4,%5,%6,%7}, {%8,%9}, {%0,%1,%2,%3};" \
                 : "+f"((d)[0]), "+f"((d)[1]), "+f"((d)[2]), "+f"((d)[3]) \
                 : "r"((a)[0]), "r"((a)[1]), "r"((a)[2]), "r"((a)[3]), \
                   "r"((b)[0]), "r"((b)[1]))
#define CP_ASYNC16(s, g) \
    asm volatile("cp.async.cg.shared.global [%0], [%1], 16;" :: "r"(s), "l"(g))
#define CP_COMMIT() asm volatile("cp.async.commit_group;" ::: "memory")
#define CP_WAIT1()  asm volatile("cp.async.wait_group 1;" ::: "memory")
#define CP_WAIT0()  asm volatile("cp.async.wait_group 0;" ::: "memory")

__device__ __forceinline__ uint32_t packbf2(__nv_bfloat16 lo, __nv_bfloat16 hi) {
    __nv_bfloat162 t = __halves2bfloat162(lo, hi);
    return *(uint32_t*)&t;
}

__device__ __forceinline__ void split4(const float4 v, __nv_bfloat16* h,
                                       __nv_bfloat16* l, int i4) {
    __nv_bfloat16 h0 = __float2bfloat16_rn(v.x);
    __nv_bfloat16 h1 = __float2bfloat16_rn(v.y);
    __nv_bfloat16 h2 = __float2bfloat16_rn(v.z);
    __nv_bfloat16 h3 = __float2bfloat16_rn(v.w);
    h[i4 * 4 + 0] = h0; h[i4 * 4 + 1] = h1; h[i4 * 4 + 2] = h2; h[i4 * 4 + 3] = h3;
    l[i4 * 4 + 0] = __float2bfloat16_rn(v.x - __bfloat162float(h0));
    l[i4 * 4 + 1] = __float2bfloat16_rn(v.y - __bfloat162float(h1));
    l[i4 * 4 + 2] = __float2bfloat16_rn(v.z - __bfloat162float(h2));
    l[i4 * 4 + 3] = __float2bfloat16_rn(v.w - __bfloat162float(h3));
}

// ---------------------------------------------------------------------------
__global__ void split_bf16(const float* __restrict__ s,
                           __nv_bfloat16* __restrict__ h,
                           __nv_bfloat16* __restrict__ l, int n4) {
    const int i = blockIdx.x * blockDim.x + threadIdx.x;
    if (i >= n4) return;
    split4(((const float4*)s)[i], h, l, i);
}

// ---------------------------------------------------------------------------
// prep_split: rope table + all input/weight hi/lo splits in ONE launch.
// ---------------------------------------------------------------------------
#define PREP_BLOCKS 20992
__global__ void __launch_bounds__(256) prep_split(const float* __restrict__ x,
                                                  const float* __restrict__ Wq,
                                                  const float* __restrict__ Wk,
                                                  const float* __restrict__ Wv,
                                                  const float* __restrict__ Wo) {
    int bid = blockIdx.x;
    const int tid = threadIdx.x;
    if (bid < 512) {
        const int idx = bid * 256 + tid;
        const int i = idx & 63;
        const int pos = idx >> 6;
        const double inv = exp(-(double)i / 64.0 * log(10000.0));
        double sd, cd;
        sincos((double)pos * inv, &sd, &cd);
        g_cos[idx] = (float)cd;
        g_sin[idx] = (float)sd;
        return;
    }
    bid -= 512;
    const float* src;
    __nv_bfloat16 *h, *l;
    int base;
    if (bid < 8192)       { src = x;  h = g_xh;  l = g_xl;  base = bid; }
    else if (bid < 12288) { src = Wq; h = g_wqh; l = g_wql; base = bid - 8192; }
    else if (bid < 14336) { src = Wk; h = g_wkh; l = g_wkl; base = bid - 12288; }
    else if (bid < 16384) { src = Wv; h = g_wvh; l = g_wvl; base = bid - 14336; }
    else                  { src = Wo; h = g_woh; l = g_wol; base = bid - 16384; }
    const int i = base * 256 + tid;
    split4(((const float4*)src)[i], h, l, i);
}

// ---------------------------------------------------------------------------
// mma.sync bf16x3 GEMM, K-chunk 32, cp.async double-buffered, 2 CTAs/SM.
// Stage layout per buffer: Ah 0, Al 10240, Bh 20480, Bl 30720 (pitch 80B).
// ---------------------------------------------------------------------------
#define GSTG 40960
#define GT_SMEM (2 * GSTG)

__global__ void __launch_bounds__(256, 2) gemm_mma(const __nv_bfloat16* __restrict__ Ah,
                                                   const __nv_bfloat16* __restrict__ Al,
                                                   const __nv_bfloat16* __restrict__ Bh,
                                                   const __nv_bfloat16* __restrict__ Bl,
                                                   float* __restrict__ C,
                                                   int N, int K) {
    extern __shared__ __nv_bfloat16 sb[];
    const uint32_t sbase = smem_u32(sb);

    const int tid = threadIdx.x;
    const int lane = tid & 31;
    const int wid = tid >> 5;
    const int wm = (wid >> 2) * 64;
    const int wn = (wid & 3) * 32;
    const int m0 = blockIdx.y * 128;
    const int n0 = blockIdx.x * 128;

    const int srow = tid >> 1;            // 0..127
    const int sub  = (tid & 1) * 2;       // unit base (unit = 16B), row = 4 units

    const char* gAh = (const char*)(Ah + (size_t)(m0 + srow) * K);
    const char* gAl = (const char*)(Al + (size_t)(m0 + srow) * K);
    const char* gBh = (const char*)(Bh + (size_t)(n0 + srow) * K);
    const char* gBl = (const char*)(Bl + (size_t)(n0 + srow) * K);
    const uint32_t srow80 = srow * 80;

    auto stage = [&](int kc, uint32_t sbuf) {
#pragma unroll
        for (int u = 0; u < 2; ++u) {
            const int off = (sub + u) * 16;
            const uint32_t d = sbuf + srow80 + off;
            const int gofs = kc * 2 + off;
            CP_ASYNC16(d,         gAh + gofs);
            CP_ASYNC16(d + 10240, gAl + gofs);
            CP_ASYNC16(d + 20480, gBh + gofs);
            CP_ASYNC16(d + 30720, gBl + gofs);
        }
    };

    float acc[4][4][4];
#pragma unroll
    for (int i = 0; i < 4; ++i)
#pragma unroll
        for (int j = 0; j < 4; ++j)
#pragma unroll
            for (int q = 0; q < 4; ++q) acc[i][j][q] = 0.f;

    const int arow = lane & 15, acol = (lane >> 4) << 3;
    const int brow = lane & 7,  bcol = ((lane >> 3) & 1) << 3;
    const uint32_t a_h0 = sbase + (wm + arow) * 80 + acol * 2;
    const uint32_t b_h0 = sbase + 20480 + (wn + brow) * 80 + bcol * 2;

    stage(0, sbase);
    CP_COMMIT();

    const int nchunk = K >> 5;
    for (int c = 0; c < nchunk; ++c) {
        if (c + 1 < nchunk) {
            stage((c + 1) << 5, sbase + (uint32_t)((c + 1) & 1) * GSTG);
            CP_COMMIT();
            CP_WAIT1();
        } else {
            CP_WAIT0();
        }
        __syncthreads();

        const uint32_t boff = (uint32_t)(c & 1) * GSTG;
        const uint32_t a_h = a_h0 + boff;
        const uint32_t a_l = a_h + 10240;
        const uint32_t b_h = b_h0 + boff;
        const uint32_t b_l = b_h + 10240;

#pragma unroll
        for (int ks = 0; ks < 2; ++ks) {
            const uint32_t koff = ks * 32;
            uint32_t ah[4][4], al[4][4], bh[4][2], bl[4][2];
#pragma unroll
            for (int mi = 0; mi < 4; ++mi) {
                LDSM4(ah[mi], a_h + mi * (16 * 80) + koff);
                LDSM4(al[mi], a_l + mi * (16 * 80) + koff);
            }
#pragma unroll
            for (int ni = 0; ni < 4; ++ni) {
                LDSM2(bh[ni], b_h + ni * (8 * 80) + koff);
                LDSM2(bl[ni], b_l + ni * (8 * 80) + koff);
            }
#pragma unroll
            for (int mi = 0; mi < 4; ++mi)
#pragma unroll
                for (int ni = 0; ni < 4; ++ni) {
                    MMA16816(acc[mi][ni], ah[mi], bh[ni]);
                    MMA16816(acc[mi][ni], ah[mi], bl[ni]);
                    MMA16816(acc[mi][ni], al[mi], bh[ni]);
                }
        }
        __syncthreads();
    }

    const int erow = lane >> 2;
    const int ecol = (lane & 3) * 2;
#pragma unroll
    for (int mi = 0; mi < 4; ++mi)
#pragma unroll
        for (int ni = 0; ni < 4; ++ni) {
            float* cp = C + (size_t)(m0 + wm + mi * 16 + erow) * N + n0 + wn + ni * 8 + ecol;
            *(float2*)cp = make_float2(acc[mi][ni][0], acc[mi][ni][1]);
            *(float2*)(cp + 8 * (size_t)N) = make_float2(acc[mi][ni][2], acc[mi][ni][3]);
        }
}

// ---------------------------------------------------------------------------
// rope_vt: fused RoPE+split (Q,K) and V split+transpose in ONE launch.
// ---------------------------------------------------------------------------
#define RVT_BLOCKS 28672
__global__ void __launch_bounds__(256) rope_vt(const float* __restrict__ q,
                                               const float* __restrict__ k,
                                               const float* __restrict__ v) {
    const int bid = blockIdx.x;
    const int tid = threadIdx.x;
    if (bid < 24576) {
        const long long idx = (long long)bid * 256 + tid;
        const int i  = (int)(idx & 63);
        long long r  = idx >> 6;
        const int hh = (int)(r % (NH_ + NKV_));
        r /= (NH_ + NKV_);
        const int bl  = (int)r;
        const int pos = bl & (L_ - 1);

        const float* src;
        __nv_bfloat16 *dh, *dl;
        size_t off;
        if (hh < NH_) {
            off = ((size_t)bl * NH_ + hh) * HD_;
            src = q + off; dh = g_qh + off; dl = g_ql + off;
        } else {
            off = ((size_t)bl * NKV_ + (hh - NH_)) * HD_;
            src = k + off; dh = g_kh + off; dl = g_kl + off;
        }

        const float c = g_cos[pos * 64 + i];
        const float s = g_sin[pos * 64 + i];
        const float a = src[i];
        const float b = src[i + 64];
        const float r0 = a * c - b * s;
        const float r1 = b * c + a * s;

        const __nv_bfloat16 h0 = __float2bfloat16_rn(r0);
        const __nv_bfloat16 h1 = __float2bfloat16_rn(r1);
        dh[i]      = h0;
        dh[i + 64] = h1;
        dl[i]      = __float2bfloat16_rn(r0 - __bfloat162float(h0));
        dl[i + 64] = __float2bfloat16_rn(r1 - __bfloat162float(h1));
    } else {
        __shared__ float s[32][33];
        const int lb = bid - 24576;
        const int l0 = (lb & 63) * 32;
        const int d0 = ((lb >> 6) & 3) * 32;
        const int bk = lb >> 8;
        const int b = bk >> 3, kvh = bk & 7;
        const int tx = tid & 31, ty = tid >> 5;

        const float* vb = v + ((size_t)b * L_ * NKV_ + kvh) * HD_;
#pragma unroll
        for (int rr = 0; rr < 4; ++rr) {
            const int lr = ty * 4 + rr;
            s[lr][tx] = vb[(size_t)(l0 + lr) * (NKV_ * HD_) + d0 + tx];
        }
        __syncthreads();

        __nv_bfloat16* oh = g_vth + (size_t)bk * HD_ * L_;
        __nv_bfloat16* ol = g_vtl + (size_t)bk * HD_ * L_;
#pragma unroll
        for (int rr = 0; rr < 4; ++rr) {
            const int dr = ty * 4 + rr;
            const float val = s[tx][dr];
            const __nv_bfloat16 hv = __float2bfloat16_rn(val);
            oh[(size_t)(d0 + dr) * L_ + l0 + tx] = hv;
            ol[(size_t)(d0 + dr) * L_ + l0 + tx] =
                __float2bfloat16_rn(val - __bfloat162float(hv));
        }
    }
}

// ---------------------------------------------------------------------------
// Flash attention (measured best): 64 q-rows / 128 threads, k-tile 64,
// single K/V buffer, 104KB smem -> 2 CTAs/SM, full 3-product split math.
// ---------------------------------------------------------------------------
#define OQH 0
#define OQL 17408
#define OKH2 34816
#define OKL2 52224
#define OVH2 69632
#define OVL2 88064
#define FM_SMEM 106496

__global__ void __launch_bounds__(128) flash_mma(const __nv_bfloat16* __restrict__ Qhg,
                                                 const __nv_bfloat16* __restrict__ Qlg,
                                                 const __nv_bfloat16* __restrict__ Khg,
                                                 const __nv_bfloat16* __restrict__ Klg,
                                                 const __nv_bfloat16* __restrict__ Vthg,
                                                 const __nv_bfloat16* __restrict__ Vtlg,
                                                 float* __restrict__ O) {
    extern __shared__ char smem[];
    const uint32_t sQ = smem_u32(smem);

    const int tid = threadIdx.x;
    const int lane = tid & 31, wid = tid >> 5;
    const int b = blockIdx.z, h = blockIdx.y;
    const int kvh = h >> 1;
    const int qt = (gridDim.x - 1) - blockIdx.x;
    const int q0 = qt * 64;
    const int wrow = wid * 16;

    const char* qh_g = (const char*)(Qhg + ((size_t)(b * L_ + q0) * NH_ + h) * HD_);
    const char* ql_g = (const char*)(Qlg + ((size_t)(b * L_ + q0) * NH_ + h) * HD_);
    const char* kh_g = (const char*)(Khg + ((size_t)b * L_ * NKV_ + kvh) * HD_);
    const char* kl_g = (const char*)(Klg + ((size_t)b * L_ * NKV_ + kvh) * HD_);
    const char* vth_g = (const char*)(Vthg + (size_t)(b * NKV_ + kvh) * HD_ * L_);
    const char* vtl_g = (const char*)(Vtlg + (size_t)(b * NKV_ + kvh) * HD_ * L_);

    for (int i = tid; i < 64 * 16; i += 128) {
        const int row = i >> 4;
        const int u = (i & 15) << 4;
        const size_t g = (size_t)row * (NH_ * HD_ * 2) + u;
        const uint32_t d = row * 272 + u;
        CP_ASYNC16(sQ + OQH + d, qh_g + g);
        CP_ASYNC16(sQ + OQL + d, ql_g + g);
    }

    const uint32_t aQh = sQ + OQH + (wrow + (lane & 15)) * 272 + ((lane >> 4) << 4);
    const uint32_t aQl = aQh + (OQL - OQH);
    const uint32_t bKh = sQ + OKH2 + (lane & 7) * 272 + (((lane >> 3) & 1) << 4);
    const uint32_t bKl = bKh + (OKL2 - OKH2);
    const uint32_t bVh = sQ + OVH2 + (lane & 7) * 144 + (((lane >> 3) & 1) << 4);
    const uint32_t bVl = bVh + (OVL2 - OVH2);

    float m0 = -1e30f, m1 = -1e30f, l0 = 0.f, l1 = 0.f;
    float ao[16][4];
#pragma unroll
    for (int i = 0; i < 16; ++i)
#pragma unroll
        for (int j = 0; j < 4; ++j) ao[i][j] = 0.f;

    for (int t = 0; t <= qt; ++t) {
        const int k0 = t * 64;

        for (int i = tid; i < 64 * 16; i += 128) {
            const int row = i >> 4;
            const int u = (i & 15) << 4;
            const size_t g = (size_t)(k0 + row) * (NKV_ * HD_ * 2) + u;
            const uint32_t d = row * 272 + u;
            CP_ASYNC16(sQ + OKH2 + d, kh_g + g);
            CP_ASYNC16(sQ + OKL2 + d, kl_g + g);
        }
        for (int i = tid; i < 128 * 8; i += 128) {
            const int row = i >> 3;
            const int u = (i & 7) << 4;
            const size_t g = (size_t)row * (L_ * 2) + (size_t)k0 * 2 + u;
            const uint32_t d = row * 144 + u;
            CP_ASYNC16(sQ + OVH2 + d, vth_g + g);
            CP_ASYNC16(sQ + OVL2 + d, vtl_g + g);
        }
        CP_COMMIT();
        CP_WAIT0();
        __syncthreads();

        float sc[8][4];
#pragma unroll
        for (int ni = 0; ni < 8; ++ni)
#pragma unroll
            for (int j = 0; j < 4; ++j) sc[ni][j] = 0.f;

#pragma unroll
        for (int ks = 0; ks < 8; ++ks) {
            const uint32_t koff = ks * 32;
            uint32_t ah[4], al[4];
            LDSM4(ah, aQh + koff);
            LDSM4(al, aQl + koff);
#pragma unroll
            for (int ni = 0; ni < 8; ++ni) {
                uint32_t bh[2], bl[2];
                LDSM2(bh, bKh + ni * (8 * 272) + koff);
                LDSM2(bl, bKl + ni * (8 * 272) + koff);
                MMA16816(sc[ni], ah, bh);
                MMA16816(sc[ni], ah, bl);
                MMA16816(sc[ni], al, bh);
            }
        }

#pragma unroll
        for (int ni = 0; ni < 8; ++ni)
#pragma unroll
            for (int j = 0; j < 4; ++j) sc[ni][j] *= SCALE_;

        if (t == qt) {
            const int qr0 = q0 + wrow + (lane >> 2);
#pragma unroll
            for (int ni = 0; ni < 8; ++ni) {
                const int kc = k0 + ni * 8 + (lane & 3) * 2;
                if (kc > qr0)         sc[ni][0] = -1e30f;
                if (kc + 1 > qr0)     sc[ni][1] = -1e30f;
                if (kc > qr0 + 8)     sc[ni][2] = -1e30f;
                if (kc + 1 > qr0 + 8) sc[ni][3] = -1e30f;
            }
        }

        float mx0 = -1e30f, mx1 = -1e30f;
#pragma unroll
        for (int ni = 0; ni < 8; ++ni) {
            mx0 = fmaxf(mx0, fmaxf(sc[ni][0], sc[ni][1]));
            mx1 = fmaxf(mx1, fmaxf(sc[ni][2], sc[ni][3]));
        }
        mx0 = fmaxf(mx0, __shfl_xor_sync(0xffffffffu, mx0, 1));
        mx0 = fmaxf(mx0, __shfl_xor_sync(0xffffffffu, mx0, 2));
        mx1 = fmaxf(mx1, __shfl_xor_sync(0xffffffffu, mx1, 1));
        mx1 = fmaxf(mx1, __shfl_xor_sync(0xffffffffu, mx1, 2));

        const float nm0 = fmaxf(m0, mx0), nm1 = fmaxf(m1, mx1);
        const float al0 = __expf(m0 - nm0), al1 = __expf(m1 - nm1);
        float s0 = 0.f, s1 = 0.f;
#pragma unroll
        for (int ni = 0; ni < 8; ++ni) {
            sc[ni][0] = __expf(sc[ni][0] - nm0); s0 += sc[ni][0];
            sc[ni][1] = __expf(sc[ni][1] - nm0); s0 += sc[ni][1];
            sc[ni][2] = __expf(sc[ni][2] - nm1); s1 += sc[ni][2];
            sc[ni][3] = __expf(sc[ni][3] - nm1); s1 += sc[ni][3];
        }
        s0 += __shfl_xor_sync(0xffffffffu, s0, 1);
        s0 += __shfl_xor_sync(0xffffffffu, s0, 2);
        s1 += __shfl_xor_sync(0xffffffffu, s1, 1);
        s1 += __shfl_xor_sync(0xffffffffu, s1, 2);
        l0 = l0 * al0 + s0; l1 = l1 * al1 + s1;
        m0 = nm0; m1 = nm1;

#pragma unroll
        for (int i = 0; i < 16; ++i) {
            ao[i][0] *= al0; ao[i][1] *= al0;
            ao[i][2] *= al1; ao[i][3] *= al1;
        }

#pragma unroll
        for (int ks = 0; ks < 4; ++ks) {
            const float p0 = sc[2 * ks][0], p1 = sc[2 * ks][1];
            const float p2 = sc[2 * ks][2], p3 = sc[2 * ks][3];
            const float p4 = sc[2 * ks + 1][0], p5 = sc[2 * ks + 1][1];
            const float p6 = sc[2 * ks + 1][2], p7 = sc[2 * ks + 1][3];
            const __nv_bfloat16 q0b = __float2bfloat16_rn(p0), q1b = __float2bfloat16_rn(p1);
            const __nv_bfloat16 q2b = __float2bfloat16_rn(p2), q3b = __float2bfloat16_rn(p3);
            const __nv_bfloat16 q4b = __float2bfloat16_rn(p4), q5b = __float2bfloat16_rn(p5);
            const __nv_bfloat16 q6b = __float2bfloat16_rn(p6), q7b = __float2bfloat16_rn(p7);
            uint32_t pah[4], pal[4];
            pah[0] = packbf2(q0b, q1b);
            pah[1] = packbf2(q2b, q3b);
            pah[2] = packbf2(q4b, q5b);
            pah[3] = packbf2(q6b, q7b);
            pal[0] = packbf2(__float2bfloat16_rn(p0 - __bfloat162float(q0b)),
                             __float2bfloat16_rn(p1 - __bfloat162float(q1b)));
            pal[1] = packbf2(__float2bfloat16_rn(p2 - __bfloat162float(q2b)),
                             __float2bfloat16_rn(p3 - __bfloat162float(q3b)));
            pal[2] = packbf2(__float2bfloat16_rn(p4 - __bfloat162float(q4b)),
                             __float2bfloat16_rn(p5 - __bfloat162float(q5b)));
            pal[3] = packbf2(__float2bfloat16_rn(p6 - __bfloat162float(q6b)),
                             __float2bfloat16_rn(p7 - __bfloat162float(q7b)));

            const uint32_t koff = ks * 32;
#pragma unroll
            for (int ni = 0; ni < 16; ++ni) {
                uint32_t bh[2], bl[2];
                LDSM2(bh, bVh + ni * (8 * 144) + koff);
                LDSM2(bl, bVl + ni * (8 * 144) + koff);
                MMA16816(ao[ni], pah, bh);
                MMA16816(ao[ni], pal, bh);
                MMA16816(ao[ni], pah, bl);
            }
        }
        __syncthreads();
    }

    const float inv0 = 1.0f / l0, inv1 = 1.0f / l1;
    const int r0 = q0 + wrow + (lane >> 2);
    const int ecol = (lane & 3) * 2;
    float* Ob0 = O + ((size_t)(b * L_ + r0) * NH_ + h) * HD_ + ecol;
    float* Ob1 = O + ((size_t)(b * L_ + r0 + 8) * NH_ + h) * HD_ + ecol;
#pragma unroll
    for (int ni = 0; ni < 16; ++ni) {
        *(float2*)(Ob0 + ni * 8) = make_float2(ao[ni][0] * inv0, ao[ni][1] * inv0);
        *(float2*)(Ob1 + ni * 8) = make_float2(ao[ni][2] * inv1, ao[ni][3] * inv1);
    }
}

// ---------------------------------------------------------------------------
extern "C" void kernel_launch(void* const* d_in, const int* in_sizes, int n_in,
                              void* d_out, int out_size) {
    const float* x  = (const float*)d_in[0];
    const float* Wq = (const float*)d_in[1];
    const float* Wk = (const float*)d_in[2];
    const float* Wv = (const float*)d_in[3];
    const float* Wo = (const float*)d_in[4];
    float* out = (float*)d_out;

    float *q, *k, *v, *o;
    cudaGetSymbolAddress((void**)&q, g_q);
    cudaGetSymbolAddress((void**)&k, g_k);
    cudaGetSymbolAddress((void**)&v, g_v);
    cudaGetSymbolAddress((void**)&o, g_o);
    __nv_bfloat16 *xh, *xl, *wqh, *wql, *wkh, *wkl, *wvh, *wvl, *woh, *wol, *oh, *ol;
    __nv_bfloat16 *qh, *ql, *kh, *kl, *vth, *vtl;
    cudaGetSymbolAddress((void**)&xh, g_xh);   cudaGetSymbolAddress((void**)&xl, g_xl);
    cudaGetSymbolAddress((void**)&wqh, g_wqh); cudaGetSymbolAddress((void**)&wql, g_wql);
    cudaGetSymbolAddress((void**)&wkh, g_wkh); cudaGetSymbolAddress((void**)&wkl, g_wkl);
    cudaGetSymbolAddress((void**)&wvh, g_wvh); cudaGetSymbolAddress((void**)&wvl, g_wvl);
    cudaGetSymbolAddress((void**)&woh, g_woh); cudaGetSymbolAddress((void**)&wol, g_wol);
    cudaGetSymbolAddress((void**)&oh, g_oh);   cudaGetSymbolAddress((void**)&ol, g_ol);
    cudaGetSymbolAddress((void**)&qh, g_qh);   cudaGetSymbolAddress((void**)&ql, g_ql);
    cudaGetSymbolAddress((void**)&kh, g_kh);   cudaGetSymbolAddress((void**)&kl, g_kl);
    cudaGetSymbolAddress((void**)&vth, g_vth); cudaGetSymbolAddress((void**)&vtl, g_vtl);

    const int M = B_ * L_;       // 4096
    const int NKVD = NKV_ * HD_; // 1024

    cudaFuncSetAttribute(gemm_mma, cudaFuncAttributeMaxDynamicSharedMemorySize, GT_SMEM);
    cudaFuncSetAttribute(flash_mma, cudaFuncAttributeMaxDynamicSharedMemorySize, FM_SMEM);

    prep_split<<<PREP_BLOCKS, 256>>>(x, Wq, Wk, Wv, Wo);

    gemm_mma<<<dim3(D_ / 128, M / 128), 256, GT_SMEM>>>(xh, xl, wqh, wql, q, D_, D_);
    gemm_mma<<<dim3(NKVD / 128, M / 128), 256, GT_SMEM>>>(xh, xl, wkh, wkl, k, NKVD, D_);
    gemm_mma<<<dim3(NKVD / 128, M / 128), 256, GT_SMEM>>>(xh, xl, wvh, wvl, v, NKVD, D_);

    rope_vt<<<RVT_BLOCKS, 256>>>(q, k, v);

    flash_mma<<<dim3(L_ / 64, NH_, B_), 128, FM_SMEM>>>(qh, ql, kh, kl, vth, vtl, o);

    split_bf16<<<(M * D_ / 4 + 255) / 256, 256>>>(o, oh, ol, M * D_ / 4);
    gemm_mma<<<dim3(D_ / 128, M / 128), 256, GT_SMEM>>>(oh, ol, woh, wol, out, D_, D_);
}

// round 14
// speedup vs baseline: 1.3764x; 1.0535x over previous
#include <cuda_runtime.h>
#include <cuda_bf16.h>
#include <math.h>
#include <stdint.h>

#define B_  2
#define L_  2048
#define D_  2048
#define NH_ 16
#define NKV_ 8
#define HD_ 128
#define GQ_ 2
#define SCALE_ 0.08838834764831845f  // 128^-0.5

// ---------------- scratch (static device globals) ----------------
__device__ float g_q[(size_t)B_ * L_ * NH_ * HD_];
__device__ float g_k[(size_t)B_ * L_ * NKV_ * HD_];
__device__ float g_v[(size_t)B_ * L_ * NKV_ * HD_];
__device__ float g_o[(size_t)B_ * L_ * NH_ * HD_];
__device__ float g_cos[(size_t)L_ * 64];
__device__ float g_sin[(size_t)L_ * 64];

__device__ __nv_bfloat16 g_xh[(size_t)B_ * L_ * D_];
__device__ __nv_bfloat16 g_xl[(size_t)B_ * L_ * D_];
__device__ __nv_bfloat16 g_wqh[(size_t)D_ * D_];
__device__ __nv_bfloat16 g_wql[(size_t)D_ * D_];
__device__ __nv_bfloat16 g_wkh[(size_t)NKV_ * HD_ * D_];
__device__ __nv_bfloat16 g_wkl[(size_t)NKV_ * HD_ * D_];
__device__ __nv_bfloat16 g_wvh[(size_t)NKV_ * HD_ * D_];
__device__ __nv_bfloat16 g_wvl[(size_t)NKV_ * HD_ * D_];
__device__ __nv_bfloat16 g_woh[(size_t)D_ * D_];
__device__ __nv_bfloat16 g_wol[(size_t)D_ * D_];
__device__ __nv_bfloat16 g_oh[(size_t)B_ * L_ * D_];
__device__ __nv_bfloat16 g_ol[(size_t)B_ * L_ * D_];

__device__ __nv_bfloat16 g_qh[(size_t)B_ * L_ * NH_ * HD_];
__device__ __nv_bfloat16 g_ql[(size_t)B_ * L_ * NH_ * HD_];
__device__ __nv_bfloat16 g_kh[(size_t)B_ * L_ * NKV_ * HD_];
__device__ __nv_bfloat16 g_kl[(size_t)B_ * L_ * NKV_ * HD_];
__device__ __nv_bfloat16 g_vth[(size_t)B_ * NKV_ * HD_ * L_];
__device__ __nv_bfloat16 g_vtl[(size_t)B_ * NKV_ * HD_ * L_];

// ---------------- helpers ----------------
__device__ __forceinline__ uint32_t smem_u32(const void* p) {
    uint32_t a;
    asm("{ .reg .u64 t; cvta.to.shared.u64 t, %1; cvt.u32.u64 %0, t; }"
        : "=r"(a) : "l"(p));
    return a;
}
#define LDSM4(r, a) \
    asm volatile("ldmatrix.sync.aligned.m8n8.x4.shared.b16 {%0,%1,%2,%3}, [%4];" \
                 : "=r"((r)[0]), "=r"((r)[1]), "=r"((r)[2]), "=r"((r)[3]) : "r"(a))
#define LDSM2(r, a) \
    asm volatile("ldmatrix.sync.aligned.m8n8.x2.shared.b16 {%0,%1}, [%2];" \
                 : "=r"((r)[0]), "=r"((r)[1]) : "r"(a))
#define MMA16816(d, a, b) \
    asm volatile("mma.sync.aligned.m16n8k16.row.col.f32.bf16.bf16.f32 " \
                 "{%0,%1,%2,%3}, {%4,%5,%6,%7}, {%8,%9}, {%0,%1,%2,%3};" \
                 : "+f"((d)[0]), "+f"((d)[1]), "+f"((d)[2]), "+f"((d)[3]) \
                 : "r"((a)[0]), "r"((a)[1]), "r"((a)[2]), "r"((a)[3]), \
                   "r"((b)[0]), "r"((b)[1]))
#define CP_ASYNC16(s, g) \
    asm volatile("cp.async.cg.shared.global [%0], [%1], 16;" :: "r"(s), "l"(g))
#define CP_COMMIT() asm volatile("cp.async.commit_group;" ::: "memory")
#define CP_WAIT1()  asm volatile("cp.async.wait_group 1;" ::: "memory")
#define CP_WAIT0()  asm volatile("cp.async.wait_group 0;" ::: "memory")

__device__ __forceinline__ uint32_t packbf2(__nv_bfloat16 lo, __nv_bfloat16 hi) {
    __nv_bfloat162 t = __halves2bfloat162(lo, hi);
    return *(uint32_t*)&t;
}

__device__ __forceinline__ void split4(const float4 v, __nv_bfloat16* h,
                                       __nv_bfloat16* l, int i4) {
    __nv_bfloat16 h0 = __float2bfloat16_rn(v.x);
    __nv_bfloat16 h1 = __float2bfloat16_rn(v.y);
    __nv_bfloat16 h2 = __float2bfloat16_rn(v.z);
    __nv_bfloat16 h3 = __float2bfloat16_rn(v.w);
    h[i4 * 4 + 0] = h0; h[i4 * 4 + 1] = h1; h[i4 * 4 + 2] = h2; h[i4 * 4 + 3] = h3;
    l[i4 * 4 + 0] = __float2bfloat16_rn(v.x - __bfloat162float(h0));
    l[i4 * 4 + 1] = __float2bfloat16_rn(v.y - __bfloat162float(h1));
    l[i4 * 4 + 2] = __float2bfloat16_rn(v.z - __bfloat162float(h2));
    l[i4 * 4 + 3] = __float2bfloat16_rn(v.w - __bfloat162float(h3));
}

// ---------------------------------------------------------------------------
__global__ void split_bf16(const float* __restrict__ s,
                           __nv_bfloat16* __restrict__ h,
                           __nv_bfloat16* __restrict__ l, int n4) {
    const int i = blockIdx.x * blockDim.x + threadIdx.x;
    if (i >= n4) return;
    split4(((const float4*)s)[i], h, l, i);
}

// ---------------------------------------------------------------------------
#define PREP_BLOCKS 20992
__global__ void __launch_bounds__(256) prep_split(const float* __restrict__ x,
                                                  const float* __restrict__ Wq,
                                                  const float* __restrict__ Wk,
                                                  const float* __restrict__ Wv,
                                                  const float* __restrict__ Wo) {
    int bid = blockIdx.x;
    const int tid = threadIdx.x;
    if (bid < 512) {
        const int idx = bid * 256 + tid;
        const int i = idx & 63;
        const int pos = idx >> 6;
        const double inv = exp(-(double)i / 64.0 * log(10000.0));
        double sd, cd;
        sincos((double)pos * inv, &sd, &cd);
        g_cos[idx] = (float)cd;
        g_sin[idx] = (float)sd;
        return;
    }
    bid -= 512;
    const float* src;
    __nv_bfloat16 *h, *l;
    int base;
    if (bid < 8192)       { src = x;  h = g_xh;  l = g_xl;  base = bid; }
    else if (bid < 12288) { src = Wq; h = g_wqh; l = g_wql; base = bid - 8192; }
    else if (bid < 14336) { src = Wk; h = g_wkh; l = g_wkl; base = bid - 12288; }
    else if (bid < 16384) { src = Wv; h = g_wvh; l = g_wvl; base = bid - 14336; }
    else                  { src = Wo; h = g_woh; l = g_wol; base = bid - 16384; }
    const int i = base * 256 + tid;
    split4(((const float4*)src)[i], h, l, i);
}

// ---------------------------------------------------------------------------
// mma.sync bf16x3 GEMM, K-chunk 32, cp.async double-buffered, 2 CTAs/SM.
// MMA issue is PRODUCT-MAJOR: 16 independent accumulators between reuses.
// ---------------------------------------------------------------------------
#define GSTG 40960
#define GT_SMEM (2 * GSTG)

__global__ void __launch_bounds__(256, 2) gemm_mma(const __nv_bfloat16* __restrict__ Ah,
                                                   const __nv_bfloat16* __restrict__ Al,
                                                   const __nv_bfloat16* __restrict__ Bh,
                                                   const __nv_bfloat16* __restrict__ Bl,
                                                   float* __restrict__ C,
                                                   int N, int K) {
    extern __shared__ __nv_bfloat16 sb[];
    const uint32_t sbase = smem_u32(sb);

    const int tid = threadIdx.x;
    const int lane = tid & 31;
    const int wid = tid >> 5;
    const int wm = (wid >> 2) * 64;
    const int wn = (wid & 3) * 32;
    const int m0 = blockIdx.y * 128;
    const int n0 = blockIdx.x * 128;

    const int srow = tid >> 1;
    const int sub  = (tid & 1) * 2;

    const char* gAh = (const char*)(Ah + (size_t)(m0 + srow) * K);
    const char* gAl = (const char*)(Al + (size_t)(m0 + srow) * K);
    const char* gBh = (const char*)(Bh + (size_t)(n0 + srow) * K);
    const char* gBl = (const char*)(Bl + (size_t)(n0 + srow) * K);
    const uint32_t srow80 = srow * 80;

    auto stage = [&](int kc, uint32_t sbuf) {
#pragma unroll
        for (int u = 0; u < 2; ++u) {
            const int off = (sub + u) * 16;
            const uint32_t d = sbuf + srow80 + off;
            const int gofs = kc * 2 + off;
            CP_ASYNC16(d,         gAh + gofs);
            CP_ASYNC16(d + 10240, gAl + gofs);
            CP_ASYNC16(d + 20480, gBh + gofs);
            CP_ASYNC16(d + 30720, gBl + gofs);
        }
    };

    float acc[4][4][4];
#pragma unroll
    for (int i = 0; i < 4; ++i)
#pragma unroll
        for (int j = 0; j < 4; ++j)
#pragma unroll
            for (int q = 0; q < 4; ++q) acc[i][j][q] = 0.f;

    const int arow = lane & 15, acol = (lane >> 4) << 3;
    const int brow = lane & 7,  bcol = ((lane >> 3) & 1) << 3;
    const uint32_t a_h0 = sbase + (wm + arow) * 80 + acol * 2;
    const uint32_t b_h0 = sbase + 20480 + (wn + brow) * 80 + bcol * 2;

    stage(0, sbase);
    CP_COMMIT();

    const int nchunk = K >> 5;
    for (int c = 0; c < nchunk; ++c) {
        if (c + 1 < nchunk) {
            stage((c + 1) << 5, sbase + (uint32_t)((c + 1) & 1) * GSTG);
            CP_COMMIT();
            CP_WAIT1();
        } else {
            CP_WAIT0();
        }
        __syncthreads();

        const uint32_t boff = (uint32_t)(c & 1) * GSTG;
        const uint32_t a_h = a_h0 + boff;
        const uint32_t a_l = a_h + 10240;
        const uint32_t b_h = b_h0 + boff;
        const uint32_t b_l = b_h + 10240;

#pragma unroll
        for (int ks = 0; ks < 2; ++ks) {
            const uint32_t koff = ks * 32;
            uint32_t ah[4][4], al[4][4], bh[4][2], bl[4][2];
#pragma unroll
            for (int mi = 0; mi < 4; ++mi) {
                LDSM4(ah[mi], a_h + mi * (16 * 80) + koff);
                LDSM4(al[mi], a_l + mi * (16 * 80) + koff);
            }
#pragma unroll
            for (int ni = 0; ni < 4; ++ni) {
                LDSM2(bh[ni], b_h + ni * (8 * 80) + koff);
                LDSM2(bl[ni], b_l + ni * (8 * 80) + koff);
            }
            // product-major: 16 independent accs between reuses
#pragma unroll
            for (int mi = 0; mi < 4; ++mi)
#pragma unroll
                for (int ni = 0; ni < 4; ++ni)
                    MMA16816(acc[mi][ni], ah[mi], bh[ni]);
#pragma unroll
            for (int mi = 0; mi < 4; ++mi)
#pragma unroll
                for (int ni = 0; ni < 4; ++ni)
                    MMA16816(acc[mi][ni], ah[mi], bl[ni]);
#pragma unroll
            for (int mi = 0; mi < 4; ++mi)
#pragma unroll
                for (int ni = 0; ni < 4; ++ni)
                    MMA16816(acc[mi][ni], al[mi], bh[ni]);
        }
        __syncthreads();
    }

    const int erow = lane >> 2;
    const int ecol = (lane & 3) * 2;
#pragma unroll
    for (int mi = 0; mi < 4; ++mi)
#pragma unroll
        for (int ni = 0; ni < 4; ++ni) {
            float* cp = C + (size_t)(m0 + wm + mi * 16 + erow) * N + n0 + wn + ni * 8 + ecol;
            *(float2*)cp = make_float2(acc[mi][ni][0], acc[mi][ni][1]);
            *(float2*)(cp + 8 * (size_t)N) = make_float2(acc[mi][ni][2], acc[mi][ni][3]);
        }
}

// ---------------------------------------------------------------------------
#define RVT_BLOCKS 28672
__global__ void __launch_bounds__(256) rope_vt(const float* __restrict__ q,
                                               const float* __restrict__ k,
                                               const float* __restrict__ v) {
    const int bid = blockIdx.x;
    const int tid = threadIdx.x;
    if (bid < 24576) {
        const long long idx = (long long)bid * 256 + tid;
        const int i  = (int)(idx & 63);
        long long r  = idx >> 6;
        const int hh = (int)(r % (NH_ + NKV_));
        r /= (NH_ + NKV_);
        const int bl  = (int)r;
        const int pos = bl & (L_ - 1);

        const float* src;
        __nv_bfloat16 *dh, *dl;
        size_t off;
        if (hh < NH_) {
            off = ((size_t)bl * NH_ + hh) * HD_;
            src = q + off; dh = g_qh + off; dl = g_ql + off;
        } else {
            off = ((size_t)bl * NKV_ + (hh - NH_)) * HD_;
            src = k + off; dh = g_kh + off; dl = g_kl + off;
        }

        const float c = g_cos[pos * 64 + i];
        const float s = g_sin[pos * 64 + i];
        const float a = src[i];
        const float b = src[i + 64];
        const float r0 = a * c - b * s;
        const float r1 = b * c + a * s;

        const __nv_bfloat16 h0 = __float2bfloat16_rn(r0);
        const __nv_bfloat16 h1 = __float2bfloat16_rn(r1);
        dh[i]      = h0;
        dh[i + 64] = h1;
        dl[i]      = __float2bfloat16_rn(r0 - __bfloat162float(h0));
        dl[i + 64] = __float2bfloat16_rn(r1 - __bfloat162float(h1));
    } else {
        __shared__ float s[32][33];
        const int lb = bid - 24576;
        const int l0 = (lb & 63) * 32;
        const int d0 = ((lb >> 6) & 3) * 32;
        const int bk = lb >> 8;
        const int b = bk >> 3, kvh = bk & 7;
        const int tx = tid & 31, ty = tid >> 5;

        const float* vb = v + ((size_t)b * L_ * NKV_ + kvh) * HD_;
#pragma unroll
        for (int rr = 0; rr < 4; ++rr) {
            const int lr = ty * 4 + rr;
            s[lr][tx] = vb[(size_t)(l0 + lr) * (NKV_ * HD_) + d0 + tx];
        }
        __syncthreads();

        __nv_bfloat16* oh = g_vth + (size_t)bk * HD_ * L_;
        __nv_bfloat16* ol = g_vtl + (size_t)bk * HD_ * L_;
#pragma unroll
        for (int rr = 0; rr < 4; ++rr) {
            const int dr = ty * 4 + rr;
            const float val = s[tx][dr];
            const __nv_bfloat16 hv = __float2bfloat16_rn(val);
            oh[(size_t)(d0 + dr) * L_ + l0 + tx] = hv;
            ol[(size_t)(d0 + dr) * L_ + l0 + tx] =
                __float2bfloat16_rn(val - __bfloat162float(hv));
        }
    }
}

// ---------------------------------------------------------------------------
// Flash attention: 64 q-rows / 128 threads, k-tile 64, single K/V buffer,
// 104KB smem -> 2 CTAs/SM, full 3-product split math, product-major S-phase.
// ---------------------------------------------------------------------------
#define OQH 0
#define OQL 17408
#define OKH2 34816
#define OKL2 52224
#define OVH2 69632
#define OVL2 88064
#define FM_SMEM 106496

__global__ void __launch_bounds__(128) flash_mma(const __nv_bfloat16* __restrict__ Qhg,
                                                 const __nv_bfloat16* __restrict__ Qlg,
                                                 const __nv_bfloat16* __restrict__ Khg,
                                                 const __nv_bfloat16* __restrict__ Klg,
                                                 const __nv_bfloat16* __restrict__ Vthg,
                                                 const __nv_bfloat16* __restrict__ Vtlg,
                                                 float* __restrict__ O) {
    extern __shared__ char smem[];
    const uint32_t sQ = smem_u32(smem);

    const int tid = threadIdx.x;
    const int lane = tid & 31, wid = tid >> 5;
    const int b = blockIdx.z, h = blockIdx.y;
    const int kvh = h >> 1;
    const int qt = (gridDim.x - 1) - blockIdx.x;
    const int q0 = qt * 64;
    const int wrow = wid * 16;

    const char* qh_g = (const char*)(Qhg + ((size_t)(b * L_ + q0) * NH_ + h) * HD_);
    const char* ql_g = (const char*)(Qlg + ((size_t)(b * L_ + q0) * NH_ + h) * HD_);
    const char* kh_g = (const char*)(Khg + ((size_t)b * L_ * NKV_ + kvh) * HD_);
    const char* kl_g = (const char*)(Klg + ((size_t)b * L_ * NKV_ + kvh) * HD_);
    const char* vth_g = (const char*)(Vthg + (size_t)(b * NKV_ + kvh) * HD_ * L_);
    const char* vtl_g = (const char*)(Vtlg + (size_t)(b * NKV_ + kvh) * HD_ * L_);

    for (int i = tid; i < 64 * 16; i += 128) {
        const int row = i >> 4;
        const int u = (i & 15) << 4;
        const size_t g = (size_t)row * (NH_ * HD_ * 2) + u;
        const uint32_t d = row * 272 + u;
        CP_ASYNC16(sQ + OQH + d, qh_g + g);
        CP_ASYNC16(sQ + OQL + d, ql_g + g);
    }

    const uint32_t aQh = sQ + OQH + (wrow + (lane & 15)) * 272 + ((lane >> 4) << 4);
    const uint32_t aQl = aQh + (OQL - OQH);
    const uint32_t bKh = sQ + OKH2 + (lane & 7) * 272 + (((lane >> 3) & 1) << 4);
    const uint32_t bKl = bKh + (OKL2 - OKH2);
    const uint32_t bVh = sQ + OVH2 + (lane & 7) * 144 + (((lane >> 3) & 1) << 4);
    const uint32_t bVl = bVh + (OVL2 - OVH2);

    float m0 = -1e30f, m1 = -1e30f, l0 = 0.f, l1 = 0.f;
    float ao[16][4];
#pragma unroll
    for (int i = 0; i < 16; ++i)
#pragma unroll
        for (int j = 0; j < 4; ++j) ao[i][j] = 0.f;

    for (int t = 0; t <= qt; ++t) {
        const int k0 = t * 64;

        for (int i = tid; i < 64 * 16; i += 128) {
            const int row = i >> 4;
            const int u = (i & 15) << 4;
            const size_t g = (size_t)(k0 + row) * (NKV_ * HD_ * 2) + u;
            const uint32_t d = row * 272 + u;
            CP_ASYNC16(sQ + OKH2 + d, kh_g + g);
            CP_ASYNC16(sQ + OKL2 + d, kl_g + g);
        }
        for (int i = tid; i < 128 * 8; i += 128) {
            const int row = i >> 3;
            const int u = (i & 7) << 4;
            const size_t g = (size_t)row * (L_ * 2) + (size_t)k0 * 2 + u;
            const uint32_t d = row * 144 + u;
            CP_ASYNC16(sQ + OVH2 + d, vth_g + g);
            CP_ASYNC16(sQ + OVL2 + d, vtl_g + g);
        }
        CP_COMMIT();
        CP_WAIT0();
        __syncthreads();

        // ---- S = Q @ K^T (3-way split, product-major) ----
        float sc[8][4];
#pragma unroll
        for (int ni = 0; ni < 8; ++ni)
#pragma unroll
            for (int j = 0; j < 4; ++j) sc[ni][j] = 0.f;

#pragma unroll
        for (int ks = 0; ks < 8; ++ks) {
            const uint32_t koff = ks * 32;
            uint32_t ah[4], al[4];
            LDSM4(ah, aQh + koff);
            LDSM4(al, aQl + koff);
            uint32_t bh[8][2], bl[8][2];
#pragma unroll
            for (int ni = 0; ni < 8; ++ni) {
                LDSM2(bh[ni], bKh + ni * (8 * 272) + koff);
                LDSM2(bl[ni], bKl + ni * (8 * 272) + koff);
            }
#pragma unroll
            for (int ni = 0; ni < 8; ++ni) MMA16816(sc[ni], ah, bh[ni]);
#pragma unroll
            for (int ni = 0; ni < 8; ++ni) MMA16816(sc[ni], ah, bl[ni]);
#pragma unroll
            for (int ni = 0; ni < 8; ++ni) MMA16816(sc[ni], al, bh[ni]);
        }

#pragma unroll
        for (int ni = 0; ni < 8; ++ni)
#pragma unroll
            for (int j = 0; j < 4; ++j) sc[ni][j] *= SCALE_;

        if (t == qt) {
            const int qr0 = q0 + wrow + (lane >> 2);
#pragma unroll
            for (int ni = 0; ni < 8; ++ni) {
                const int kc = k0 + ni * 8 + (lane & 3) * 2;
                if (kc > qr0)         sc[ni][0] = -1e30f;
                if (kc + 1 > qr0)     sc[ni][1] = -1e30f;
                if (kc > qr0 + 8)     sc[ni][2] = -1e30f;
                if (kc + 1 > qr0 + 8) sc[ni][3] = -1e30f;
            }
        }

        float mx0 = -1e30f, mx1 = -1e30f;
#pragma unroll
        for (int ni = 0; ni < 8; ++ni) {
            mx0 = fmaxf(mx0, fmaxf(sc[ni][0], sc[ni][1]));
            mx1 = fmaxf(mx1, fmaxf(sc[ni][2], sc[ni][3]));
        }
        mx0 = fmaxf(mx0, __shfl_xor_sync(0xffffffffu, mx0, 1));
        mx0 = fmaxf(mx0, __shfl_xor_sync(0xffffffffu, mx0, 2));
        mx1 = fmaxf(mx1, __shfl_xor_sync(0xffffffffu, mx1, 1));
        mx1 = fmaxf(mx1, __shfl_xor_sync(0xffffffffu, mx1, 2));

        const float nm0 = fmaxf(m0, mx0), nm1 = fmaxf(m1, mx1);
        const float al0 = __expf(m0 - nm0), al1 = __expf(m1 - nm1);
        float s0 = 0.f, s1 = 0.f;
#pragma unroll
        for (int ni = 0; ni < 8; ++ni) {
            sc[ni][0] = __expf(sc[ni][0] - nm0); s0 += sc[ni][0];
            sc[ni][1] = __expf(sc[ni][1] - nm0); s0 += sc[ni][1];
            sc[ni][2] = __expf(sc[ni][2] - nm1); s1 += sc[ni][2];
            sc[ni][3] = __expf(sc[ni][3] - nm1); s1 += sc[ni][3];
        }
        s0 += __shfl_xor_sync(0xffffffffu, s0, 1);
        s0 += __shfl_xor_sync(0xffffffffu, s0, 2);
        s1 += __shfl_xor_sync(0xffffffffu, s1, 1);
        s1 += __shfl_xor_sync(0xffffffffu, s1, 2);
        l0 = l0 * al0 + s0; l1 = l1 * al1 + s1;
        m0 = nm0; m1 = nm1;

#pragma unroll
        for (int i = 0; i < 16; ++i) {
            ao[i][0] *= al0; ao[i][1] *= al0;
            ao[i][2] *= al1; ao[i][3] *= al1;
        }

        // ---- O += P @ V (3-product split, pairwise-interleaved) ----
#pragma unroll
        for (int ks = 0; ks < 4; ++ks) {
            const float p0 = sc[2 * ks][0], p1 = sc[2 * ks][1];
            const float p2 = sc[2 * ks][2], p3 = sc[2 * ks][3];
            const float p4 = sc[2 * ks + 1][0], p5 = sc[2 * ks + 1][1];
            const float p6 = sc[2 * ks + 1][2], p7 = sc[2 * ks + 1][3];
            const __nv_bfloat16 q0b = __float2bfloat16_rn(p0), q1b = __float2bfloat16_rn(p1);
            const __nv_bfloat16 q2b = __float2bfloat16_rn(p2), q3b = __float2bfloat16_rn(p3);
            const __nv_bfloat16 q4b = __float2bfloat16_rn(p4), q5b = __float2bfloat16_rn(p5);
            const __nv_bfloat16 q6b = __float2bfloat16_rn(p6), q7b = __float2bfloat16_rn(p7);
            uint32_t pah[4], pal[4];
            pah[0] = packbf2(q0b, q1b);
            pah[1] = packbf2(q2b, q3b);
            pah[2] = packbf2(q4b, q5b);
            pah[3] = packbf2(q6b, q7b);
            pal[0] = packbf2(__float2bfloat16_rn(p0 - __bfloat162float(q0b)),
                             __float2bfloat16_rn(p1 - __bfloat162float(q1b)));
            pal[1] = packbf2(__float2bfloat16_rn(p2 - __bfloat162float(q2b)),
                             __float2bfloat16_rn(p3 - __bfloat162float(q3b)));
            pal[2] = packbf2(__float2bfloat16_rn(p4 - __bfloat162float(q4b)),
                             __float2bfloat16_rn(p5 - __bfloat162float(q5b)));
            pal[3] = packbf2(__float2bfloat16_rn(p6 - __bfloat162float(q6b)),
                             __float2bfloat16_rn(p7 - __bfloat162float(q7b)));

            const uint32_t koff = ks * 32;
#pragma unroll
            for (int ni = 0; ni < 16; ni += 2) {
                uint32_t b0h[2], b0l[2], b1h[2], b1l[2];
                LDSM2(b0h, bVh + ni * (8 * 144) + koff);
                LDSM2(b0l, bVl + ni * (8 * 144) + koff);
                LDSM2(b1h, bVh + (ni + 1) * (8 * 144) + koff);
                LDSM2(b1l, bVl + (ni + 1) * (8 * 144) + koff);
                MMA16816(ao[ni], pah, b0h);
                MMA16816(ao[ni + 1], pah, b1h);
                MMA16816(ao[ni], pal, b0h);
                MMA16816(ao[ni + 1], pal, b1h);
                MMA16816(ao[ni], pah, b0l);
                MMA16816(ao[ni + 1], pah, b1l);
            }
        }
        __syncthreads();
    }

    const float inv0 = 1.0f / l0, inv1 = 1.0f / l1;
    const int r0 = q0 + wrow + (lane >> 2);
    const int ecol = (lane & 3) * 2;
    float* Ob0 = O + ((size_t)(b * L_ + r0) * NH_ + h) * HD_ + ecol;
    float* Ob1 = O + ((size_t)(b * L_ + r0 + 8) * NH_ + h) * HD_ + ecol;
#pragma unroll
    for (int ni = 0; ni < 16; ++ni) {
        *(float2*)(Ob0 + ni * 8) = make_float2(ao[ni][0] * inv0, ao[ni][1] * inv0);
        *(float2*)(Ob1 + ni * 8) = make_float2(ao[ni][2] * inv1, ao[ni][3] * inv1);
    }
}

// ---------------------------------------------------------------------------
extern "C" void kernel_launch(void* const* d_in, const int* in_sizes, int n_in,
                              void* d_out, int out_size) {
    const float* x  = (const float*)d_in[0];
    const float* Wq = (const float*)d_in[1];
    const float* Wk = (const float*)d_in[2];
    const float* Wv = (const float*)d_in[3];
    const float* Wo = (const float*)d_in[4];
    float* out = (float*)d_out;

    float *q, *k, *v, *o;
    cudaGetSymbolAddress((void**)&q, g_q);
    cudaGetSymbolAddress((void**)&k, g_k);
    cudaGetSymbolAddress((void**)&v, g_v);
    cudaGetSymbolAddress((void**)&o, g_o);
    __nv_bfloat16 *xh, *xl, *wqh, *wql, *wkh, *wkl, *wvh, *wvl, *woh, *wol, *oh, *ol;
    __nv_bfloat16 *qh, *ql, *kh, *kl, *vth, *vtl;
    cudaGetSymbolAddress((void**)&xh, g_xh);   cudaGetSymbolAddress((void**)&xl, g_xl);
    cudaGetSymbolAddress((void**)&wqh, g_wqh); cudaGetSymbolAddress((void**)&wql, g_wql);
    cudaGetSymbolAddress((void**)&wkh, g_wkh); cudaGetSymbolAddress((void**)&wkl, g_wkl);
    cudaGetSymbolAddress((void**)&wvh, g_wvh); cudaGetSymbolAddress((void**)&wvl, g_wvl);
    cudaGetSymbolAddress((void**)&woh, g_woh); cudaGetSymbolAddress((void**)&wol, g_wol);
    cudaGetSymbolAddress((void**)&oh, g_oh);   cudaGetSymbolAddress((void**)&ol, g_ol);
    cudaGetSymbolAddress((void**)&qh, g_qh);   cudaGetSymbolAddress((void**)&ql, g_ql);
    cudaGetSymbolAddress((void**)&kh, g_kh);   cudaGetSymbolAddress((void**)&kl, g_kl);
    cudaGetSymbolAddress((void**)&vth, g_vth); cudaGetSymbolAddress((void**)&vtl, g_vtl);

    const int M = B_ * L_;       // 4096
    const int NKVD = NKV_ * HD_; // 1024

    cudaFuncSetAttribute(gemm_mma, cudaFuncAttributeMaxDynamicSharedMemorySize, GT_SMEM);
    cudaFuncSetAttribute(flash_mma, cudaFuncAttributeMaxDynamicSharedMemorySize, FM_SMEM);

    prep_split<<<PREP_BLOCKS, 256>>>(x, Wq, Wk, Wv, Wo);

    gemm_mma<<<dim3(D_ / 128, M / 128), 256, GT_SMEM>>>(xh, xl, wqh, wql, q, D_, D_);
    gemm_mma<<<dim3(NKVD / 128, M / 128), 256, GT_SMEM>>>(xh, xl, wkh, wkl, k, NKVD, D_);
    gemm_mma<<<dim3(NKVD / 128, M / 128), 256, GT_SMEM>>>(xh, xl, wvh, wvl, v, NKVD, D_);

    rope_vt<<<RVT_BLOCKS, 256>>>(q, k, v);

    flash_mma<<<dim3(L_ / 64, NH_, B_), 128, FM_SMEM>>>(qh, ql, kh, kl, vth, vtl, o);

    split_bf16<<<(M * D_ / 4 + 255) / 256, 256>>>(o, oh, ol, M * D_ / 4);
    gemm_mma<<<dim3(D_ / 128, M / 128), 256, GT_SMEM>>>(oh, ol, woh, wol, out, D_, D_);
}

// round 15
// speedup vs baseline: 1.5317x; 1.1128x over previous
#include <cuda_runtime.h>
#include <cuda_fp16.h>
#include <math.h>
#include <stdint.h>

#define B_  2
#define L_  2048
#define D_  2048
#define NH_ 16
#define NKV_ 8
#define HD_ 128
#define GQ_ 2
#define SCALE_ 0.08838834764831845f  // 128^-0.5

// ---------------- scratch (static device globals) ----------------
__device__ float g_q[(size_t)B_ * L_ * NH_ * HD_];
__device__ float g_k[(size_t)B_ * L_ * NKV_ * HD_];
__device__ float g_v[(size_t)B_ * L_ * NKV_ * HD_];
__device__ float g_o[(size_t)B_ * L_ * NH_ * HD_];
__device__ float g_cos[(size_t)L_ * 64];
__device__ float g_sin[(size_t)L_ * 64];

__device__ __half g_x16[(size_t)B_ * L_ * D_];
__device__ __half g_wqh[(size_t)D_ * D_];
__device__ __half g_wql[(size_t)D_ * D_];
__device__ __half g_wkh[(size_t)NKV_ * HD_ * D_];
__device__ __half g_wkl[(size_t)NKV_ * HD_ * D_];
__device__ __half g_wvh[(size_t)NKV_ * HD_ * D_];
__device__ __half g_wvl[(size_t)NKV_ * HD_ * D_];
__device__ __half g_woh[(size_t)D_ * D_];
__device__ __half g_wol[(size_t)D_ * D_];
__device__ __half g_o16[(size_t)B_ * L_ * D_];

// attention operands (RoPE'd / transposed)
__device__ __half g_q16[(size_t)B_ * L_ * NH_ * HD_];
__device__ __half g_kh[(size_t)B_ * L_ * NKV_ * HD_];
__device__ __half g_kl[(size_t)B_ * L_ * NKV_ * HD_];
__device__ __half g_vth[(size_t)B_ * NKV_ * HD_ * L_];
__device__ __half g_vtl[(size_t)B_ * NKV_ * HD_ * L_];

// ---------------- helpers ----------------
__device__ __forceinline__ uint32_t smem_u32(const void* p) {
    uint32_t a;
    asm("{ .reg .u64 t; cvta.to.shared.u64 t, %1; cvt.u32.u64 %0, t; }"
        : "=r"(a) : "l"(p));
    return a;
}
#define LDSM4(r, a) \
    asm volatile("ldmatrix.sync.aligned.m8n8.x4.shared.b16 {%0,%1,%2,%3}, [%4];" \
                 : "=r"((r)[0]), "=r"((r)[1]), "=r"((r)[2]), "=r"((r)[3]) : "r"(a))
#define LDSM2(r, a) \
    asm volatile("ldmatrix.sync.aligned.m8n8.x2.shared.b16 {%0,%1}, [%2];" \
                 : "=r"((r)[0]), "=r"((r)[1]) : "r"(a))
#define MMA16816H(d, a, b) \
    asm volatile("mma.sync.aligned.m16n8k16.row.col.f32.f16.f16.f32 " \
                 "{%0,%1,%2,%3}, {%4,%5,%6,%7}, {%8,%9}, {%0,%1,%2,%3};" \
                 : "+f"((d)[0]), "+f"((d)[1]), "+f"((d)[2]), "+f"((d)[3]) \
                 : "r"((a)[0]), "r"((a)[1]), "r"((a)[2]), "r"((a)[3]), \
                   "r"((b)[0]), "r"((b)[1]))
#define CP_ASYNC16(s, g) \
    asm volatile("cp.async.cg.shared.global [%0], [%1], 16;" :: "r"(s), "l"(g))
#define CP_COMMIT() asm volatile("cp.async.commit_group;" ::: "memory")
#define CP_WAIT1()  asm volatile("cp.async.wait_group 1;" ::: "memory")
#define CP_WAIT0()  asm volatile("cp.async.wait_group 0;" ::: "memory")

__device__ __forceinline__ uint32_t packh2(__half lo, __half hi) {
    __half2 t = __halves2half2(lo, hi);
    return *(uint32_t*)&t;
}

__device__ __forceinline__ void wsplit4(const float4 v, __half* h, __half* l, int i4) {
    __half h0 = __float2half_rn(v.x);
    __half h1 = __float2half_rn(v.y);
    __half h2 = __float2half_rn(v.z);
    __half h3 = __float2half_rn(v.w);
    h[i4 * 4 + 0] = h0; h[i4 * 4 + 1] = h1; h[i4 * 4 + 2] = h2; h[i4 * 4 + 3] = h3;
    l[i4 * 4 + 0] = __float2half_rn(v.x - __half2float(h0));
    l[i4 * 4 + 1] = __float2half_rn(v.y - __half2float(h1));
    l[i4 * 4 + 2] = __float2half_rn(v.z - __half2float(h2));
    l[i4 * 4 + 3] = __float2half_rn(v.w - __half2float(h3));
}

// ---------------------------------------------------------------------------
// conv_fp16: fp32 -> fp16 (single)
// ---------------------------------------------------------------------------
__global__ void conv_fp16(const float* __restrict__ s, __half* __restrict__ h, int n4) {
    const int i = blockIdx.x * blockDim.x + threadIdx.x;
    if (i >= n4) return;
    const float4 v = ((const float4*)s)[i];
    h[i * 4 + 0] = __float2half_rn(v.x);
    h[i * 4 + 1] = __float2half_rn(v.y);
    h[i * 4 + 2] = __float2half_rn(v.z);
    h[i * 4 + 3] = __float2half_rn(v.w);
}

// ---------------------------------------------------------------------------
// prep_split: rope table + x fp16 convert + weight hi/lo splits, ONE launch.
// blocks: 512 rope | x 8192 | Wq 4096 | Wk 2048 | Wv 2048 | Wo 4096
// ---------------------------------------------------------------------------
#define PREP_BLOCKS 20992
__global__ void __launch_bounds__(256) prep_split(const float* __restrict__ x,
                                                  const float* __restrict__ Wq,
                                                  const float* __restrict__ Wk,
                                                  const float* __restrict__ Wv,
                                                  const float* __restrict__ Wo) {
    int bid = blockIdx.x;
    const int tid = threadIdx.x;
    if (bid < 512) {
        const int idx = bid * 256 + tid;
        const int i = idx & 63;
        const int pos = idx >> 6;
        const double inv = exp(-(double)i / 64.0 * log(10000.0));
        double sd, cd;
        sincos((double)pos * inv, &sd, &cd);
        g_cos[idx] = (float)cd;
        g_sin[idx] = (float)sd;
        return;
    }
    bid -= 512;
    if (bid < 8192) {
        const int i = bid * 256 + tid;
        const float4 v = ((const float4*)x)[i];
        g_x16[i * 4 + 0] = __float2half_rn(v.x);
        g_x16[i * 4 + 1] = __float2half_rn(v.y);
        g_x16[i * 4 + 2] = __float2half_rn(v.z);
        g_x16[i * 4 + 3] = __float2half_rn(v.w);
        return;
    }
    bid -= 8192;
    const float* src;
    __half *h, *l;
    int base;
    if (bid < 4096)      { src = Wq; h = g_wqh; l = g_wql; base = bid; }
    else if (bid < 6144) { src = Wk; h = g_wkh; l = g_wkl; base = bid - 4096; }
    else if (bid < 8192) { src = Wv; h = g_wvh; l = g_wvl; base = bid - 6144; }
    else                 { src = Wo; h = g_woh; l = g_wol; base = bid - 8192; }
    const int i = base * 256 + tid;
    wsplit4(((const float4*)src)[i], h, l, i);
}

// ---------------------------------------------------------------------------
// fp16x2 GEMM: C = A @ (Bh+Bl)^T. K-chunk 32, cp.async double-buffered,
// 2 CTAs/SM. Stage per buffer: A 0 (10240B), Bh 10240, Bl 20480; 30720B.
// ---------------------------------------------------------------------------
#define GSTG 30720
#define GT_SMEM (2 * GSTG)

__global__ void __launch_bounds__(256, 2) gemm_mma(const __half* __restrict__ A,
                                                   const __half* __restrict__ Bh,
                                                   const __half* __restrict__ Bl,
                                                   float* __restrict__ C,
                                                   int N, int K) {
    extern __shared__ __half sb[];
    const uint32_t sbase = smem_u32(sb);

    const int tid = threadIdx.x;
    const int lane = tid & 31;
    const int wid = tid >> 5;
    const int wm = (wid >> 2) * 64;
    const int wn = (wid & 3) * 32;
    const int m0 = blockIdx.y * 128;
    const int n0 = blockIdx.x * 128;

    const int srow = tid >> 1;
    const int sub  = (tid & 1) * 2;

    const char* gA  = (const char*)(A + (size_t)(m0 + srow) * K);
    const char* gBh = (const char*)(Bh + (size_t)(n0 + srow) * K);
    const char* gBl = (const char*)(Bl + (size_t)(n0 + srow) * K);
    const uint32_t srow80 = srow * 80;

    auto stage = [&](int kc, uint32_t sbuf) {
#pragma unroll
        for (int u = 0; u < 2; ++u) {
            const int off = (sub + u) * 16;
            const uint32_t d = sbuf + srow80 + off;
            const int gofs = kc * 2 + off;
            CP_ASYNC16(d,         gA + gofs);
            CP_ASYNC16(d + 10240, gBh + gofs);
            CP_ASYNC16(d + 20480, gBl + gofs);
        }
    };

    float acc[4][4][4];
#pragma unroll
    for (int i = 0; i < 4; ++i)
#pragma unroll
        for (int j = 0; j < 4; ++j)
#pragma unroll
            for (int q = 0; q < 4; ++q) acc[i][j][q] = 0.f;

    const int arow = lane & 15, acol = (lane >> 4) << 3;
    const int brow = lane & 7,  bcol = ((lane >> 3) & 1) << 3;
    const uint32_t a_0  = sbase + (wm + arow) * 80 + acol * 2;
    const uint32_t b_h0 = sbase + 10240 + (wn + brow) * 80 + bcol * 2;

    stage(0, sbase);
    CP_COMMIT();

    const int nchunk = K >> 5;
    for (int c = 0; c < nchunk; ++c) {
        if (c + 1 < nchunk) {
            stage((c + 1) << 5, sbase + (uint32_t)((c + 1) & 1) * GSTG);
            CP_COMMIT();
            CP_WAIT1();
        } else {
            CP_WAIT0();
        }
        __syncthreads();

        const uint32_t boff = (uint32_t)(c & 1) * GSTG;
        const uint32_t a_p = a_0 + boff;
        const uint32_t b_h = b_h0 + boff;
        const uint32_t b_l = b_h + 10240;

#pragma unroll
        for (int ks = 0; ks < 2; ++ks) {
            const uint32_t koff = ks * 32;
            uint32_t ah[4][4], bh[4][2], bl[4][2];
#pragma unroll
            for (int mi = 0; mi < 4; ++mi)
                LDSM4(ah[mi], a_p + mi * (16 * 80) + koff);
#pragma unroll
            for (int ni = 0; ni < 4; ++ni) {
                LDSM2(bh[ni], b_h + ni * (8 * 80) + koff);
                LDSM2(bl[ni], b_l + ni * (8 * 80) + koff);
            }
#pragma unroll
            for (int mi = 0; mi < 4; ++mi)
#pragma unroll
                for (int ni = 0; ni < 4; ++ni)
                    MMA16816H(acc[mi][ni], ah[mi], bh[ni]);
#pragma unroll
            for (int mi = 0; mi < 4; ++mi)
#pragma unroll
                for (int ni = 0; ni < 4; ++ni)
                    MMA16816H(acc[mi][ni], ah[mi], bl[ni]);
        }
        __syncthreads();
    }

    const int erow = lane >> 2;
    const int ecol = (lane & 3) * 2;
#pragma unroll
    for (int mi = 0; mi < 4; ++mi)
#pragma unroll
        for (int ni = 0; ni < 4; ++ni) {
            float* cp = C + (size_t)(m0 + wm + mi * 16 + erow) * N + n0 + wn + ni * 8 + ecol;
            *(float2*)cp = make_float2(acc[mi][ni][0], acc[mi][ni][1]);
            *(float2*)(cp + 8 * (size_t)N) = make_float2(acc[mi][ni][2], acc[mi][ni][3]);
        }
}

// ---------------------------------------------------------------------------
// rope_vt: RoPE -> q fp16 single / k hi/lo; V fp16 hi/lo + transpose.
// ---------------------------------------------------------------------------
#define RVT_BLOCKS 28672
__global__ void __launch_bounds__(256) rope_vt(const float* __restrict__ q,
                                               const float* __restrict__ k,
                                               const float* __restrict__ v) {
    const int bid = blockIdx.x;
    const int tid = threadIdx.x;
    if (bid < 24576) {
        const long long idx = (long long)bid * 256 + tid;
        const int i  = (int)(idx & 63);
        long long r  = idx >> 6;
        const int hh = (int)(r % (NH_ + NKV_));
        r /= (NH_ + NKV_);
        const int bl  = (int)r;
        const int pos = bl & (L_ - 1);

        const float c = g_cos[pos * 64 + i];
        const float s = g_sin[pos * 64 + i];

        if (hh < NH_) {
            const size_t off = ((size_t)bl * NH_ + hh) * HD_;
            const float a = q[off + i];
            const float b = q[off + i + 64];
            g_q16[off + i]      = __float2half_rn(a * c - b * s);
            g_q16[off + i + 64] = __float2half_rn(b * c + a * s);
        } else {
            const size_t off = ((size_t)bl * NKV_ + (hh - NH_)) * HD_;
            const float a = k[off + i];
            const float b = k[off + i + 64];
            const float r0 = a * c - b * s;
            const float r1 = b * c + a * s;
            const __half h0 = __float2half_rn(r0);
            const __half h1 = __float2half_rn(r1);
            g_kh[off + i]      = h0;
            g_kh[off + i + 64] = h1;
            g_kl[off + i]      = __float2half_rn(r0 - __half2float(h0));
            g_kl[off + i + 64] = __float2half_rn(r1 - __half2float(h1));
        }
    } else {
        __shared__ float s[32][33];
        const int lb = bid - 24576;
        const int l0 = (lb & 63) * 32;
        const int d0 = ((lb >> 6) & 3) * 32;
        const int bk = lb >> 8;
        const int b = bk >> 3, kvh = bk & 7;
        const int tx = tid & 31, ty = tid >> 5;

        const float* vb = v + ((size_t)b * L_ * NKV_ + kvh) * HD_;
#pragma unroll
        for (int rr = 0; rr < 4; ++rr) {
            const int lr = ty * 4 + rr;
            s[lr][tx] = vb[(size_t)(l0 + lr) * (NKV_ * HD_) + d0 + tx];
        }
        __syncthreads();

        __half* oh = g_vth + (size_t)bk * HD_ * L_;
        __half* ol = g_vtl + (size_t)bk * HD_ * L_;
#pragma unroll
        for (int rr = 0; rr < 4; ++rr) {
            const int dr = ty * 4 + rr;
            const float val = s[tx][dr];
            const __half hv = __float2half_rn(val);
            oh[(size_t)(d0 + dr) * L_ + l0 + tx] = hv;
            ol[(size_t)(d0 + dr) * L_ + l0 + tx] =
                __float2half_rn(val - __half2float(hv));
        }
    }
}

// ---------------------------------------------------------------------------
// Flash attention fp16x2: 64 q-rows / 128 threads, k-tile 64, single buffer.
// S = Q(Kh+Kl)^T (2 products), O += P(Vh+Vl) (2 products, no P-lo repack).
// smem: Q 64x272, Kh/Kl 64x272, Vth/Vtl 128x144 = 89088 B -> 2 CTAs/SM.
// ---------------------------------------------------------------------------
#define OQ   0
#define OKH  17408
#define OKL  34816
#define OVH  52224
#define OVL  70656
#define FM_SMEM 89088

__global__ void __launch_bounds__(128) flash_mma(const __half* __restrict__ Qg,
                                                 const __half* __restrict__ Khg,
                                                 const __half* __restrict__ Klg,
                                                 const __half* __restrict__ Vthg,
                                                 const __half* __restrict__ Vtlg,
                                                 float* __restrict__ O) {
    extern __shared__ char smem[];
    const uint32_t sQ = smem_u32(smem);

    const int tid = threadIdx.x;
    const int lane = tid & 31, wid = tid >> 5;
    const int b = blockIdx.z, h = blockIdx.y;
    const int kvh = h >> 1;
    const int qt = (gridDim.x - 1) - blockIdx.x;
    const int q0 = qt * 64;
    const int wrow = wid * 16;

    const char* q_g = (const char*)(Qg + ((size_t)(b * L_ + q0) * NH_ + h) * HD_);
    const char* kh_g = (const char*)(Khg + ((size_t)b * L_ * NKV_ + kvh) * HD_);
    const char* kl_g = (const char*)(Klg + ((size_t)b * L_ * NKV_ + kvh) * HD_);
    const char* vth_g = (const char*)(Vthg + (size_t)(b * NKV_ + kvh) * HD_ * L_);
    const char* vtl_g = (const char*)(Vtlg + (size_t)(b * NKV_ + kvh) * HD_ * L_);

    for (int i = tid; i < 64 * 16; i += 128) {
        const int row = i >> 4;
        const int u = (i & 15) << 4;
        CP_ASYNC16(sQ + OQ + row * 272 + u, q_g + (size_t)row * (NH_ * HD_ * 2) + u);
    }

    const uint32_t aQ  = sQ + OQ + (wrow + (lane & 15)) * 272 + ((lane >> 4) << 4);
    const uint32_t bKh = sQ + OKH + (lane & 7) * 272 + (((lane >> 3) & 1) << 4);
    const uint32_t bKl = bKh + (OKL - OKH);
    const uint32_t bVh = sQ + OVH + (lane & 7) * 144 + (((lane >> 3) & 1) << 4);
    const uint32_t bVl = bVh + (OVL - OVH);

    float m0 = -1e30f, m1 = -1e30f, l0 = 0.f, l1 = 0.f;
    float ao[16][4];
#pragma unroll
    for (int i = 0; i < 16; ++i)
#pragma unroll
        for (int j = 0; j < 4; ++j) ao[i][j] = 0.f;

    for (int t = 0; t <= qt; ++t) {
        const int k0 = t * 64;

        for (int i = tid; i < 64 * 16; i += 128) {
            const int row = i >> 4;
            const int u = (i & 15) << 4;
            const size_t g = (size_t)(k0 + row) * (NKV_ * HD_ * 2) + u;
            const uint32_t d = row * 272 + u;
            CP_ASYNC16(sQ + OKH + d, kh_g + g);
            CP_ASYNC16(sQ + OKL + d, kl_g + g);
        }
        for (int i = tid; i < 128 * 8; i += 128) {
            const int row = i >> 3;
            const int u = (i & 7) << 4;
            const size_t g = (size_t)row * (L_ * 2) + (size_t)k0 * 2 + u;
            const uint32_t d = row * 144 + u;
            CP_ASYNC16(sQ + OVH + d, vth_g + g);
            CP_ASYNC16(sQ + OVL + d, vtl_g + g);
        }
        CP_COMMIT();
        CP_WAIT0();
        __syncthreads();

        // ---- S = Q @ (Kh+Kl)^T, product-major ----
        float sc[8][4];
#pragma unroll
        for (int ni = 0; ni < 8; ++ni)
#pragma unroll
            for (int j = 0; j < 4; ++j) sc[ni][j] = 0.f;

#pragma unroll
        for (int ks = 0; ks < 8; ++ks) {
            const uint32_t koff = ks * 32;
            uint32_t ah[4];
            LDSM4(ah, aQ + koff);
            uint32_t bh[8][2], bl[8][2];
#pragma unroll
            for (int ni = 0; ni < 8; ++ni) {
                LDSM2(bh[ni], bKh + ni * (8 * 272) + koff);
                LDSM2(bl[ni], bKl + ni * (8 * 272) + koff);
            }
#pragma unroll
            for (int ni = 0; ni < 8; ++ni) MMA16816H(sc[ni], ah, bh[ni]);
#pragma unroll
            for (int ni = 0; ni < 8; ++ni) MMA16816H(sc[ni], ah, bl[ni]);
        }

#pragma unroll
        for (int ni = 0; ni < 8; ++ni)
#pragma unroll
            for (int j = 0; j < 4; ++j) sc[ni][j] *= SCALE_;

        if (t == qt) {
            const int qr0 = q0 + wrow + (lane >> 2);
#pragma unroll
            for (int ni = 0; ni < 8; ++ni) {
                const int kc = k0 + ni * 8 + (lane & 3) * 2;
                if (kc > qr0)         sc[ni][0] = -1e30f;
                if (kc + 1 > qr0)     sc[ni][1] = -1e30f;
                if (kc > qr0 + 8)     sc[ni][2] = -1e30f;
                if (kc + 1 > qr0 + 8) sc[ni][3] = -1e30f;
            }
        }

        float mx0 = -1e30f, mx1 = -1e30f;
#pragma unroll
        for (int ni = 0; ni < 8; ++ni) {
            mx0 = fmaxf(mx0, fmaxf(sc[ni][0], sc[ni][1]));
            mx1 = fmaxf(mx1, fmaxf(sc[ni][2], sc[ni][3]));
        }
        mx0 = fmaxf(mx0, __shfl_xor_sync(0xffffffffu, mx0, 1));
        mx0 = fmaxf(mx0, __shfl_xor_sync(0xffffffffu, mx0, 2));
        mx1 = fmaxf(mx1, __shfl_xor_sync(0xffffffffu, mx1, 1));
        mx1 = fmaxf(mx1, __shfl_xor_sync(0xffffffffu, mx1, 2));

        const float nm0 = fmaxf(m0, mx0), nm1 = fmaxf(m1, mx1);
        const float al0 = __expf(m0 - nm0), al1 = __expf(m1 - nm1);
        float s0 = 0.f, s1 = 0.f;
#pragma unroll
        for (int ni = 0; ni < 8; ++ni) {
            sc[ni][0] = __expf(sc[ni][0] - nm0); s0 += sc[ni][0];
            sc[ni][1] = __expf(sc[ni][1] - nm0); s0 += sc[ni][1];
            sc[ni][2] = __expf(sc[ni][2] - nm1); s1 += sc[ni][2];
            sc[ni][3] = __expf(sc[ni][3] - nm1); s1 += sc[ni][3];
        }
        s0 += __shfl_xor_sync(0xffffffffu, s0, 1);
        s0 += __shfl_xor_sync(0xffffffffu, s0, 2);
        s1 += __shfl_xor_sync(0xffffffffu, s1, 1);
        s1 += __shfl_xor_sync(0xffffffffu, s1, 2);
        l0 = l0 * al0 + s0; l1 = l1 * al1 + s1;
        m0 = nm0; m1 = nm1;

#pragma unroll
        for (int i = 0; i < 16; ++i) {
            ao[i][0] *= al0; ao[i][1] *= al0;
            ao[i][2] *= al1; ao[i][3] *= al1;
        }

        // ---- O += P @ (Vh+Vl), P single fp16, pairwise-interleaved ----
#pragma unroll
        for (int ks = 0; ks < 4; ++ks) {
            uint32_t pah[4];
            pah[0] = packh2(__float2half_rn(sc[2 * ks][0]), __float2half_rn(sc[2 * ks][1]));
            pah[1] = packh2(__float2half_rn(sc[2 * ks][2]), __float2half_rn(sc[2 * ks][3]));
            pah[2] = packh2(__float2half_rn(sc[2 * ks + 1][0]), __float2half_rn(sc[2 * ks + 1][1]));
            pah[3] = packh2(__float2half_rn(sc[2 * ks + 1][2]), __float2half_rn(sc[2 * ks + 1][3]));

            const uint32_t koff = ks * 32;
#pragma unroll
            for (int ni = 0; ni < 16; ni += 2) {
                uint32_t b0h[2], b0l[2], b1h[2], b1l[2];
                LDSM2(b0h, bVh + ni * (8 * 144) + koff);
                LDSM2(b0l, bVl + ni * (8 * 144) + koff);
                LDSM2(b1h, bVh + (ni + 1) * (8 * 144) + koff);
                LDSM2(b1l, bVl + (ni + 1) * (8 * 144) + koff);
                MMA16816H(ao[ni], pah, b0h);
                MMA16816H(ao[ni + 1], pah, b1h);
                MMA16816H(ao[ni], pah, b0l);
                MMA16816H(ao[ni + 1], pah, b1l);
            }
        }
        __syncthreads();
    }

    const float inv0 = 1.0f / l0, inv1 = 1.0f / l1;
    const int r0 = q0 + wrow + (lane >> 2);
    const int ecol = (lane & 3) * 2;
    float* Ob0 = O + ((size_t)(b * L_ + r0) * NH_ + h) * HD_ + ecol;
    float* Ob1 = O + ((size_t)(b * L_ + r0 + 8) * NH_ + h) * HD_ + ecol;
#pragma unroll
    for (int ni = 0; ni < 16; ++ni) {
        *(float2*)(Ob0 + ni * 8) = make_float2(ao[ni][0] * inv0, ao[ni][1] * inv0);
        *(float2*)(Ob1 + ni * 8) = make_float2(ao[ni][2] * inv1, ao[ni][3] * inv1);
    }
}

// ---------------------------------------------------------------------------
extern "C" void kernel_launch(void* const* d_in, const int* in_sizes, int n_in,
                              void* d_out, int out_size) {
    const float* x  = (const float*)d_in[0];
    const float* Wq = (const float*)d_in[1];
    const float* Wk = (const float*)d_in[2];
    const float* Wv = (const float*)d_in[3];
    const float* Wo = (const float*)d_in[4];
    float* out = (float*)d_out;

    float *q, *k, *v, *o;
    cudaGetSymbolAddress((void**)&q, g_q);
    cudaGetSymbolAddress((void**)&k, g_k);
    cudaGetSymbolAddress((void**)&v, g_v);
    cudaGetSymbolAddress((void**)&o, g_o);
    __half *x16, *wqh, *wql, *wkh, *wkl, *wvh, *wvl, *woh, *wol, *o16;
    __half *q16, *kh, *kl, *vth, *vtl;
    cudaGetSymbolAddress((void**)&x16, g_x16);
    cudaGetSymbolAddress((void**)&wqh, g_wqh); cudaGetSymbolAddress((void**)&wql, g_wql);
    cudaGetSymbolAddress((void**)&wkh, g_wkh); cudaGetSymbolAddress((void**)&wkl, g_wkl);
    cudaGetSymbolAddress((void**)&wvh, g_wvh); cudaGetSymbolAddress((void**)&wvl, g_wvl);
    cudaGetSymbolAddress((void**)&woh, g_woh); cudaGetSymbolAddress((void**)&wol, g_wol);
    cudaGetSymbolAddress((void**)&o16, g_o16);
    cudaGetSymbolAddress((void**)&q16, g_q16);
    cudaGetSymbolAddress((void**)&kh, g_kh);   cudaGetSymbolAddress((void**)&kl, g_kl);
    cudaGetSymbolAddress((void**)&vth, g_vth); cudaGetSymbolAddress((void**)&vtl, g_vtl);

    const int M = B_ * L_;       // 4096
    const int NKVD = NKV_ * HD_; // 1024

    cudaFuncSetAttribute(gemm_mma, cudaFuncAttributeMaxDynamicSharedMemorySize, GT_SMEM);
    cudaFuncSetAttribute(flash_mma, cudaFuncAttributeMaxDynamicSharedMemorySize, FM_SMEM);

    prep_split<<<PREP_BLOCKS, 256>>>(x, Wq, Wk, Wv, Wo);

    gemm_mma<<<dim3(D_ / 128, M / 128), 256, GT_SMEM>>>(x16, wqh, wql, q, D_, D_);
    gemm_mma<<<dim3(NKVD / 128, M / 128), 256, GT_SMEM>>>(x16, wkh, wkl, k, NKVD, D_);
    gemm_mma<<<dim3(NKVD / 128, M / 128), 256, GT_SMEM>>>(x16, wvh, wvl, v, NKVD, D_);

    rope_vt<<<RVT_BLOCKS, 256>>>(q, k, v);

    flash_mma<<<dim3(L_ / 64, NH_, B_), 128, FM_SMEM>>>(q16, kh, kl, vth, vtl, o);

    conv_fp16<<<(M * D_ / 4 + 255) / 256, 256>>>(o, o16, M * D_ / 4);
    gemm_mma<<<dim3(D_ / 128, M / 128), 256, GT_SMEM>>>(o16, woh, wol, out, D_, D_);
}

// round 16
// speedup vs baseline: 1.5602x; 1.0187x over previous
#include <cuda_runtime.h>
#include <cuda_fp16.h>
#include <math.h>
#include <stdint.h>

#define B_  2
#define L_  2048
#define D_  2048
#define NH_ 16
#define NKV_ 8
#define HD_ 128
#define GQ_ 2
#define SCALE_ 0.08838834764831845f  // 128^-0.5

// ---------------- scratch (static device globals) ----------------
__device__ float g_q[(size_t)B_ * L_ * NH_ * HD_];
__device__ float g_k[(size_t)B_ * L_ * NKV_ * HD_];
__device__ float g_v[(size_t)B_ * L_ * NKV_ * HD_];
__device__ float g_o[(size_t)B_ * L_ * NH_ * HD_];
__device__ float g_cos[(size_t)L_ * 64];
__device__ float g_sin[(size_t)L_ * 64];

__device__ __half g_x16[(size_t)B_ * L_ * D_];
__device__ __half g_wqh[(size_t)D_ * D_];
__device__ __half g_wql[(size_t)D_ * D_];
__device__ __half g_wkh[(size_t)NKV_ * HD_ * D_];
__device__ __half g_wkl[(size_t)NKV_ * HD_ * D_];
__device__ __half g_wvh[(size_t)NKV_ * HD_ * D_];
__device__ __half g_wvl[(size_t)NKV_ * HD_ * D_];
__device__ __half g_woh[(size_t)D_ * D_];
__device__ __half g_wol[(size_t)D_ * D_];
__device__ __half g_o16[(size_t)B_ * L_ * D_];

// attention operands (RoPE'd / transposed)
__device__ __half g_q16[(size_t)B_ * L_ * NH_ * HD_];
__device__ __half g_kh[(size_t)B_ * L_ * NKV_ * HD_];
__device__ __half g_kl[(size_t)B_ * L_ * NKV_ * HD_];
__device__ __half g_vth[(size_t)B_ * NKV_ * HD_ * L_];
__device__ __half g_vtl[(size_t)B_ * NKV_ * HD_ * L_];

// ---------------- helpers ----------------
__device__ __forceinline__ uint32_t smem_u32(const void* p) {
    uint32_t a;
    asm("{ .reg .u64 t; cvta.to.shared.u64 t, %1; cvt.u32.u64 %0, t; }"
        : "=r"(a) : "l"(p));
    return a;
}
#define LDSM4(r, a) \
    asm volatile("ldmatrix.sync.aligned.m8n8.x4.shared.b16 {%0,%1,%2,%3}, [%4];" \
                 : "=r"((r)[0]), "=r"((r)[1]), "=r"((r)[2]), "=r"((r)[3]) : "r"(a))
#define LDSM2(r, a) \
    asm volatile("ldmatrix.sync.aligned.m8n8.x2.shared.b16 {%0,%1}, [%2];" \
                 : "=r"((r)[0]), "=r"((r)[1]) : "r"(a))
#define MMA16816H(d, a, b) \
    asm volatile("mma.sync.aligned.m16n8k16.row.col.f32.f16.f16.f32 " \
                 "{%0,%1,%2,%3}, {%4,%5,%6,%7}, {%8,%9}, {%0,%1,%2,%3};" \
                 : "+f"((d)[0]), "+f"((d)[1]), "+f"((d)[2]), "+f"((d)[3]) \
                 : "r"((a)[0]), "r"((a)[1]), "r"((a)[2]), "r"((a)[3]), \
                   "r"((b)[0]), "r"((b)[1]))
#define CP_ASYNC16(s, g) \
    asm volatile("cp.async.cg.shared.global [%0], [%1], 16;" :: "r"(s), "l"(g))
#define CP_COMMIT() asm volatile("cp.async.commit_group;" ::: "memory")
#define CP_WAIT1()  asm volatile("cp.async.wait_group 1;" ::: "memory")
#define CP_WAIT0()  asm volatile("cp.async.wait_group 0;" ::: "memory")

__device__ __forceinline__ uint32_t packh2(__half lo, __half hi) {
    __half2 t = __halves2half2(lo, hi);
    return *(uint32_t*)&t;
}

__device__ __forceinline__ void wsplit4(const float4 v, __half* h, __half* l, int i4) {
    __half h0 = __float2half_rn(v.x);
    __half h1 = __float2half_rn(v.y);
    __half h2 = __float2half_rn(v.z);
    __half h3 = __float2half_rn(v.w);
    h[i4 * 4 + 0] = h0; h[i4 * 4 + 1] = h1; h[i4 * 4 + 2] = h2; h[i4 * 4 + 3] = h3;
    l[i4 * 4 + 0] = __float2half_rn(v.x - __half2float(h0));
    l[i4 * 4 + 1] = __float2half_rn(v.y - __half2float(h1));
    l[i4 * 4 + 2] = __float2half_rn(v.z - __half2float(h2));
    l[i4 * 4 + 3] = __float2half_rn(v.w - __half2float(h3));
}

// ---------------------------------------------------------------------------
__global__ void conv_fp16(const float* __restrict__ s, __half* __restrict__ h, int n4) {
    const int i = blockIdx.x * blockDim.x + threadIdx.x;
    if (i >= n4) return;
    const float4 v = ((const float4*)s)[i];
    h[i * 4 + 0] = __float2half_rn(v.x);
    h[i * 4 + 1] = __float2half_rn(v.y);
    h[i * 4 + 2] = __float2half_rn(v.z);
    h[i * 4 + 3] = __float2half_rn(v.w);
}

// ---------------------------------------------------------------------------
// prep_split: rope table + x fp16 convert + weight hi/lo splits, ONE launch.
// ---------------------------------------------------------------------------
#define PREP_BLOCKS 20992
__global__ void __launch_bounds__(256) prep_split(const float* __restrict__ x,
                                                  const float* __restrict__ Wq,
                                                  const float* __restrict__ Wk,
                                                  const float* __restrict__ Wv,
                                                  const float* __restrict__ Wo) {
    int bid = blockIdx.x;
    const int tid = threadIdx.x;
    if (bid < 512) {
        const int idx = bid * 256 + tid;
        const int i = idx & 63;
        const int pos = idx >> 6;
        const double inv = exp(-(double)i / 64.0 * log(10000.0));
        double sd, cd;
        sincos((double)pos * inv, &sd, &cd);
        g_cos[idx] = (float)cd;
        g_sin[idx] = (float)sd;
        return;
    }
    bid -= 512;
    if (bid < 8192) {
        const int i = bid * 256 + tid;
        const float4 v = ((const float4*)x)[i];
        g_x16[i * 4 + 0] = __float2half_rn(v.x);
        g_x16[i * 4 + 1] = __float2half_rn(v.y);
        g_x16[i * 4 + 2] = __float2half_rn(v.z);
        g_x16[i * 4 + 3] = __float2half_rn(v.w);
        return;
    }
    bid -= 8192;
    const float* src;
    __half *h, *l;
    int base;
    if (bid < 4096)      { src = Wq; h = g_wqh; l = g_wql; base = bid; }
    else if (bid < 6144) { src = Wk; h = g_wkh; l = g_wkl; base = bid - 4096; }
    else if (bid < 8192) { src = Wv; h = g_wvh; l = g_wvl; base = bid - 6144; }
    else                 { src = Wo; h = g_woh; l = g_wol; base = bid - 8192; }
    const int i = base * 256 + tid;
    wsplit4(((const float4*)src)[i], h, l, i);
}

// ---------------------------------------------------------------------------
// fp16x2 GEMM: C = A @ (Bh+Bl)^T. K-chunk 64, cp.async double-buffered,
// 2 CTAs/SM. Stage per buffer (pitch 144B): A 0, Bh 18432, Bl 36864; 55296B.
// ---------------------------------------------------------------------------
#define GSTG 55296
#define GT_SMEM (2 * GSTG)

__global__ void __launch_bounds__(256, 2) gemm_mma(const __half* __restrict__ A,
                                                   const __half* __restrict__ Bh,
                                                   const __half* __restrict__ Bl,
                                                   float* __restrict__ C,
                                                   int N, int K) {
    extern __shared__ __half sb[];
    const uint32_t sbase = smem_u32(sb);

    const int tid = threadIdx.x;
    const int lane = tid & 31;
    const int wid = tid >> 5;
    const int wm = (wid >> 2) * 64;
    const int wn = (wid & 3) * 32;
    const int m0 = blockIdx.y * 128;
    const int n0 = blockIdx.x * 128;

    const int srow = tid >> 1;
    const int sub  = (tid & 1) * 4;

    const char* gA  = (const char*)(A + (size_t)(m0 + srow) * K);
    const char* gBh = (const char*)(Bh + (size_t)(n0 + srow) * K);
    const char* gBl = (const char*)(Bl + (size_t)(n0 + srow) * K);
    const uint32_t srow144 = srow * 144;

    auto stage = [&](int kc, uint32_t sbuf) {
#pragma unroll
        for (int u = 0; u < 4; ++u) {
            const int off = (sub + u) * 16;
            const uint32_t d = sbuf + srow144 + off;
            const int gofs = kc * 2 + off;
            CP_ASYNC16(d,         gA + gofs);
            CP_ASYNC16(d + 18432, gBh + gofs);
            CP_ASYNC16(d + 36864, gBl + gofs);
        }
    };

    float acc[4][4][4];
#pragma unroll
    for (int i = 0; i < 4; ++i)
#pragma unroll
        for (int j = 0; j < 4; ++j)
#pragma unroll
            for (int q = 0; q < 4; ++q) acc[i][j][q] = 0.f;

    const int arow = lane & 15, acol = (lane >> 4) << 3;
    const int brow = lane & 7,  bcol = ((lane >> 3) & 1) << 3;
    const uint32_t a_0  = sbase + (wm + arow) * 144 + acol * 2;
    const uint32_t b_h0 = sbase + 18432 + (wn + brow) * 144 + bcol * 2;

    stage(0, sbase);
    CP_COMMIT();

    const int nchunk = K >> 6;
    for (int c = 0; c < nchunk; ++c) {
        if (c + 1 < nchunk) {
            stage((c + 1) << 6, sbase + (uint32_t)((c + 1) & 1) * GSTG);
            CP_COMMIT();
            CP_WAIT1();
        } else {
            CP_WAIT0();
        }
        __syncthreads();

        const uint32_t boff = (uint32_t)(c & 1) * GSTG;
        const uint32_t a_p = a_0 + boff;
        const uint32_t b_h = b_h0 + boff;
        const uint32_t b_l = b_h + 18432;

#pragma unroll
        for (int ks = 0; ks < 4; ++ks) {
            const uint32_t koff = ks * 32;
            uint32_t ah[4][4], bh[4][2], bl[4][2];
#pragma unroll
            for (int mi = 0; mi < 4; ++mi)
                LDSM4(ah[mi], a_p + mi * (16 * 144) + koff);
#pragma unroll
            for (int ni = 0; ni < 4; ++ni) {
                LDSM2(bh[ni], b_h + ni * (8 * 144) + koff);
                LDSM2(bl[ni], b_l + ni * (8 * 144) + koff);
            }
#pragma unroll
            for (int mi = 0; mi < 4; ++mi)
#pragma unroll
                for (int ni = 0; ni < 4; ++ni)
                    MMA16816H(acc[mi][ni], ah[mi], bh[ni]);
#pragma unroll
            for (int mi = 0; mi < 4; ++mi)
#pragma unroll
                for (int ni = 0; ni < 4; ++ni)
                    MMA16816H(acc[mi][ni], ah[mi], bl[ni]);
        }
        __syncthreads();
    }

    const int erow = lane >> 2;
    const int ecol = (lane & 3) * 2;
#pragma unroll
    for (int mi = 0; mi < 4; ++mi)
#pragma unroll
        for (int ni = 0; ni < 4; ++ni) {
            float* cp = C + (size_t)(m0 + wm + mi * 16 + erow) * N + n0 + wn + ni * 8 + ecol;
            *(float2*)cp = make_float2(acc[mi][ni][0], acc[mi][ni][1]);
            *(float2*)(cp + 8 * (size_t)N) = make_float2(acc[mi][ni][2], acc[mi][ni][3]);
        }
}

// ---------------------------------------------------------------------------
// rope_vt: RoPE -> q fp16 single / k hi/lo; V fp16 hi/lo + transpose.
// ---------------------------------------------------------------------------
#define RVT_BLOCKS 28672
__global__ void __launch_bounds__(256) rope_vt(const float* __restrict__ q,
                                               const float* __restrict__ k,
                                               const float* __restrict__ v) {
    const int bid = blockIdx.x;
    const int tid = threadIdx.x;
    if (bid < 24576) {
        const long long idx = (long long)bid * 256 + tid;
        const int i  = (int)(idx & 63);
        long long r  = idx >> 6;
        const int hh = (int)(r % (NH_ + NKV_));
        r /= (NH_ + NKV_);
        const int bl  = (int)r;
        const int pos = bl & (L_ - 1);

        const float c = g_cos[pos * 64 + i];
        const float s = g_sin[pos * 64 + i];

        if (hh < NH_) {
            const size_t off = ((size_t)bl * NH_ + hh) * HD_;
            const float a = q[off + i];
            const float b = q[off + i + 64];
            g_q16[off + i]      = __float2half_rn(a * c - b * s);
            g_q16[off + i + 64] = __float2half_rn(b * c + a * s);
        } else {
            const size_t off = ((size_t)bl * NKV_ + (hh - NH_)) * HD_;
            const float a = k[off + i];
            const float b = k[off + i + 64];
            const float r0 = a * c - b * s;
            const float r1 = b * c + a * s;
            const __half h0 = __float2half_rn(r0);
            const __half h1 = __float2half_rn(r1);
            g_kh[off + i]      = h0;
            g_kh[off + i + 64] = h1;
            g_kl[off + i]      = __float2half_rn(r0 - __half2float(h0));
            g_kl[off + i + 64] = __float2half_rn(r1 - __half2float(h1));
        }
    } else {
        __shared__ float s[32][33];
        const int lb = bid - 24576;
        const int l0 = (lb & 63) * 32;
        const int d0 = ((lb >> 6) & 3) * 32;
        const int bk = lb >> 8;
        const int b = bk >> 3, kvh = bk & 7;
        const int tx = tid & 31, ty = tid >> 5;

        const float* vb = v + ((size_t)b * L_ * NKV_ + kvh) * HD_;
#pragma unroll
        for (int rr = 0; rr < 4; ++rr) {
            const int lr = ty * 4 + rr;
            s[lr][tx] = vb[(size_t)(l0 + lr) * (NKV_ * HD_) + d0 + tx];
        }
        __syncthreads();

        __half* oh = g_vth + (size_t)bk * HD_ * L_;
        __half* ol = g_vtl + (size_t)bk * HD_ * L_;
#pragma unroll
        for (int rr = 0; rr < 4; ++rr) {
            const int dr = ty * 4 + rr;
            const float val = s[tx][dr];
            const __half hv = __float2half_rn(val);
            oh[(size_t)(d0 + dr) * L_ + l0 + tx] = hv;
            ol[(size_t)(d0 + dr) * L_ + l0 + tx] =
                __float2half_rn(val - __half2float(hv));
        }
    }
}

// ---------------------------------------------------------------------------
// Flash attention fp16x2 (R14, measured best).
// ---------------------------------------------------------------------------
#define OQ   0
#define OKH  17408
#define OKL  34816
#define OVH  52224
#define OVL  70656
#define FM_SMEM 89088

__global__ void __launch_bounds__(128) flash_mma(const __half* __restrict__ Qg,
                                                 const __half* __restrict__ Khg,
                                                 const __half* __restrict__ Klg,
                                                 const __half* __restrict__ Vthg,
                                                 const __half* __restrict__ Vtlg,
                                                 float* __restrict__ O) {
    extern __shared__ char smem[];
    const uint32_t sQ = smem_u32(smem);

    const int tid = threadIdx.x;
    const int lane = tid & 31, wid = tid >> 5;
    const int b = blockIdx.z, h = blockIdx.y;
    const int kvh = h >> 1;
    const int qt = (gridDim.x - 1) - blockIdx.x;
    const int q0 = qt * 64;
    const int wrow = wid * 16;

    const char* q_g = (const char*)(Qg + ((size_t)(b * L_ + q0) * NH_ + h) * HD_);
    const char* kh_g = (const char*)(Khg + ((size_t)b * L_ * NKV_ + kvh) * HD_);
    const char* kl_g = (const char*)(Klg + ((size_t)b * L_ * NKV_ + kvh) * HD_);
    const char* vth_g = (const char*)(Vthg + (size_t)(b * NKV_ + kvh) * HD_ * L_);
    const char* vtl_g = (const char*)(Vtlg + (size_t)(b * NKV_ + kvh) * HD_ * L_);

    for (int i = tid; i < 64 * 16; i += 128) {
        const int row = i >> 4;
        const int u = (i & 15) << 4;
        CP_ASYNC16(sQ + OQ + row * 272 + u, q_g + (size_t)row * (NH_ * HD_ * 2) + u);
    }

    const uint32_t aQ  = sQ + OQ + (wrow + (lane & 15)) * 272 + ((lane >> 4) << 4);
    const uint32_t bKh = sQ + OKH + (lane & 7) * 272 + (((lane >> 3) & 1) << 4);
    const uint32_t bKl = bKh + (OKL - OKH);
    const uint32_t bVh = sQ + OVH + (lane & 7) * 144 + (((lane >> 3) & 1) << 4);
    const uint32_t bVl = bVh + (OVL - OVH);

    float m0 = -1e30f, m1 = -1e30f, l0 = 0.f, l1 = 0.f;
    float ao[16][4];
#pragma unroll
    for (int i = 0; i < 16; ++i)
#pragma unroll
        for (int j = 0; j < 4; ++j) ao[i][j] = 0.f;

    for (int t = 0; t <= qt; ++t) {
        const int k0 = t * 64;

        for (int i = tid; i < 64 * 16; i += 128) {
            const int row = i >> 4;
            const int u = (i & 15) << 4;
            const size_t g = (size_t)(k0 + row) * (NKV_ * HD_ * 2) + u;
            const uint32_t d = row * 272 + u;
            CP_ASYNC16(sQ + OKH + d, kh_g + g);
            CP_ASYNC16(sQ + OKL + d, kl_g + g);
        }
        for (int i = tid; i < 128 * 8; i += 128) {
            const int row = i >> 3;
            const int u = (i & 7) << 4;
            const size_t g = (size_t)row * (L_ * 2) + (size_t)k0 * 2 + u;
            const uint32_t d = row * 144 + u;
            CP_ASYNC16(sQ + OVH + d, vth_g + g);
            CP_ASYNC16(sQ + OVL + d, vtl_g + g);
        }
        CP_COMMIT();
        CP_WAIT0();
        __syncthreads();

        float sc[8][4];
#pragma unroll
        for (int ni = 0; ni < 8; ++ni)
#pragma unroll
            for (int j = 0; j < 4; ++j) sc[ni][j] = 0.f;

#pragma unroll
        for (int ks = 0; ks < 8; ++ks) {
            const uint32_t koff = ks * 32;
            uint32_t ah[4];
            LDSM4(ah, aQ + koff);
            uint32_t bh[8][2], bl[8][2];
#pragma unroll
            for (int ni = 0; ni < 8; ++ni) {
                LDSM2(bh[ni], bKh + ni * (8 * 272) + koff);
                LDSM2(bl[ni], bKl + ni * (8 * 272) + koff);
            }
#pragma unroll
            for (int ni = 0; ni < 8; ++ni) MMA16816H(sc[ni], ah, bh[ni]);
#pragma unroll
            for (int ni = 0; ni < 8; ++ni) MMA16816H(sc[ni], ah, bl[ni]);
        }

#pragma unroll
        for (int ni = 0; ni < 8; ++ni)
#pragma unroll
            for (int j = 0; j < 4; ++j) sc[ni][j] *= SCALE_;

        if (t == qt) {
            const int qr0 = q0 + wrow + (lane >> 2);
#pragma unroll
            for (int ni = 0; ni < 8; ++ni) {
                const int kc = k0 + ni * 8 + (lane & 3) * 2;
                if (kc > qr0)         sc[ni][0] = -1e30f;
                if (kc + 1 > qr0)     sc[ni][1] = -1e30f;
                if (kc > qr0 + 8)     sc[ni][2] = -1e30f;
                if (kc + 1 > qr0 + 8) sc[ni][3] = -1e30f;
            }
        }

        float mx0 = -1e30f, mx1 = -1e30f;
#pragma unroll
        for (int ni = 0; ni < 8; ++ni) {
            mx0 = fmaxf(mx0, fmaxf(sc[ni][0], sc[ni][1]));
            mx1 = fmaxf(mx1, fmaxf(sc[ni][2], sc[ni][3]));
        }
        mx0 = fmaxf(mx0, __shfl_xor_sync(0xffffffffu, mx0, 1));
        mx0 = fmaxf(mx0, __shfl_xor_sync(0xffffffffu, mx0, 2));
        mx1 = fmaxf(mx1, __shfl_xor_sync(0xffffffffu, mx1, 1));
        mx1 = fmaxf(mx1, __shfl_xor_sync(0xffffffffu, mx1, 2));

        const float nm0 = fmaxf(m0, mx0), nm1 = fmaxf(m1, mx1);
        const float al0 = __expf(m0 - nm0), al1 = __expf(m1 - nm1);
        float s0 = 0.f, s1 = 0.f;
#pragma unroll
        for (int ni = 0; ni < 8; ++ni) {
            sc[ni][0] = __expf(sc[ni][0] - nm0); s0 += sc[ni][0];
            sc[ni][1] = __expf(sc[ni][1] - nm0); s0 += sc[ni][1];
            sc[ni][2] = __expf(sc[ni][2] - nm1); s1 += sc[ni][2];
            sc[ni][3] = __expf(sc[ni][3] - nm1); s1 += sc[ni][3];
        }
        s0 += __shfl_xor_sync(0xffffffffu, s0, 1);
        s0 += __shfl_xor_sync(0xffffffffu, s0, 2);
        s1 += __shfl_xor_sync(0xffffffffu, s1, 1);
        s1 += __shfl_xor_sync(0xffffffffu, s1, 2);
        l0 = l0 * al0 + s0; l1 = l1 * al1 + s1;
        m0 = nm0; m1 = nm1;

#pragma unroll
        for (int i = 0; i < 16; ++i) {
            ao[i][0] *= al0; ao[i][1] *= al0;
            ao[i][2] *= al1; ao[i][3] *= al1;
        }

#pragma unroll
        for (int ks = 0; ks < 4; ++ks) {
            uint32_t pah[4];
            pah[0] = packh2(__float2half_rn(sc[2 * ks][0]), __float2half_rn(sc[2 * ks][1]));
            pah[1] = packh2(__float2half_rn(sc[2 * ks][2]), __float2half_rn(sc[2 * ks][3]));
            pah[2] = packh2(__float2half_rn(sc[2 * ks + 1][0]), __float2half_rn(sc[2 * ks + 1][1]));
            pah[3] = packh2(__float2half_rn(sc[2 * ks + 1][2]), __float2half_rn(sc[2 * ks + 1][3]));

            const uint32_t koff = ks * 32;
#pragma unroll
            for (int ni = 0; ni < 16; ni += 2) {
                uint32_t b0h[2], b0l[2], b1h[2], b1l[2];
                LDSM2(b0h, bVh + ni * (8 * 144) + koff);
                LDSM2(b0l, bVl + ni * (8 * 144) + koff);
                LDSM2(b1h, bVh + (ni + 1) * (8 * 144) + koff);
                LDSM2(b1l, bVl + (ni + 1) * (8 * 144) + koff);
                MMA16816H(ao[ni], pah, b0h);
                MMA16816H(ao[ni + 1], pah, b1h);
                MMA16816H(ao[ni], pah, b0l);
                MMA16816H(ao[ni + 1], pah, b1l);
            }
        }
        __syncthreads();
    }

    const float inv0 = 1.0f / l0, inv1 = 1.0f / l1;
    const int r0 = q0 + wrow + (lane >> 2);
    const int ecol = (lane & 3) * 2;
    float* Ob0 = O + ((size_t)(b * L_ + r0) * NH_ + h) * HD_ + ecol;
    float* Ob1 = O + ((size_t)(b * L_ + r0 + 8) * NH_ + h) * HD_ + ecol;
#pragma unroll
    for (int ni = 0; ni < 16; ++ni) {
        *(float2*)(Ob0 + ni * 8) = make_float2(ao[ni][0] * inv0, ao[ni][1] * inv0);
        *(float2*)(Ob1 + ni * 8) = make_float2(ao[ni][2] * inv1, ao[ni][3] * inv1);
    }
}

// ---------------------------------------------------------------------------
extern "C" void kernel_launch(void* const* d_in, const int* in_sizes, int n_in,
                              void* d_out, int out_size) {
    const float* x  = (const float*)d_in[0];
    const float* Wq = (const float*)d_in[1];
    const float* Wk = (const float*)d_in[2];
    const float* Wv = (const float*)d_in[3];
    const float* Wo = (const float*)d_in[4];
    float* out = (float*)d_out;

    float *q, *k, *v, *o;
    cudaGetSymbolAddress((void**)&q, g_q);
    cudaGetSymbolAddress((void**)&k, g_k);
    cudaGetSymbolAddress((void**)&v, g_v);
    cudaGetSymbolAddress((void**)&o, g_o);
    __half *x16, *wqh, *wql, *wkh, *wkl, *wvh, *wvl, *woh, *wol, *o16;
    __half *q16, *kh, *kl, *vth, *vtl;
    cudaGetSymbolAddress((void**)&x16, g_x16);
    cudaGetSymbolAddress((void**)&wqh, g_wqh); cudaGetSymbolAddress((void**)&wql, g_wql);
    cudaGetSymbolAddress((void**)&wkh, g_wkh); cudaGetSymbolAddress((void**)&wkl, g_wkl);
    cudaGetSymbolAddress((void**)&wvh, g_wvh); cudaGetSymbolAddress((void**)&wvl, g_wvl);
    cudaGetSymbolAddress((void**)&woh, g_woh); cudaGetSymbolAddress((void**)&wol, g_wol);
    cudaGetSymbolAddress((void**)&o16, g_o16);
    cudaGetSymbolAddress((void**)&q16, g_q16);
    cudaGetSymbolAddress((void**)&kh, g_kh);   cudaGetSymbolAddress((void**)&kl, g_kl);
    cudaGetSymbolAddress((void**)&vth, g_vth); cudaGetSymbolAddress((void**)&vtl, g_vtl);

    const int M = B_ * L_;       // 4096
    const int NKVD = NKV_ * HD_; // 1024

    cudaFuncSetAttribute(gemm_mma, cudaFuncAttributeMaxDynamicSharedMemorySize, GT_SMEM);
    cudaFuncSetAttribute(flash_mma, cudaFuncAttributeMaxDynamicSharedMemorySize, FM_SMEM);

    prep_split<<<PREP_BLOCKS, 256>>>(x, Wq, Wk, Wv, Wo);

    gemm_mma<<<dim3(D_ / 128, M / 128), 256, GT_SMEM>>>(x16, wqh, wql, q, D_, D_);
    gemm_mma<<<dim3(NKVD / 128, M / 128), 256, GT_SMEM>>>(x16, wkh, wkl, k, NKVD, D_);
    gemm_mma<<<dim3(NKVD / 128, M / 128), 256, GT_SMEM>>>(x16, wvh, wvl, v, NKVD, D_);

    rope_vt<<<RVT_BLOCKS, 256>>>(q, k, v);

    flash_mma<<<dim3(L_ / 64, NH_, B_), 128, FM_SMEM>>>(q16, kh, kl, vth, vtl, o);

    conv_fp16<<<(M * D_ / 4 + 255) / 256, 256>>>(o, o16, M * D_ / 4);
    gemm_mma<<<dim3(D_ / 128, M / 128), 256, GT_SMEM>>>(o16, woh, wol, out, D_, D_);
}

// round 17
// speedup vs baseline: 2.0879x; 1.3382x over previous
#include <cuda_runtime.h>
#include <cuda_fp16.h>
#include <math.h>
#include <stdint.h>

#define B_  2
#define L_  2048
#define D_  2048
#define NH_ 16
#define NKV_ 8
#define HD_ 128
#define GQ_ 2
#define SCALE_ 0.08838834764831845f  // 128^-0.5

// ---------------- scratch (static device globals) ----------------
__device__ float g_q[(size_t)B_ * L_ * NH_ * HD_];
__device__ float g_k[(size_t)B_ * L_ * NKV_ * HD_];
__device__ float g_v[(size_t)B_ * L_ * NKV_ * HD_];
__device__ float g_o[(size_t)B_ * L_ * NH_ * HD_];
__device__ float g_cos[(size_t)L_ * 64];
__device__ float g_sin[(size_t)L_ * 64];

__device__ __half g_x16[(size_t)B_ * L_ * D_];
__device__ __half g_wq16[(size_t)D_ * D_];
__device__ __half g_wk16[(size_t)NKV_ * HD_ * D_];
__device__ __half g_wv16[(size_t)NKV_ * HD_ * D_];
__device__ __half g_wo16[(size_t)D_ * D_];
__device__ __half g_o16[(size_t)B_ * L_ * D_];

// attention operands (RoPE'd / transposed)
__device__ __half g_q16[(size_t)B_ * L_ * NH_ * HD_];
__device__ __half g_kh[(size_t)B_ * L_ * NKV_ * HD_];
__device__ __half g_kl[(size_t)B_ * L_ * NKV_ * HD_];
__device__ __half g_vth[(size_t)B_ * NKV_ * HD_ * L_];
__device__ __half g_vtl[(size_t)B_ * NKV_ * HD_ * L_];

// ---------------- helpers ----------------
__device__ __forceinline__ uint32_t smem_u32(const void* p) {
    uint32_t a;
    asm("{ .reg .u64 t; cvta.to.shared.u64 t, %1; cvt.u32.u64 %0, t; }"
        : "=r"(a) : "l"(p));
    return a;
}
#define LDSM4(r, a) \
    asm volatile("ldmatrix.sync.aligned.m8n8.x4.shared.b16 {%0,%1,%2,%3}, [%4];" \
                 : "=r"((r)[0]), "=r"((r)[1]), "=r"((r)[2]), "=r"((r)[3]) : "r"(a))
#define LDSM2(r, a) \
    asm volatile("ldmatrix.sync.aligned.m8n8.x2.shared.b16 {%0,%1}, [%2];" \
                 : "=r"((r)[0]), "=r"((r)[1]) : "r"(a))
#define MMA16816H(d, a, b) \
    asm volatile("mma.sync.aligned.m16n8k16.row.col.f32.f16.f16.f32 " \
                 "{%0,%1,%2,%3}, {%4,%5,%6,%7}, {%8,%9}, {%0,%1,%2,%3};" \
                 : "+f"((d)[0]), "+f"((d)[1]), "+f"((d)[2]), "+f"((d)[3]) \
                 : "r"((a)[0]), "r"((a)[1]), "r"((a)[2]), "r"((a)[3]), \
                   "r"((b)[0]), "r"((b)[1]))
#define CP_ASYNC16(s, g) \
    asm volatile("cp.async.cg.shared.global [%0], [%1], 16;" :: "r"(s), "l"(g))
#define CP_COMMIT() asm volatile("cp.async.commit_group;" ::: "memory")
#define CP_WAIT1()  asm volatile("cp.async.wait_group 1;" ::: "memory")
#define CP_WAIT0()  asm volatile("cp.async.wait_group 0;" ::: "memory")

__device__ __forceinline__ uint32_t packh2(__half lo, __half hi) {
    __half2 t = __halves2half2(lo, hi);
    return *(uint32_t*)&t;
}

// ---------------------------------------------------------------------------
__global__ void conv_fp16(const float* __restrict__ s, __half* __restrict__ h, int n4) {
    const int i = blockIdx.x * blockDim.x + threadIdx.x;
    if (i >= n4) return;
    const float4 v = ((const float4*)s)[i];
    h[i * 4 + 0] = __float2half_rn(v.x);
    h[i * 4 + 1] = __float2half_rn(v.y);
    h[i * 4 + 2] = __float2half_rn(v.z);
    h[i * 4 + 3] = __float2half_rn(v.w);
}

// ---------------------------------------------------------------------------
// prep_split: rope table + fp16 converts (x + all weights), ONE launch.
// blocks: 512 rope | x 8192 | Wq 4096 | Wk 2048 | Wv 2048 | Wo 4096
// ---------------------------------------------------------------------------
#define PREP_BLOCKS 20992
__global__ void __launch_bounds__(256) prep_split(const float* __restrict__ x,
                                                  const float* __restrict__ Wq,
                                                  const float* __restrict__ Wk,
                                                  const float* __restrict__ Wv,
                                                  const float* __restrict__ Wo) {
    int bid = blockIdx.x;
    const int tid = threadIdx.x;
    if (bid < 512) {
        const int idx = bid * 256 + tid;
        const int i = idx & 63;
        const int pos = idx >> 6;
        const double inv = exp(-(double)i / 64.0 * log(10000.0));
        double sd, cd;
        sincos((double)pos * inv, &sd, &cd);
        g_cos[idx] = (float)cd;
        g_sin[idx] = (float)sd;
        return;
    }
    bid -= 512;
    const float* src;
    __half* dst;
    int base;
    if (bid < 8192)       { src = x;  dst = g_x16;  base = bid; }
    else if (bid < 12288) { src = Wq; dst = g_wq16; base = bid - 8192; }
    else if (bid < 14336) { src = Wk; dst = g_wk16; base = bid - 12288; }
    else if (bid < 16384) { src = Wv; dst = g_wv16; base = bid - 14336; }
    else                  { src = Wo; dst = g_wo16; base = bid - 16384; }
    const int i = base * 256 + tid;
    const float4 v = ((const float4*)src)[i];
    dst[i * 4 + 0] = __float2half_rn(v.x);
    dst[i * 4 + 1] = __float2half_rn(v.y);
    dst[i * 4 + 2] = __float2half_rn(v.z);
    dst[i * 4 + 3] = __float2half_rn(v.w);
}

// ---------------------------------------------------------------------------
// fp16 GEMM core: C = A @ B^T. Tile 128x128, K-chunk 64, cp.async double
// buffered, 2 CTAs/SM. Stage per buffer (pitch 144B): A 0, B 18432; 36864B.
// ---------------------------------------------------------------------------
#define GSTG 36864
#define GT_SMEM (2 * GSTG)

__device__ __forceinline__ void gemm_body(const __half* __restrict__ A,
                                          const __half* __restrict__ Bm,
                                          float* __restrict__ C,
                                          int m0, int n0, int N, int K,
                                          __half* sb) {
    const uint32_t sbase = smem_u32(sb);
    const int tid = threadIdx.x;
    const int lane = tid & 31;
    const int wid = tid >> 5;
    const int wm = (wid >> 2) * 64;
    const int wn = (wid & 3) * 32;

    const int srow = tid >> 1;
    const int sub  = (tid & 1) * 4;

    const char* gA = (const char*)(A + (size_t)(m0 + srow) * K);
    const char* gB = (const char*)(Bm + (size_t)(n0 + srow) * K);
    const uint32_t srow144 = srow * 144;

    auto stage = [&](int kc, uint32_t sbuf) {
#pragma unroll
        for (int u = 0; u < 4; ++u) {
            const int off = (sub + u) * 16;
            const uint32_t d = sbuf + srow144 + off;
            const int gofs = kc * 2 + off;
            CP_ASYNC16(d,         gA + gofs);
            CP_ASYNC16(d + 18432, gB + gofs);
        }
    };

    float acc[4][4][4];
#pragma unroll
    for (int i = 0; i < 4; ++i)
#pragma unroll
        for (int j = 0; j < 4; ++j)
#pragma unroll
            for (int q = 0; q < 4; ++q) acc[i][j][q] = 0.f;

    const int arow = lane & 15, acol = (lane >> 4) << 3;
    const int brow = lane & 7,  bcol = ((lane >> 3) & 1) << 3;
    const uint32_t a_0  = sbase + (wm + arow) * 144 + acol * 2;
    const uint32_t b_0  = sbase + 18432 + (wn + brow) * 144 + bcol * 2;

    stage(0, sbase);
    CP_COMMIT();

    const int nchunk = K >> 6;
    for (int c = 0; c < nchunk; ++c) {
        if (c + 1 < nchunk) {
            stage((c + 1) << 6, sbase + (uint32_t)((c + 1) & 1) * GSTG);
            CP_COMMIT();
            CP_WAIT1();
        } else {
            CP_WAIT0();
        }
        __syncthreads();

        const uint32_t boff = (uint32_t)(c & 1) * GSTG;
        const uint32_t a_p = a_0 + boff;
        const uint32_t b_p = b_0 + boff;

#pragma unroll
        for (int ks = 0; ks < 4; ++ks) {
            const uint32_t koff = ks * 32;
            uint32_t ah[4][4], bh[4][2];
#pragma unroll
            for (int mi = 0; mi < 4; ++mi)
                LDSM4(ah[mi], a_p + mi * (16 * 144) + koff);
#pragma unroll
            for (int ni = 0; ni < 4; ++ni)
                LDSM2(bh[ni], b_p + ni * (8 * 144) + koff);
#pragma unroll
            for (int mi = 0; mi < 4; ++mi)
#pragma unroll
                for (int ni = 0; ni < 4; ++ni)
                    MMA16816H(acc[mi][ni], ah[mi], bh[ni]);
        }
        __syncthreads();
    }

    const int erow = lane >> 2;
    const int ecol = (lane & 3) * 2;
#pragma unroll
    for (int mi = 0; mi < 4; ++mi)
#pragma unroll
        for (int ni = 0; ni < 4; ++ni) {
            float* cp = C + (size_t)(m0 + wm + mi * 16 + erow) * N + n0 + wn + ni * 8 + ecol;
            *(float2*)cp = make_float2(acc[mi][ni][0], acc[mi][ni][1]);
            *(float2*)(cp + 8 * (size_t)N) = make_float2(acc[mi][ni][2], acc[mi][ni][3]);
        }
}

// fused QKV: grid.x in [0,32): 0-15 -> Q, 16-23 -> K, 24-31 -> V
__global__ void __launch_bounds__(256, 2) gemm_qkv(const __half* __restrict__ A,
                                                   float* __restrict__ q,
                                                   float* __restrict__ k,
                                                   float* __restrict__ v) {
    extern __shared__ __half sb[];
    __half *wq, *wk, *wv;
    // resolve weight symbol addresses (device-side, cheap)
    wq = g_wq16; wk = g_wk16; wv = g_wv16;
    const int m0 = blockIdx.y * 128;
    const int bx = blockIdx.x;
    if (bx < 16)      gemm_body(A, wq, q, m0, bx * 128, D_, D_, sb);
    else if (bx < 24) gemm_body(A, wk, k, m0, (bx - 16) * 128, NKV_ * HD_, D_, sb);
    else              gemm_body(A, wv, v, m0, (bx - 24) * 128, NKV_ * HD_, D_, sb);
}

__global__ void __launch_bounds__(256, 2) gemm_single(const __half* __restrict__ A,
                                                      const __half* __restrict__ Bm,
                                                      float* __restrict__ C,
                                                      int N, int K) {
    extern __shared__ __half sb[];
    gemm_body(A, Bm, C, blockIdx.y * 128, blockIdx.x * 128, N, K, sb);
}

// ---------------------------------------------------------------------------
// rope_vt: RoPE -> q fp16 single / k hi/lo; V fp16 hi/lo + transpose.
// ---------------------------------------------------------------------------
#define RVT_BLOCKS 28672
__global__ void __launch_bounds__(256) rope_vt(const float* __restrict__ q,
                                               const float* __restrict__ k,
                                               const float* __restrict__ v) {
    const int bid = blockIdx.x;
    const int tid = threadIdx.x;
    if (bid < 24576) {
        const long long idx = (long long)bid * 256 + tid;
        const int i  = (int)(idx & 63);
        long long r  = idx >> 6;
        const int hh = (int)(r % (NH_ + NKV_));
        r /= (NH_ + NKV_);
        const int bl  = (int)r;
        const int pos = bl & (L_ - 1);

        const float c = g_cos[pos * 64 + i];
        const float s = g_sin[pos * 64 + i];

        if (hh < NH_) {
            const size_t off = ((size_t)bl * NH_ + hh) * HD_;
            const float a = q[off + i];
            const float b = q[off + i + 64];
            g_q16[off + i]      = __float2half_rn(a * c - b * s);
            g_q16[off + i + 64] = __float2half_rn(b * c + a * s);
        } else {
            const size_t off = ((size_t)bl * NKV_ + (hh - NH_)) * HD_;
            const float a = k[off + i];
            const float b = k[off + i + 64];
            const float r0 = a * c - b * s;
            const float r1 = b * c + a * s;
            const __half h0 = __float2half_rn(r0);
            const __half h1 = __float2half_rn(r1);
            g_kh[off + i]      = h0;
            g_kh[off + i + 64] = h1;
            g_kl[off + i]      = __float2half_rn(r0 - __half2float(h0));
            g_kl[off + i + 64] = __float2half_rn(r1 - __half2float(h1));
        }
    } else {
        __shared__ float s[32][33];
        const int lb = bid - 24576;
        const int l0 = (lb & 63) * 32;
        const int d0 = ((lb >> 6) & 3) * 32;
        const int bk = lb >> 8;
        const int b = bk >> 3, kvh = bk & 7;
        const int tx = tid & 31, ty = tid >> 5;

        const float* vb = v + ((size_t)b * L_ * NKV_ + kvh) * HD_;
#pragma unroll
        for (int rr = 0; rr < 4; ++rr) {
            const int lr = ty * 4 + rr;
            s[lr][tx] = vb[(size_t)(l0 + lr) * (NKV_ * HD_) + d0 + tx];
        }
        __syncthreads();

        __half* oh = g_vth + (size_t)bk * HD_ * L_;
        __half* ol = g_vtl + (size_t)bk * HD_ * L_;
#pragma unroll
        for (int rr = 0; rr < 4; ++rr) {
            const int dr = ty * 4 + rr;
            const float val = s[tx][dr];
            const __half hv = __float2half_rn(val);
            oh[(size_t)(d0 + dr) * L_ + l0 + tx] = hv;
            ol[(size_t)(d0 + dr) * L_ + l0 + tx] =
                __float2half_rn(val - __half2float(hv));
        }
    }
}

// ---------------------------------------------------------------------------
// Flash attention fp16x2 (R14/R15, measured best) — unchanged.
// ---------------------------------------------------------------------------
#define OQ   0
#define OKH  17408
#define OKL  34816
#define OVH  52224
#define OVL  70656
#define FM_SMEM 89088

__global__ void __launch_bounds__(128) flash_mma(const __half* __restrict__ Qg,
                                                 const __half* __restrict__ Khg,
                                                 const __half* __restrict__ Klg,
                                                 const __half* __restrict__ Vthg,
                                                 const __half* __restrict__ Vtlg,
                                                 float* __restrict__ O) {
    extern __shared__ char smem[];
    const uint32_t sQ = smem_u32(smem);

    const int tid = threadIdx.x;
    const int lane = tid & 31, wid = tid >> 5;
    const int b = blockIdx.z, h = blockIdx.y;
    const int kvh = h >> 1;
    const int qt = (gridDim.x - 1) - blockIdx.x;
    const int q0 = qt * 64;
    const int wrow = wid * 16;

    const char* q_g = (const char*)(Qg + ((size_t)(b * L_ + q0) * NH_ + h) * HD_);
    const char* kh_g = (const char*)(Khg + ((size_t)b * L_ * NKV_ + kvh) * HD_);
    const char* kl_g = (const char*)(Klg + ((size_t)b * L_ * NKV_ + kvh) * HD_);
    const char* vth_g = (const char*)(Vthg + (size_t)(b * NKV_ + kvh) * HD_ * L_);
    const char* vtl_g = (const char*)(Vtlg + (size_t)(b * NKV_ + kvh) * HD_ * L_);

    for (int i = tid; i < 64 * 16; i += 128) {
        const int row = i >> 4;
        const int u = (i & 15) << 4;
        CP_ASYNC16(sQ + OQ + row * 272 + u, q_g + (size_t)row * (NH_ * HD_ * 2) + u);
    }

    const uint32_t aQ  = sQ + OQ + (wrow + (lane & 15)) * 272 + ((lane >> 4) << 4);
    const uint32_t bKh = sQ + OKH + (lane & 7) * 272 + (((lane >> 3) & 1) << 4);
    const uint32_t bKl = bKh + (OKL - OKH);
    const uint32_t bVh = sQ + OVH + (lane & 7) * 144 + (((lane >> 3) & 1) << 4);
    const uint32_t bVl = bVh + (OVL - OVH);

    float m0 = -1e30f, m1 = -1e30f, l0 = 0.f, l1 = 0.f;
    float ao[16][4];
#pragma unroll
    for (int i = 0; i < 16; ++i)
#pragma unroll
        for (int j = 0; j < 4; ++j) ao[i][j] = 0.f;

    for (int t = 0; t <= qt; ++t) {
        const int k0 = t * 64;

        for (int i = tid; i < 64 * 16; i += 128) {
            const int row = i >> 4;
            const int u = (i & 15) << 4;
            const size_t g = (size_t)(k0 + row) * (NKV_ * HD_ * 2) + u;
            const uint32_t d = row * 272 + u;
            CP_ASYNC16(sQ + OKH + d, kh_g + g);
            CP_ASYNC16(sQ + OKL + d, kl_g + g);
        }
        for (int i = tid; i < 128 * 8; i += 128) {
            const int row = i >> 3;
            const int u = (i & 7) << 4;
            const size_t g = (size_t)row * (L_ * 2) + (size_t)k0 * 2 + u;
            const uint32_t d = row * 144 + u;
            CP_ASYNC16(sQ + OVH + d, vth_g + g);
            CP_ASYNC16(sQ + OVL + d, vtl_g + g);
        }
        CP_COMMIT();
        CP_WAIT0();
        __syncthreads();

        float sc[8][4];
#pragma unroll
        for (int ni = 0; ni < 8; ++ni)
#pragma unroll
            for (int j = 0; j < 4; ++j) sc[ni][j] = 0.f;

#pragma unroll
        for (int ks = 0; ks < 8; ++ks) {
            const uint32_t koff = ks * 32;
            uint32_t ah[4];
            LDSM4(ah, aQ + koff);
            uint32_t bh[8][2], bl[8][2];
#pragma unroll
            for (int ni = 0; ni < 8; ++ni) {
                LDSM2(bh[ni], bKh + ni * (8 * 272) + koff);
                LDSM2(bl[ni], bKl + ni * (8 * 272) + koff);
            }
#pragma unroll
            for (int ni = 0; ni < 8; ++ni) MMA16816H(sc[ni], ah, bh[ni]);
#pragma unroll
            for (int ni = 0; ni < 8; ++ni) MMA16816H(sc[ni], ah, bl[ni]);
        }

#pragma unroll
        for (int ni = 0; ni < 8; ++ni)
#pragma unroll
            for (int j = 0; j < 4; ++j) sc[ni][j] *= SCALE_;

        if (t == qt) {
            const int qr0 = q0 + wrow + (lane >> 2);
#pragma unroll
            for (int ni = 0; ni < 8; ++ni) {
                const int kc = k0 + ni * 8 + (lane & 3) * 2;
                if (kc > qr0)         sc[ni][0] = -1e30f;
                if (kc + 1 > qr0)     sc[ni][1] = -1e30f;
                if (kc > qr0 + 8)     sc[ni][2] = -1e30f;
                if (kc + 1 > qr0 + 8) sc[ni][3] = -1e30f;
            }
        }

        float mx0 = -1e30f, mx1 = -1e30f;
#pragma unroll
        for (int ni = 0; ni < 8; ++ni) {
            mx0 = fmaxf(mx0, fmaxf(sc[ni][0], sc[ni][1]));
            mx1 = fmaxf(mx1, fmaxf(sc[ni][2], sc[ni][3]));
        }
        mx0 = fmaxf(mx0, __shfl_xor_sync(0xffffffffu, mx0, 1));
        mx0 = fmaxf(mx0, __shfl_xor_sync(0xffffffffu, mx0, 2));
        mx1 = fmaxf(mx1, __shfl_xor_sync(0xffffffffu, mx1, 1));
        mx1 = fmaxf(mx1, __shfl_xor_sync(0xffffffffu, mx1, 2));

        const float nm0 = fmaxf(m0, mx0), nm1 = fmaxf(m1, mx1);
        const float al0 = __expf(m0 - nm0), al1 = __expf(m1 - nm1);
        float s0 = 0.f, s1 = 0.f;
#pragma unroll
        for (int ni = 0; ni < 8; ++ni) {
            sc[ni][0] = __expf(sc[ni][0] - nm0); s0 += sc[ni][0];
            sc[ni][1] = __expf(sc[ni][1] - nm0); s0 += sc[ni][1];
            sc[ni][2] = __expf(sc[ni][2] - nm1); s1 += sc[ni][2];
            sc[ni][3] = __expf(sc[ni][3] - nm1); s1 += sc[ni][3];
        }
        s0 += __shfl_xor_sync(0xffffffffu, s0, 1);
        s0 += __shfl_xor_sync(0xffffffffu, s0, 2);
        s1 += __shfl_xor_sync(0xffffffffu, s1, 1);
        s1 += __shfl_xor_sync(0xffffffffu, s1, 2);
        l0 = l0 * al0 + s0; l1 = l1 * al1 + s1;
        m0 = nm0; m1 = nm1;

#pragma unroll
        for (int i = 0; i < 16; ++i) {
            ao[i][0] *= al0; ao[i][1] *= al0;
            ao[i][2] *= al1; ao[i][3] *= al1;
        }

#pragma unroll
        for (int ks = 0; ks < 4; ++ks) {
            uint32_t pah[4];
            pah[0] = packh2(__float2half_rn(sc[2 * ks][0]), __float2half_rn(sc[2 * ks][1]));
            pah[1] = packh2(__float2half_rn(sc[2 * ks][2]), __float2half_rn(sc[2 * ks][3]));
            pah[2] = packh2(__float2half_rn(sc[2 * ks + 1][0]), __float2half_rn(sc[2 * ks + 1][1]));
            pah[3] = packh2(__float2half_rn(sc[2 * ks + 1][2]), __float2half_rn(sc[2 * ks + 1][3]));

            const uint32_t koff = ks * 32;
#pragma unroll
            for (int ni = 0; ni < 16; ni += 2) {
                uint32_t b0h[2], b0l[2], b1h[2], b1l[2];
                LDSM2(b0h, bVh + ni * (8 * 144) + koff);
                LDSM2(b0l, bVl + ni * (8 * 144) + koff);
                LDSM2(b1h, bVh + (ni + 1) * (8 * 144) + koff);
                LDSM2(b1l, bVl + (ni + 1) * (8 * 144) + koff);
                MMA16816H(ao[ni], pah, b0h);
                MMA16816H(ao[ni + 1], pah, b1h);
                MMA16816H(ao[ni], pah, b0l);
                MMA16816H(ao[ni + 1], pah, b1l);
            }
        }
        __syncthreads();
    }

    const float inv0 = 1.0f / l0, inv1 = 1.0f / l1;
    const int r0 = q0 + wrow + (lane >> 2);
    const int ecol = (lane & 3) * 2;
    float* Ob0 = O + ((size_t)(b * L_ + r0) * NH_ + h) * HD_ + ecol;
    float* Ob1 = O + ((size_t)(b * L_ + r0 + 8) * NH_ + h) * HD_ + ecol;
#pragma unroll
    for (int ni = 0; ni < 16; ++ni) {
        *(float2*)(Ob0 + ni * 8) = make_float2(ao[ni][0] * inv0, ao[ni][1] * inv0);
        *(float2*)(Ob1 + ni * 8) = make_float2(ao[ni][2] * inv1, ao[ni][3] * inv1);
    }
}

// ---------------------------------------------------------------------------
extern "C" void kernel_launch(void* const* d_in, const int* in_sizes, int n_in,
                              void* d_out, int out_size) {
    const float* x  = (const float*)d_in[0];
    const float* Wq = (const float*)d_in[1];
    const float* Wk = (const float*)d_in[2];
    const float* Wv = (const float*)d_in[3];
    const float* Wo = (const float*)d_in[4];
    float* out = (float*)d_out;

    float *q, *k, *v, *o;
    cudaGetSymbolAddress((void**)&q, g_q);
    cudaGetSymbolAddress((void**)&k, g_k);
    cudaGetSymbolAddress((void**)&v, g_v);
    cudaGetSymbolAddress((void**)&o, g_o);
    __half *x16, *wo16, *o16, *q16, *kh, *kl, *vth, *vtl;
    cudaGetSymbolAddress((void**)&x16, g_x16);
    cudaGetSymbolAddress((void**)&wo16, g_wo16);
    cudaGetSymbolAddress((void**)&o16, g_o16);
    cudaGetSymbolAddress((void**)&q16, g_q16);
    cudaGetSymbolAddress((void**)&kh, g_kh);   cudaGetSymbolAddress((void**)&kl, g_kl);
    cudaGetSymbolAddress((void**)&vth, g_vth); cudaGetSymbolAddress((void**)&vtl, g_vtl);

    const int M = B_ * L_;       // 4096

    cudaFuncSetAttribute(gemm_qkv, cudaFuncAttributeMaxDynamicSharedMemorySize, GT_SMEM);
    cudaFuncSetAttribute(gemm_single, cudaFuncAttributeMaxDynamicSharedMemorySize, GT_SMEM);
    cudaFuncSetAttribute(flash_mma, cudaFuncAttributeMaxDynamicSharedMemorySize, FM_SMEM);

    prep_split<<<PREP_BLOCKS, 256>>>(x, Wq, Wk, Wv, Wo);

    // fused Q/K/V projections
    gemm_qkv<<<dim3(32, M / 128), 256, GT_SMEM>>>(x16, q, k, v);

    rope_vt<<<RVT_BLOCKS, 256>>>(q, k, v);

    flash_mma<<<dim3(L_ / 64, NH_, B_), 128, FM_SMEM>>>(q16, kh, kl, vth, vtl, o);

    conv_fp16<<<(M * D_ / 4 + 255) / 256, 256>>>(o, o16, M * D_ / 4);
    gemm_single<<<dim3(D_ / 128, M / 128), 256, GT_SMEM>>>(o16, wo16, out, D_, D_);
}